// round 11
// baseline (speedup 1.0000x reference)
#include <cuda_runtime.h>
#include <cuda_bf16.h>
#include <math.h>

typedef __nv_bfloat16 bf16;

// ---------------- dims ----------------
#define BB   2
#define TT   2048
#define DD   768
#define NHH  12
#define NKVV 4
#define HDD  64
#define LL   6
#define VV   32000
#define DII  1536
#define NCC  64
#define CDD  128
#define ROWS (BB*TT)          // 4096
#define GATE_STRENGTH 0.001f
#define EXN  ((long)DD*DII)   // expert matrix elements = 1,179,648

// ---------------- fp32 scratch ----------------
__device__ float g_x [ROWS*DD];
__device__ float g_q [ROWS*NHH*HDD];
__device__ float g_k [ROWS*NKVV*HDD];
__device__ float g_v [ROWS*NKVV*HDD];
__device__ float g_eb[6L*ROWS*DII];    // gate/up outputs; also MoE-down partials
__device__ float g_cv[BB*10];
__device__ float g_tw[LL*BB*3];
__device__ int   g_ti[LL*BB*3];

// ---------------- bf16 hi/lo activation planes ----------------
__device__ bf16 g_h_h [ROWS*DD],        g_h_l [ROWS*DD];
__device__ bf16 g_ao_h[ROWS*NHH*HDD],   g_ao_l[ROWS*NHH*HDD];
__device__ bf16 g_hd_h[ROWS*DII],       g_hd_l[ROWS*DII];       // PF hidden
__device__ bf16 g_mh_h[3L*ROWS*DII],    g_mh_l[3L*ROWS*DII];    // MoE hidden

// ---------------- bf16 hi/lo weight planes (same layout as source) -------------
__device__ bf16 g_wq_h[6L*768*768],  g_wq_l[6L*768*768];
__device__ bf16 g_wk_h[6L*768*256],  g_wk_l[6L*768*256];
__device__ bf16 g_wv_h[6L*768*256],  g_wv_l[6L*768*256];
__device__ bf16 g_wo_h[6L*768*768],  g_wo_l[6L*768*768];
__device__ bf16 g_pg_h[6L*768*1536], g_pg_l[6L*768*1536];
__device__ bf16 g_pu_h[6L*768*1536], g_pu_l[6L*768*1536];
__device__ bf16 g_pd_h[6L*1536*768], g_pd_l[6L*1536*768];
__device__ bf16 g_em_h[(long)VV*DD], g_em_l[(long)VV*DD];   // [N][K] for TRANSB
__device__ bf16 g_hg_h[(long)VV*DD], g_hg_l[(long)VV*DD];
__device__ bf16 g_eg_h[36L*DD*DII],  g_eg_l[36L*DD*DII];
__device__ bf16 g_eu_h[36L*DD*DII],  g_eu_l[36L*DD*DII];
__device__ bf16 g_ed_h[36L*DD*DII],  g_ed_l[36L*DD*DII];

// ---------------- helpers ----------------
__device__ __forceinline__ float block_reduce_sum_256(float v) {
    __shared__ float red[8];
    int t = threadIdx.x;
    #pragma unroll
    for (int off = 16; off; off >>= 1) v += __shfl_xor_sync(0xffffffffu, v, off);
    if ((t & 31) == 0) red[t >> 5] = v;
    __syncthreads();
    float tot = 0.f;
    #pragma unroll
    for (int i = 0; i < 8; i++) tot += red[i];
    return tot;
}

__device__ __forceinline__ void split1(float f, bf16& h, bf16& l) {
    h = __float2bfloat16_rn(f);
    l = __float2bfloat16_rn(f - __bfloat162float(h));
}

__device__ __forceinline__ void split2(float f0, float f1, unsigned& hi, unsigned& lo) {
    __nv_bfloat162 h = __floats2bfloat162_rn(f0, f1);
    float r0 = f0 - __bfloat162float(__low2bfloat16(h));
    float r1 = f1 - __bfloat162float(__high2bfloat16(h));
    __nv_bfloat162 l = __floats2bfloat162_rn(r0, r1);
    hi = *(unsigned*)&h;
    lo = *(unsigned*)&l;
}

__device__ __forceinline__ void mma16816(float* c, const unsigned* a, const unsigned* b) {
    asm volatile(
        "mma.sync.aligned.m16n8k16.row.col.f32.bf16.bf16.f32 "
        "{%0,%1,%2,%3}, {%4,%5,%6,%7}, {%8,%9}, {%0,%1,%2,%3};\n"
        : "+f"(c[0]), "+f"(c[1]), "+f"(c[2]), "+f"(c[3])
        : "r"(a[0]), "r"(a[1]), "r"(a[2]), "r"(a[3]), "r"(b[0]), "r"(b[1]));
}

__device__ __forceinline__ void ldsm_x4(unsigned& r0, unsigned& r1, unsigned& r2,
                                        unsigned& r3, unsigned addr) {
    asm volatile("ldmatrix.sync.aligned.m8n8.x4.shared.b16 {%0,%1,%2,%3}, [%4];\n"
                 : "=r"(r0), "=r"(r1), "=r"(r2), "=r"(r3) : "r"(addr));
}

__device__ __forceinline__ void ldsm_x4_t(unsigned& r0, unsigned& r1, unsigned& r2,
                                          unsigned& r3, unsigned addr) {
    asm volatile("ldmatrix.sync.aligned.m8n8.x4.trans.shared.b16 {%0,%1,%2,%3}, [%4];\n"
                 : "=r"(r0), "=r"(r1), "=r"(r2), "=r"(r3) : "r"(addr));
}

__device__ __forceinline__ void cp16(unsigned dst, const void* src) {
    asm volatile("cp.async.cg.shared.global [%0], [%1], 16;\n" :: "r"(dst), "l"(src));
}
__device__ __forceinline__ void cp_commit() { asm volatile("cp.async.commit_group;\n"); }
__device__ __forceinline__ void cp_wait0()  { asm volatile("cp.async.wait_group 0;\n" ::: "memory"); }

// ---------------- weight converters (no transpose; layouts as in source) -------
__global__ void convw_kernel(const float* __restrict__ s, bf16* __restrict__ hi,
                             bf16* __restrict__ lo, long n) {
    long i = ((long)blockIdx.x * blockDim.x + threadIdx.x) * 4;
    if (i < n) {
        float4 v = *(const float4*)(s + i);
        unsigned h0, l0, h1, l1;
        split2(v.x, v.y, h0, l0);
        split2(v.z, v.w, h1, l1);
        *(uint2*)&hi[i] = make_uint2(h0, h1);
        *(uint2*)&lo[i] = make_uint2(l0, l1);
    }
}

// selected-expert conversion: grid (EXN/1024, 36, 3)
__global__ void convexp_kernel(const float* __restrict__ eg, const float* __restrict__ eu,
                               const float* __restrict__ ed,
                               bf16* gh, bf16* gl, bf16* uh, bf16* ul,
                               bf16* dh, bf16* dl, const int* __restrict__ ti) {
    const int slot = blockIdx.y, mat = blockIdx.z;
    const int l = slot / 6, e = ti[slot];
    long i = ((long)blockIdx.x * 256 + threadIdx.x) * 4;
    if (i >= EXN) return;
    const float* src; bf16 *hi, *lo;
    if (mat == 0)      { src = eg; hi = gh; lo = gl; }
    else if (mat == 1) { src = eu; hi = uh; lo = ul; }
    else               { src = ed; hi = dh; lo = dl; }
    src += ((long)l * 10 + e) * EXN + i;
    hi  += (long)slot * EXN + i;
    lo  += (long)slot * EXN + i;
    float4 v = *(const float4*)src;
    unsigned h0, l0, h1, l1;
    split2(v.x, v.y, h0, l0);
    split2(v.z, v.w, h1, l1);
    *(uint2*)hi = make_uint2(h0, h1);
    *(uint2*)lo = make_uint2(l0, l1);
}

// ---------------- embedding ----------------
__global__ void embed_kernel(const int* __restrict__ idx,
                             const float* __restrict__ emb,
                             float* __restrict__ x) {
    long i = (long)blockIdx.x * blockDim.x + threadIdx.x;
    if (i < (long)ROWS * DD) {
        long r = i / DD, c = i % DD;
        x[i] = emb[(long)idx[r] * DD + c];
    }
}

// ---------------- consciousness vector (tiny MLP) ----------------
__global__ void cv_kernel(const float* __restrict__ cs,
                          const float* __restrict__ w1, const float* __restrict__ b1,
                          const float* __restrict__ w2, const float* __restrict__ b2,
                          float* __restrict__ cv) {
    __shared__ float pooled[BB][CDD];
    __shared__ float h1[BB][64];
    int t = threadIdx.x;  // 256 threads
    {
        int b = t / CDD, c = t % CDD;
        float s = 0.f;
        for (int n = 0; n < NCC; n++)
            s += cs[((long)b * NCC + n) * CDD + c];
        pooled[b][c] = s * (1.f / NCC);
    }
    __syncthreads();
    if (t < BB * 64) {
        int b = t / 64, j = t % 64;
        float z = b1[j];
        for (int c = 0; c < CDD; c++) z += pooled[b][c] * w1[c * 64 + j];
        float z3 = z * z * z;
        h1[b][j] = 0.5f * z * (1.f + tanhf(0.7978845608028654f * (z + 0.044715f * z3)));
    }
    __syncthreads();
    if (t < BB * 10) {
        int b = t / 10, i = t % 10;
        float z = b2[i];
        for (int j = 0; j < 64; j++) z += h1[b][j] * w2[j * 10 + i];
        cv[b * 10 + i] = 1.f / (1.f + expf(-z));
    }
}

// ---------------- routers for all layers ----------------
__global__ void router_all_kernel(const float* __restrict__ cv,
                                  const float* __restrict__ W,
                                  const float* __restrict__ bias,
                                  float* __restrict__ tw, int* __restrict__ ti) {
    int l = blockIdx.x;
    int b = threadIdx.x;
    if (b >= BB) return;
    const float* Wl = W + (long)l * 100;
    const float* bl = bias + (long)l * 10;
    float lg[10];
    float mx = -1e30f;
    for (int i = 0; i < 10; i++) {
        float z = bl[i];
        for (int j = 0; j < 10; j++) z += cv[b * 10 + j] * Wl[j * 10 + i];
        lg[i] = z;
        mx = fmaxf(mx, z);
    }
    float se = 0.f;
    for (int i = 0; i < 10; i++) { lg[i] = expf(lg[i] - mx); se += lg[i]; }
    for (int i = 0; i < 10; i++) lg[i] /= se;
    float wsum = 0.f;
    int base = l * 6 + b * 3;
    for (int kk = 0; kk < 3; kk++) {
        int bi = 0; float bv = -1.f;
        for (int i = 0; i < 10; i++) if (lg[i] > bv) { bv = lg[i]; bi = i; }
        ti[base + kk] = bi; tw[base + kk] = bv; wsum += bv;
        lg[bi] = -2.f;
    }
    for (int kk = 0; kk < 3; kk++) tw[base + kk] /= wsum;
}

// ---------------- RMSNorm -> bf16 hi/lo planes ----------------
__global__ void __launch_bounds__(256) rms_kernel(const float* __restrict__ x,
                                                  const float* __restrict__ w,
                                                  bf16* __restrict__ oh,
                                                  bf16* __restrict__ ol) {
    int row = blockIdx.x, t = threadIdx.x;
    const float* xr = x + (long)row * DD;
    float v0 = xr[t], v1 = xr[t + 256], v2 = xr[t + 512];
    float tot = block_reduce_sum_256(v0 * v0 + v1 * v1 + v2 * v2);
    float s = rsqrtf(tot * (1.f / DD) + 1e-6f);
    bf16* ohr = oh + (long)row * DD;
    bf16* olr = ol + (long)row * DD;
    split1(v0 * s * w[t],       ohr[t],       olr[t]);
    split1(v1 * s * w[t + 256], ohr[t + 256], olr[t + 256]);
    split1(v2 * s * w[t + 512], ohr[t + 512], olr[t + 512]);
}

// ---------------- fused: x += p0+p1+p2 (MoE-down partials), then RMSNorm -------
__global__ void __launch_bounds__(256) rms_sum_kernel(float* __restrict__ x,
                                                      const float* __restrict__ p,
                                                      const float* __restrict__ w,
                                                      bf16* __restrict__ oh,
                                                      bf16* __restrict__ ol) {
    int row = blockIdx.x, t = threadIdx.x;
    float* xr = x + (long)row * DD;
    const float* p0 = p + (long)row * DD;
    const float* p1 = p + (long)ROWS * DD + (long)row * DD;
    const float* p2 = p + 2L * ROWS * DD + (long)row * DD;
    float v0 = xr[t]       + p0[t]       + p1[t]       + p2[t];
    float v1 = xr[t + 256] + p0[t + 256] + p1[t + 256] + p2[t + 256];
    float v2 = xr[t + 512] + p0[t + 512] + p1[t + 512] + p2[t + 512];
    xr[t] = v0; xr[t + 256] = v1; xr[t + 512] = v2;
    float tot = block_reduce_sum_256(v0 * v0 + v1 * v1 + v2 * v2);
    float s = rsqrtf(tot * (1.f / DD) + 1e-6f);
    bf16* ohr = oh + (long)row * DD;
    bf16* olr = ol + (long)row * DD;
    split1(v0 * s * w[t],       ohr[t],       olr[t]);
    split1(v1 * s * w[t + 256], ohr[t + 256], olr[t + 256]);
    split1(v2 * s * w[t + 512], ohr[t + 512], olr[t + 512]);
}

// ---------------- fused cs-residual add + RMSNorm (MoE norm, l>0) --------------
__global__ void __launch_bounds__(256) rms_cs_kernel(float* __restrict__ x,
                                                     const float* __restrict__ w,
                                                     const float* __restrict__ tension,
                                                     const float* __restrict__ twv,
                                                     bf16* __restrict__ oh,
                                                     bf16* __restrict__ ol) {
    int row = blockIdx.x, t = threadIdx.x;
    float* xr = x + (long)row * DD;
    float ten = tension[row] * GATE_STRENGTH;
    float v0 = xr[t]       + ten * twv[t];
    float v1 = xr[t + 256] + ten * twv[t + 256];
    float v2 = xr[t + 512] + ten * twv[t + 512];
    xr[t] = v0; xr[t + 256] = v1; xr[t + 512] = v2;
    float tot = block_reduce_sum_256(v0 * v0 + v1 * v1 + v2 * v2);
    float s = rsqrtf(tot * (1.f / DD) + 1e-6f);
    bf16* ohr = oh + (long)row * DD;
    bf16* olr = ol + (long)row * DD;
    split1(v0 * s * w[t],       ohr[t],       olr[t]);
    split1(v1 * s * w[t + 256], ohr[t + 256], olr[t + 256]);
    split1(v2 * s * w[t + 512], ohr[t + 512], olr[t + 512]);
}

// ---------------- SwiGLU (+ tension) -> bf16 planes ----------------
__global__ void __launch_bounds__(256) swiglu_kernel(const float* __restrict__ g,
                                                     const float* __restrict__ u,
                                                     bf16* __restrict__ oh,
                                                     bf16* __restrict__ ol,
                                                     float* __restrict__ tension) {
    int row = blockIdx.x, t = threadIdx.x;
    const float* gr = g + (long)row * DII;
    const float* ur = u + (long)row * DII;
    bf16* ohr = oh + (long)row * DII;
    bf16* olr = ol + (long)row * DII;
    float sum = 0.f;
    #pragma unroll
    for (int j = 0; j < 6; j++) {
        int c = t + j * 256;
        float a = gr[c], bv = ur[c];
        float hv = (a / (1.f + __expf(-a))) * bv;
        split1(hv, ohr[c], olr[c]);
        sum += hv;
    }
    float tot = block_reduce_sum_256(sum);
    if (t == 0) tension[row] = tanhf(tot * (1.f / DII));
}

// ---------------- MoE SwiGLU (folds router weight) -> bf16 planes --------------
__global__ void __launch_bounds__(256) swiglu_moe_kernel(const float* __restrict__ buf,
                                                         const float* __restrict__ tw,
                                                         bf16* __restrict__ mh,
                                                         bf16* __restrict__ ml) {
    int row = blockIdx.x, e = blockIdx.y, t = threadIdx.x;
    int b = row / TT;
    float scale = tw[b * 3 + e];
    const float* gr = buf + (long)(2 * e) * ROWS * DII + (long)row * DII;
    const float* ur = buf + (long)(2 * e + 1) * ROWS * DII + (long)row * DII;
    bf16* ohr = mh + (long)e * ROWS * DII + (long)row * DII;
    bf16* olr = ml + (long)e * ROWS * DII + (long)row * DII;
    #pragma unroll
    for (int j = 0; j < 6; j++) {
        int c = t + j * 256;
        float a = gr[c], bv = ur[c];
        split1((a / (1.f + __expf(-a))) * bv * scale, ohr[c], olr[c]);
    }
}

// ---------------- flash-style causal attention (fp32, GQA, shared K/V) ---------
// grid (T/64, NKV, B), 192 threads: 3 query-heads of one KV group share K/V tiles.
__global__ void __launch_bounds__(192) attn_kernel(const float* __restrict__ q,
                                                   const float* __restrict__ k,
                                                   const float* __restrict__ v,
                                                   bf16* __restrict__ oh,
                                                   bf16* __restrict__ ol) {
    const int q0  = blockIdx.x * 64;
    const int kvh = blockIdx.y;
    const int b   = blockIdx.z;
    const int tid = threadIdx.x;
    const int hq  = tid / 64;          // which of 3 query heads
    const int t   = tid % 64;          // query row within tile
    const int h   = kvh * 3 + hq;
    const int qg  = q0 + t;

    __shared__ float Ks[64][64];
    __shared__ float Vs[64][64];

    float qreg[64], acc[64];
    const float* qp = q + ((long)(b * TT + qg) * NHH + h) * HDD;
    #pragma unroll
    for (int d = 0; d < 64; d++) { qreg[d] = qp[d]; acc[d] = 0.f; }
    float lsum = 0.f;

    for (int s0 = 0; s0 <= q0; s0 += 64) {
        __syncthreads();
        for (int i = tid; i < 64 * 64; i += 192) {
            int r = i >> 6, c = i & 63;
            long base = ((long)(b * TT + s0 + r) * NKVV + kvh) * HDD + c;
            Ks[r][c] = k[base];
            Vs[r][c] = v[base];
        }
        __syncthreads();
        int kmax = min(64, qg - s0 + 1);
        for (int kk = 0; kk < kmax; kk++) {
            float s = 0.f;
            #pragma unroll
            for (int d = 0; d < 64; d++) s += qreg[d] * Ks[kk][d];
            float p = __expf(s * 0.125f);
            lsum += p;
            #pragma unroll
            for (int d = 0; d < 64; d++) acc[d] += p * Vs[kk][d];
        }
    }
    float inv = 1.f / lsum;
    long base = ((long)(b * TT + qg) * NHH + h) * HDD;
    #pragma unroll
    for (int d = 0; d < 64; d += 2) {
        unsigned hi, lo;
        split2(acc[d] * inv, acc[d + 1] * inv, hi, lo);
        *(unsigned*)&oh[base + d] = hi;
        *(unsigned*)&ol[base + d] = lo;
    }
}

// ---------------- tensor-core GEMM: bf16 hi/lo planes, cp.async, 2 CTA/SM ------
// C(MxN) = [C +] Ahi@Bhi + Ahi@Blo + Alo@Bhi   (fp32 accum)
// MODE 0: plain; optional pair (B2,C2) via blockIdx.z.
// MODE 1: MoE gate/up: z in [0,6): kexp=z>>1; plane = (z&1 ? B2 : B) +
//         (bb*3+kexp)*sstride; C += z*ROWS*N.
// MODE 2: MoE down, segment-split: z=seg in [0,3): A += seg*ROWS*K;
//         B += (bb*3+seg)*sstride; C += seg*ROWS*N (plain stores, no atomics).
template<bool ACC, bool TRANSB, int MODE>
__global__ void __launch_bounds__(256, 2) gemm_bf16(
    const bf16* __restrict__ Ah, const bf16* __restrict__ Al,
    const bf16* __restrict__ Bh, const bf16* __restrict__ Bl,
    float* __restrict__ C,
    const bf16* __restrict__ B2h, const bf16* __restrict__ B2l, float* __restrict__ C2,
    int M, int N, int K, long sstride)
{
    const int bx = blockIdx.x, by = blockIdx.y;
    const int bb = (by * 128) / TT;              // batch (tiles never straddle)
    if (MODE == 0) {
        if (B2h != nullptr && blockIdx.z == 1) { Bh = B2h; Bl = B2l; C = C2; }
    } else if (MODE == 1) {
        const int z = blockIdx.z, kexp = z >> 1;
        long off = (long)(bb * 3 + kexp) * sstride;
        if (z & 1) { Bh = B2h + off; Bl = B2l + off; }
        else       { Bh = Bh  + off; Bl = Bl  + off; }
        C += (long)z * ROWS * N;
    } else if (MODE == 2) {
        const int seg = blockIdx.z;
        Ah += (long)seg * ROWS * K;
        Al += (long)seg * ROWS * K;
        long off = (long)(bb * 3 + seg) * sstride;
        Bh += off; Bl += off;
        C += (long)seg * ROWS * N;
    }

    extern __shared__ bf16 sm[];
    constexpr int ASZ2 = 128 * 40;
    constexpr int BSZ2 = TRANSB ? 128 * 40 : 32 * 136;
    bf16* smAh = sm;                 // [2][ASZ2]
    bf16* smAl = smAh + 2 * ASZ2;
    bf16* smBh = smAl + 2 * ASZ2;    // [2][BSZ2]
    bf16* smBl = smBh + 2 * BSZ2;

    const unsigned uAh = (unsigned)__cvta_generic_to_shared(smAh);
    const unsigned uAl = (unsigned)__cvta_generic_to_shared(smAl);
    const unsigned uBh = (unsigned)__cvta_generic_to_shared(smBh);
    const unsigned uBl = (unsigned)__cvta_generic_to_shared(smBl);

    const int tid = threadIdx.x;
    const int wid = tid >> 5, lane = tid & 31;
    const int g = lane >> 2, t = lane & 3;
    const int m0 = (wid & 1) * 64, n0 = (wid >> 1) * 32;

    const int arow = tid >> 1, acb = (tid & 1) * 16;
    const int kr = tid >> 3,  nb = (tid & 7) * 16;

    const int total = K >> 5;

    auto issue = [&](int it, int st) {
        const int k0 = it * 32;
        long aoff = (long)(by * 128 + arow) * K + k0 + acb;
        unsigned d = uAh + (unsigned)(st * ASZ2 + arow * 40 + acb) * 2u;
        cp16(d, Ah + aoff);       cp16(d + 16, Ah + aoff + 8);
        d = uAl + (unsigned)(st * ASZ2 + arow * 40 + acb) * 2u;
        cp16(d, Al + aoff);       cp16(d + 16, Al + aoff + 8);
        if (TRANSB) {
            long boff = (long)(bx * 128 + arow) * K + k0 + acb;
            d = uBh + (unsigned)(st * BSZ2 + arow * 40 + acb) * 2u;
            cp16(d, Bh + boff);   cp16(d + 16, Bh + boff + 8);
            d = uBl + (unsigned)(st * BSZ2 + arow * 40 + acb) * 2u;
            cp16(d, Bl + boff);   cp16(d + 16, Bl + boff + 8);
        } else {
            long boff = (long)(k0 + kr) * N + bx * 128 + nb;
            d = uBh + (unsigned)(st * BSZ2 + kr * 136 + nb) * 2u;
            cp16(d, Bh + boff);   cp16(d + 16, Bh + boff + 8);
            d = uBl + (unsigned)(st * BSZ2 + kr * 136 + nb) * 2u;
            cp16(d, Bl + boff);   cp16(d + 16, Bl + boff + 8);
        }
        cp_commit();
    };

    float acc[4][4][4];
    #pragma unroll
    for (int i = 0; i < 4; i++)
        #pragma unroll
        for (int j = 0; j < 4; j++)
            #pragma unroll
            for (int e = 0; e < 4; e++) acc[i][j][e] = 0.f;

    issue(0, 0);

    for (int it = 0; it < total; it++) {
        const int st = it & 1;
        cp_wait0();
        __syncthreads();
        if (it + 1 < total) issue(it + 1, st ^ 1);

        const unsigned aO = (unsigned)(st * ASZ2) * 2u;
        const unsigned bO = (unsigned)(st * BSZ2) * 2u;
        #pragma unroll
        for (int ks = 0; ks < 2; ks++) {
            const int kk = ks * 16;
            unsigned ah[4][4], al[4][4];
            #pragma unroll
            for (int i = 0; i < 4; i++) {
                int row = m0 + i * 16 + (lane & 15);
                int col = kk + (lane >> 4) * 8;
                unsigned off = (unsigned)(row * 40 + col) * 2u;
                ldsm_x4(ah[i][0], ah[i][1], ah[i][2], ah[i][3], uAh + aO + off);
                ldsm_x4(al[i][0], al[i][1], al[i][2], al[i][3], uAl + aO + off);
            }
            unsigned bh[4][2], bl[4][2];
            if (TRANSB) {
                #pragma unroll
                for (int jp = 0; jp < 2; jp++) {
                    int row = n0 + jp * 16 + (lane & 15);
                    int col = kk + (lane >> 4) * 8;
                    unsigned off = (unsigned)(row * 40 + col) * 2u;
                    unsigned r0, r1, r2, r3;
                    ldsm_x4(r0, r1, r2, r3, uBh + bO + off);
                    bh[2*jp][0] = r0; bh[2*jp+1][0] = r1;
                    bh[2*jp][1] = r2; bh[2*jp+1][1] = r3;
                    ldsm_x4(r0, r1, r2, r3, uBl + bO + off);
                    bl[2*jp][0] = r0; bl[2*jp+1][0] = r1;
                    bl[2*jp][1] = r2; bl[2*jp+1][1] = r3;
                }
            } else {
                #pragma unroll
                for (int jp = 0; jp < 2; jp++) {
                    int row = kk + (lane & 15);
                    int col = n0 + jp * 16 + (lane >> 4) * 8;
                    unsigned off = (unsigned)(row * 136 + col) * 2u;
                    unsigned r0, r1, r2, r3;
                    ldsm_x4_t(r0, r1, r2, r3, uBh + bO + off);
                    bh[2*jp][0] = r0; bh[2*jp][1] = r1;
                    bh[2*jp+1][0] = r2; bh[2*jp+1][1] = r3;
                    ldsm_x4_t(r0, r1, r2, r3, uBl + bO + off);
                    bl[2*jp][0] = r0; bl[2*jp][1] = r1;
                    bl[2*jp+1][0] = r2; bl[2*jp+1][1] = r3;
                }
            }
            #pragma unroll
            for (int j = 0; j < 4; j++) {
                #pragma unroll
                for (int i = 0; i < 4; i++) {
                    mma16816(acc[i][j], ah[i], bh[j]);
                    mma16816(acc[i][j], ah[i], bl[j]);
                    mma16816(acc[i][j], al[i], bh[j]);
                }
            }
        }
    }

    // ---- epilogue ----
    #pragma unroll
    for (int i = 0; i < 4; i++) {
        long r0 = (long)(by * 128 + m0 + i * 16 + g);
        long r1 = r0 + 8;
        #pragma unroll
        for (int j = 0; j < 4; j++) {
            long c = (long)(bx * 128 + n0 + j * 8 + 2 * t);
            if (ACC) {
                C[r0 * N + c]     += acc[i][j][0];
                C[r0 * N + c + 1] += acc[i][j][1];
                C[r1 * N + c]     += acc[i][j][2];
                C[r1 * N + c + 1] += acc[i][j][3];
            } else {
                *(float2*)&C[r0 * N + c] = make_float2(acc[i][j][0], acc[i][j][1]);
                *(float2*)&C[r1 * N + c] = make_float2(acc[i][j][2], acc[i][j][3]);
            }
        }
    }
}

// smem sizes
constexpr int SMN = (4 * 128 * 40 + 4 * 32 * 136) * 2;   // 75,776 B
constexpr int SMT = (4 * 128 * 40 + 4 * 128 * 40) * 2;   // 81,920 B

// ---------------- launch ----------------
extern "C" void kernel_launch(void* const* d_in, const int* in_sizes, int n_in,
                              void* d_out, int out_size) {
    const int*   idx       = (const int*)  d_in[0];
    const float* cons      = (const float*)d_in[1];
    const float* tok_emb   = (const float*)d_in[2];
    const float* head_g    = (const float*)d_in[3];
    const float* cv_w1     = (const float*)d_in[4];
    const float* cv_b1     = (const float*)d_in[5];
    const float* cv_w2     = (const float*)d_in[6];
    const float* cv_b2     = (const float*)d_in[7];
    const float* tension_w = (const float*)d_in[8];
    const float* ln_attn   = (const float*)d_in[9];
    const float* ln_pf     = (const float*)d_in[10];
    const float* ln_moe    = (const float*)d_in[11];
    const float* ln_f      = (const float*)d_in[12];
    const float* wq        = (const float*)d_in[13];
    const float* wk        = (const float*)d_in[14];
    const float* wv        = (const float*)d_in[15];
    const float* wo        = (const float*)d_in[16];
    const float* pf_gate   = (const float*)d_in[17];
    const float* pf_up     = (const float*)d_in[18];
    const float* pf_down   = (const float*)d_in[19];
    const float* e_gate    = (const float*)d_in[20];
    const float* e_up      = (const float*)d_in[21];
    const float* e_down    = (const float*)d_in[22];
    const float* router_w  = (const float*)d_in[23];
    const float* router_b  = (const float*)d_in[24];
    float* out = (float*)d_out;

    // scratch addresses
    float *xp, *qp, *kp, *vp, *ebp, *cvp, *twp;  int* tip;
    bf16 *hh, *hl, *aoh, *aol, *hdh, *hdl, *mhh, *mhl;
    bf16 *wqh, *wql, *wkh, *wkl, *wvh, *wvl, *woh, *wol;
    bf16 *pgh, *pgl, *puh, *pul, *pdh, *pdl;
    bf16 *emh, *eml, *hgh, *hgl;
    bf16 *egh, *egl, *euh, *eul, *edh, *edl;
    cudaGetSymbolAddress((void**)&xp,  g_x);
    cudaGetSymbolAddress((void**)&qp,  g_q);
    cudaGetSymbolAddress((void**)&kp,  g_k);
    cudaGetSymbolAddress((void**)&vp,  g_v);
    cudaGetSymbolAddress((void**)&ebp, g_eb);
    cudaGetSymbolAddress((void**)&cvp, g_cv);
    cudaGetSymbolAddress((void**)&twp, g_tw);
    cudaGetSymbolAddress((void**)&tip, g_ti);
    cudaGetSymbolAddress((void**)&hh,  g_h_h);  cudaGetSymbolAddress((void**)&hl,  g_h_l);
    cudaGetSymbolAddress((void**)&aoh, g_ao_h); cudaGetSymbolAddress((void**)&aol, g_ao_l);
    cudaGetSymbolAddress((void**)&hdh, g_hd_h); cudaGetSymbolAddress((void**)&hdl, g_hd_l);
    cudaGetSymbolAddress((void**)&mhh, g_mh_h); cudaGetSymbolAddress((void**)&mhl, g_mh_l);
    cudaGetSymbolAddress((void**)&wqh, g_wq_h); cudaGetSymbolAddress((void**)&wql, g_wq_l);
    cudaGetSymbolAddress((void**)&wkh, g_wk_h); cudaGetSymbolAddress((void**)&wkl, g_wk_l);
    cudaGetSymbolAddress((void**)&wvh, g_wv_h); cudaGetSymbolAddress((void**)&wvl, g_wv_l);
    cudaGetSymbolAddress((void**)&woh, g_wo_h); cudaGetSymbolAddress((void**)&wol, g_wo_l);
    cudaGetSymbolAddress((void**)&pgh, g_pg_h); cudaGetSymbolAddress((void**)&pgl, g_pg_l);
    cudaGetSymbolAddress((void**)&puh, g_pu_h); cudaGetSymbolAddress((void**)&pul, g_pu_l);
    cudaGetSymbolAddress((void**)&pdh, g_pd_h); cudaGetSymbolAddress((void**)&pdl, g_pd_l);
    cudaGetSymbolAddress((void**)&emh, g_em_h); cudaGetSymbolAddress((void**)&eml, g_em_l);
    cudaGetSymbolAddress((void**)&hgh, g_hg_h); cudaGetSymbolAddress((void**)&hgl, g_hg_l);
    cudaGetSymbolAddress((void**)&egh, g_eg_h); cudaGetSymbolAddress((void**)&egl, g_eg_l);
    cudaGetSymbolAddress((void**)&euh, g_eu_h); cudaGetSymbolAddress((void**)&eul, g_eu_l);
    cudaGetSymbolAddress((void**)&edh, g_ed_h); cudaGetSymbolAddress((void**)&edl, g_ed_l);

    // opt-in smem (idempotent host calls, not captured)
    cudaFuncSetAttribute(gemm_bf16<false, false, 0>, cudaFuncAttributeMaxDynamicSharedMemorySize, SMN);
    cudaFuncSetAttribute(gemm_bf16<true,  false, 0>, cudaFuncAttributeMaxDynamicSharedMemorySize, SMN);
    cudaFuncSetAttribute(gemm_bf16<false, false, 1>, cudaFuncAttributeMaxDynamicSharedMemorySize, SMN);
    cudaFuncSetAttribute(gemm_bf16<false, false, 2>, cudaFuncAttributeMaxDynamicSharedMemorySize, SMN);
    cudaFuncSetAttribute(gemm_bf16<false, true,  0>, cudaFuncAttributeMaxDynamicSharedMemorySize, SMT);

    float* tens = out + (long)2 * ROWS * VV;   // output tail: tensions (L, B, T)
    float* b1p = ebp;                          // PF gate fp32
    float* b2p = ebp + (long)ROWS * DII;       // PF up fp32
    float* pdown = ebp;                        // MoE-down partials (3 x ROWS x DD),
                                               // reuses gate/up space after swiglu_moe

    // ---- preprocessing: embed, cv, routers, weight conversion ----
    embed_kernel<<<(ROWS * DD + 255) / 256, 256>>>(idx, tok_emb, xp);
    cv_kernel<<<1, 256>>>(cons, cv_w1, cv_b1, cv_w2, cv_b2, cvp);
    router_all_kernel<<<LL, 32>>>(cvp, router_w, router_b, twp, tip);

    auto convw = [&](const float* s, bf16* hi, bf16* lo, long n) {
        convw_kernel<<<(int)(n / 4 / 256), 256>>>(s, hi, lo, n);
    };
    convw(wq, wqh, wql, 6L * 768 * 768);
    convw(wk, wkh, wkl, 6L * 768 * 256);
    convw(wv, wvh, wvl, 6L * 768 * 256);
    convw(wo, woh, wol, 6L * 768 * 768);
    convw(pf_gate, pgh, pgl, 6L * 768 * 1536);
    convw(pf_up,   puh, pul, 6L * 768 * 1536);
    convw(pf_down, pdh, pdl, 6L * 1536 * 768);
    convw(tok_emb, emh, eml, (long)VV * DD);
    convw(head_g,  hgh, hgl, (long)VV * DD);
    convexp_kernel<<<dim3((int)(EXN / 4 / 256), 36, 3), 256>>>(
        e_gate, e_up, e_down, egh, egl, euh, eul, edh, edl, tip);

    const dim3 g768 (DD  / 128, ROWS / 128, 1);
    const dim3 gkv  (256 / 128, ROWS / 128, 2);
    const dim3 gff  (DII / 128, ROWS / 128, 2);
    const dim3 gegu (DII / 128, ROWS / 128, 6);
    const dim3 gdn3 (DD  / 128, ROWS / 128, 3);   // MoE down, 3 K-segments

    for (int l = 0; l < LL; l++) {
        long o768  = (long)l * 768 * 768;
        long o256  = (long)l * 768 * 256;
        long o1536 = (long)l * 768 * 1536;
        long oexp  = (long)l * 6 * EXN;

        // ---- attention norm: fold in previous layer's MoE-down partials ----
        if (l > 0)
            rms_sum_kernel<<<ROWS, 256>>>(xp, pdown, ln_attn + (long)l * DD, hh, hl);
        else
            rms_kernel<<<ROWS, 256>>>(xp, ln_attn + (long)l * DD, hh, hl);

        // ---- attention ----
        gemm_bf16<false, false, 0><<<g768, 256, SMN>>>(hh, hl, wqh + o768, wql + o768, qp,
                                                       nullptr, nullptr, nullptr,
                                                       ROWS, 768, DD, 0);
        gemm_bf16<false, false, 0><<<gkv, 256, SMN>>>(hh, hl, wkh + o256, wkl + o256, kp,
                                                      wvh + o256, wvl + o256, vp,
                                                      ROWS, 256, DD, 0);
        attn_kernel<<<dim3(TT / 64, NKVV, BB), 192>>>(qp, kp, vp, aoh, aol);
        gemm_bf16<true, false, 0><<<g768, 256, SMN>>>(aoh, aol, woh + o768, wol + o768, xp,
                                                      nullptr, nullptr, nullptr,
                                                      ROWS, DD, 768, 0);

        // ---- PureField FFN + tension ----
        rms_kernel<<<ROWS, 256>>>(xp, ln_pf + (long)l * DD, hh, hl);
        gemm_bf16<false, false, 0><<<gff, 256, SMN>>>(hh, hl, pgh + o1536, pgl + o1536, b1p,
                                                      puh + o1536, pul + o1536, b2p,
                                                      ROWS, DII, DD, 0);
        swiglu_kernel<<<ROWS, 256>>>(b1p, b2p, hdh, hdl, tens + (long)l * ROWS);
        gemm_bf16<true, false, 0><<<g768, 256, SMN>>>(hdh, hdl, pdh + (long)l * 1536 * 768,
                                                      pdl + (long)l * 1536 * 768, xp,
                                                      nullptr, nullptr, nullptr,
                                                      ROWS, DD, DII, 0);

        // ---- MoE norm (fused with cs residual for l>0) ----
        if (l > 0)
            rms_cs_kernel<<<ROWS, 256>>>(xp, ln_moe + (long)l * DD,
                                         tens + (long)(l - 1) * ROWS, tension_w, hh, hl);
        else
            rms_kernel<<<ROWS, 256>>>(xp, ln_moe + (long)l * DD, hh, hl);

        // ---- MoE ----
        gemm_bf16<false, false, 1><<<gegu, 256, SMN>>>(hh, hl, egh + oexp, egl + oexp, ebp,
                                                       euh + oexp, eul + oexp, nullptr,
                                                       ROWS, DII, DD, EXN);
        swiglu_moe_kernel<<<dim3(ROWS, 3), 256>>>(ebp, twp + (long)l * 6, mhh, mhl);
        // down: 3 segment partials into pdown (gate/up space now dead)
        gemm_bf16<false, false, 2><<<gdn3, 256, SMN>>>(mhh, mhl, edh + oexp, edl + oexp,
                                                       pdown, nullptr, nullptr, nullptr,
                                                       ROWS, DD, DII, EXN);
    }

    // ---- final norm (fold last layer's partials) + tied heads (paired) ----
    rms_sum_kernel<<<ROWS, 256>>>(xp, pdown, ln_f, hh, hl);
    const dim3 gv(VV / 128, ROWS / 128, 2);
    gemm_bf16<false, true, 0><<<gv, 256, SMT>>>(hh, hl, emh, eml, out,
                                                hgh, hgl, out + (long)ROWS * VV,
                                                ROWS, VV, DD, 0);
}

// round 12
// speedup vs baseline: 1.0065x; 1.0065x over previous
#include <cuda_runtime.h>
#include <cuda_bf16.h>
#include <math.h>

typedef __nv_bfloat16 bf16;

// ---------------- dims ----------------
#define BB   2
#define TT   2048
#define DD   768
#define NHH  12
#define NKVV 4
#define HDD  64
#define LL   6
#define VV   32000
#define DII  1536
#define NCC  64
#define CDD  128
#define ROWS (BB*TT)          // 4096
#define GATE_STRENGTH 0.001f
#define EXN  ((long)DD*DII)   // expert matrix elements = 1,179,648

// ---------------- fp32 scratch ----------------
__device__ float g_x [ROWS*DD];
__device__ float g_q [ROWS*NHH*HDD];
__device__ float g_k [ROWS*NKVV*HDD];
__device__ float g_v [ROWS*NKVV*HDD];
__device__ float g_eb[6L*ROWS*DII];    // gate/up GEMM outputs (PF uses slots 0,1)
__device__ float g_cv[BB*10];
__device__ float g_tw[LL*BB*3];
__device__ int   g_ti[LL*BB*3];

// ---------------- bf16 hi/lo activation planes ----------------
__device__ bf16 g_h_h [ROWS*DD],        g_h_l [ROWS*DD];
__device__ bf16 g_ao_h[ROWS*NHH*HDD],   g_ao_l[ROWS*NHH*HDD];
__device__ bf16 g_hd_h[ROWS*DII],       g_hd_l[ROWS*DII];       // PF hidden
__device__ bf16 g_mh_h[3L*ROWS*DII],    g_mh_l[3L*ROWS*DII];    // MoE hidden

// ---------------- bf16 hi/lo weight planes (same layout as source) -------------
__device__ bf16 g_wq_h[6L*768*768],  g_wq_l[6L*768*768];
__device__ bf16 g_wk_h[6L*768*256],  g_wk_l[6L*768*256];
__device__ bf16 g_wv_h[6L*768*256],  g_wv_l[6L*768*256];
__device__ bf16 g_wo_h[6L*768*768],  g_wo_l[6L*768*768];
__device__ bf16 g_pg_h[6L*768*1536], g_pg_l[6L*768*1536];
__device__ bf16 g_pu_h[6L*768*1536], g_pu_l[6L*768*1536];
__device__ bf16 g_pd_h[6L*1536*768], g_pd_l[6L*1536*768];
__device__ bf16 g_em_h[(long)VV*DD], g_em_l[(long)VV*DD];   // [N][K] for TRANSB
__device__ bf16 g_hg_h[(long)VV*DD], g_hg_l[(long)VV*DD];
__device__ bf16 g_eg_h[36L*DD*DII],  g_eg_l[36L*DD*DII];
__device__ bf16 g_eu_h[36L*DD*DII],  g_eu_l[36L*DD*DII];
__device__ bf16 g_ed_h[36L*DD*DII],  g_ed_l[36L*DD*DII];

// ---------------- helpers ----------------
__device__ __forceinline__ float block_reduce_sum_256(float v) {
    __shared__ float red[8];
    int t = threadIdx.x;
    #pragma unroll
    for (int off = 16; off; off >>= 1) v += __shfl_xor_sync(0xffffffffu, v, off);
    if ((t & 31) == 0) red[t >> 5] = v;
    __syncthreads();
    float tot = 0.f;
    #pragma unroll
    for (int i = 0; i < 8; i++) tot += red[i];
    return tot;
}

__device__ __forceinline__ void split1(float f, bf16& h, bf16& l) {
    h = __float2bfloat16_rn(f);
    l = __float2bfloat16_rn(f - __bfloat162float(h));
}

__device__ __forceinline__ void split2(float f0, float f1, unsigned& hi, unsigned& lo) {
    __nv_bfloat162 h = __floats2bfloat162_rn(f0, f1);
    float r0 = f0 - __bfloat162float(__low2bfloat16(h));
    float r1 = f1 - __bfloat162float(__high2bfloat16(h));
    __nv_bfloat162 l = __floats2bfloat162_rn(r0, r1);
    hi = *(unsigned*)&h;
    lo = *(unsigned*)&l;
}

__device__ __forceinline__ void mma16816(float* c, const unsigned* a, const unsigned* b) {
    asm volatile(
        "mma.sync.aligned.m16n8k16.row.col.f32.bf16.bf16.f32 "
        "{%0,%1,%2,%3}, {%4,%5,%6,%7}, {%8,%9}, {%0,%1,%2,%3};\n"
        : "+f"(c[0]), "+f"(c[1]), "+f"(c[2]), "+f"(c[3])
        : "r"(a[0]), "r"(a[1]), "r"(a[2]), "r"(a[3]), "r"(b[0]), "r"(b[1]));
}

__device__ __forceinline__ void ldsm_x4(unsigned& r0, unsigned& r1, unsigned& r2,
                                        unsigned& r3, unsigned addr) {
    asm volatile("ldmatrix.sync.aligned.m8n8.x4.shared.b16 {%0,%1,%2,%3}, [%4];\n"
                 : "=r"(r0), "=r"(r1), "=r"(r2), "=r"(r3) : "r"(addr));
}

__device__ __forceinline__ void ldsm_x4_t(unsigned& r0, unsigned& r1, unsigned& r2,
                                          unsigned& r3, unsigned addr) {
    asm volatile("ldmatrix.sync.aligned.m8n8.x4.trans.shared.b16 {%0,%1,%2,%3}, [%4];\n"
                 : "=r"(r0), "=r"(r1), "=r"(r2), "=r"(r3) : "r"(addr));
}

__device__ __forceinline__ void cp16(unsigned dst, const void* src) {
    asm volatile("cp.async.cg.shared.global [%0], [%1], 16;\n" :: "r"(dst), "l"(src));
}
__device__ __forceinline__ void cp_commit() { asm volatile("cp.async.commit_group;\n"); }

// ---------------- weight converters (no transpose; layouts as in source) -------
__global__ void convw_kernel(const float* __restrict__ s, bf16* __restrict__ hi,
                             bf16* __restrict__ lo, long n) {
    long i = ((long)blockIdx.x * blockDim.x + threadIdx.x) * 4;
    if (i < n) {
        float4 v = *(const float4*)(s + i);
        unsigned h0, l0, h1, l1;
        split2(v.x, v.y, h0, l0);
        split2(v.z, v.w, h1, l1);
        *(uint2*)&hi[i] = make_uint2(h0, h1);
        *(uint2*)&lo[i] = make_uint2(l0, l1);
    }
}

// selected-expert conversion: grid (EXN/1024, 36, 3)
__global__ void convexp_kernel(const float* __restrict__ eg, const float* __restrict__ eu,
                               const float* __restrict__ ed,
                               bf16* gh, bf16* gl, bf16* uh, bf16* ul,
                               bf16* dh, bf16* dl, const int* __restrict__ ti) {
    const int slot = blockIdx.y, mat = blockIdx.z;
    const int l = slot / 6, e = ti[slot];
    long i = ((long)blockIdx.x * 256 + threadIdx.x) * 4;
    if (i >= EXN) return;
    const float* src; bf16 *hi, *lo;
    if (mat == 0)      { src = eg; hi = gh; lo = gl; }
    else if (mat == 1) { src = eu; hi = uh; lo = ul; }
    else               { src = ed; hi = dh; lo = dl; }
    src += ((long)l * 10 + e) * EXN + i;
    hi  += (long)slot * EXN + i;
    lo  += (long)slot * EXN + i;
    float4 v = *(const float4*)src;
    unsigned h0, l0, h1, l1;
    split2(v.x, v.y, h0, l0);
    split2(v.z, v.w, h1, l1);
    *(uint2*)hi = make_uint2(h0, h1);
    *(uint2*)lo = make_uint2(l0, l1);
}

// ---------------- embedding ----------------
__global__ void embed_kernel(const int* __restrict__ idx,
                             const float* __restrict__ emb,
                             float* __restrict__ x) {
    long i = (long)blockIdx.x * blockDim.x + threadIdx.x;
    if (i < (long)ROWS * DD) {
        long r = i / DD, c = i % DD;
        x[i] = emb[(long)idx[r] * DD + c];
    }
}

// ---------------- consciousness vector (tiny MLP) ----------------
__global__ void cv_kernel(const float* __restrict__ cs,
                          const float* __restrict__ w1, const float* __restrict__ b1,
                          const float* __restrict__ w2, const float* __restrict__ b2,
                          float* __restrict__ cv) {
    __shared__ float pooled[BB][CDD];
    __shared__ float h1[BB][64];
    int t = threadIdx.x;  // 256 threads
    {
        int b = t / CDD, c = t % CDD;
        float s = 0.f;
        for (int n = 0; n < NCC; n++)
            s += cs[((long)b * NCC + n) * CDD + c];
        pooled[b][c] = s * (1.f / NCC);
    }
    __syncthreads();
    if (t < BB * 64) {
        int b = t / 64, j = t % 64;
        float z = b1[j];
        for (int c = 0; c < CDD; c++) z += pooled[b][c] * w1[c * 64 + j];
        float z3 = z * z * z;
        h1[b][j] = 0.5f * z * (1.f + tanhf(0.7978845608028654f * (z + 0.044715f * z3)));
    }
    __syncthreads();
    if (t < BB * 10) {
        int b = t / 10, i = t % 10;
        float z = b2[i];
        for (int j = 0; j < 64; j++) z += h1[b][j] * w2[j * 10 + i];
        cv[b * 10 + i] = 1.f / (1.f + expf(-z));
    }
}

// ---------------- routers for all layers ----------------
__global__ void router_all_kernel(const float* __restrict__ cv,
                                  const float* __restrict__ W,
                                  const float* __restrict__ bias,
                                  float* __restrict__ tw, int* __restrict__ ti) {
    int l = blockIdx.x;
    int b = threadIdx.x;
    if (b >= BB) return;
    const float* Wl = W + (long)l * 100;
    const float* bl = bias + (long)l * 10;
    float lg[10];
    float mx = -1e30f;
    for (int i = 0; i < 10; i++) {
        float z = bl[i];
        for (int j = 0; j < 10; j++) z += cv[b * 10 + j] * Wl[j * 10 + i];
        lg[i] = z;
        mx = fmaxf(mx, z);
    }
    float se = 0.f;
    for (int i = 0; i < 10; i++) { lg[i] = expf(lg[i] - mx); se += lg[i]; }
    for (int i = 0; i < 10; i++) lg[i] /= se;
    float wsum = 0.f;
    int base = l * 6 + b * 3;
    for (int kk = 0; kk < 3; kk++) {
        int bi = 0; float bv = -1.f;
        for (int i = 0; i < 10; i++) if (lg[i] > bv) { bv = lg[i]; bi = i; }
        ti[base + kk] = bi; tw[base + kk] = bv; wsum += bv;
        lg[bi] = -2.f;
    }
    for (int kk = 0; kk < 3; kk++) tw[base + kk] /= wsum;
}

// ---------------- RMSNorm -> bf16 hi/lo planes ----------------
__global__ void __launch_bounds__(256) rms_kernel(const float* __restrict__ x,
                                                  const float* __restrict__ w,
                                                  bf16* __restrict__ oh,
                                                  bf16* __restrict__ ol) {
    int row = blockIdx.x, t = threadIdx.x;
    const float* xr = x + (long)row * DD;
    float v0 = xr[t], v1 = xr[t + 256], v2 = xr[t + 512];
    float tot = block_reduce_sum_256(v0 * v0 + v1 * v1 + v2 * v2);
    float s = rsqrtf(tot * (1.f / DD) + 1e-6f);
    bf16* ohr = oh + (long)row * DD;
    bf16* olr = ol + (long)row * DD;
    split1(v0 * s * w[t],       ohr[t],       olr[t]);
    split1(v1 * s * w[t + 256], ohr[t + 256], olr[t + 256]);
    split1(v2 * s * w[t + 512], ohr[t + 512], olr[t + 512]);
}

// ---------------- SwiGLU (+ tension) -> bf16 planes ----------------
__global__ void __launch_bounds__(256) swiglu_kernel(const float* __restrict__ g,
                                                     const float* __restrict__ u,
                                                     bf16* __restrict__ oh,
                                                     bf16* __restrict__ ol,
                                                     float* __restrict__ tension) {
    int row = blockIdx.x, t = threadIdx.x;
    const float* gr = g + (long)row * DII;
    const float* ur = u + (long)row * DII;
    bf16* ohr = oh + (long)row * DII;
    bf16* olr = ol + (long)row * DII;
    float sum = 0.f;
    #pragma unroll
    for (int j = 0; j < 6; j++) {
        int c = t + j * 256;
        float a = gr[c], bv = ur[c];
        float hv = (a / (1.f + __expf(-a))) * bv;
        split1(hv, ohr[c], olr[c]);
        sum += hv;
    }
    float tot = block_reduce_sum_256(sum);
    if (t == 0) tension[row] = tanhf(tot * (1.f / DII));
}

// ---------------- MoE SwiGLU (folds router weight) -> bf16 planes --------------
__global__ void __launch_bounds__(256) swiglu_moe_kernel(const float* __restrict__ buf,
                                                         const float* __restrict__ tw,
                                                         bf16* __restrict__ mh,
                                                         bf16* __restrict__ ml) {
    int row = blockIdx.x, e = blockIdx.y, t = threadIdx.x;
    int b = row / TT;
    float scale = tw[b * 3 + e];
    const float* gr = buf + (long)(2 * e) * ROWS * DII + (long)row * DII;
    const float* ur = buf + (long)(2 * e + 1) * ROWS * DII + (long)row * DII;
    bf16* ohr = mh + (long)e * ROWS * DII + (long)row * DII;
    bf16* olr = ml + (long)e * ROWS * DII + (long)row * DII;
    #pragma unroll
    for (int j = 0; j < 6; j++) {
        int c = t + j * 256;
        float a = gr[c], bv = ur[c];
        split1((a / (1.f + __expf(-a))) * bv * scale, ohr[c], olr[c]);
    }
}

// ---------------- consciousness-state residual add ----------------
__global__ void __launch_bounds__(256) csadd_kernel(float* __restrict__ x,
                                                    const float* __restrict__ tension,
                                                    const float* __restrict__ tw) {
    int row = blockIdx.x, t = threadIdx.x;
    float ten = tension[row] * GATE_STRENGTH;
    float* xr = x + (long)row * DD;
    xr[t]       += ten * tw[t];
    xr[t + 256] += ten * tw[t + 256];
    xr[t + 512] += ten * tw[t + 512];
}

// ---------------- flash-style causal attention (fp32, GQA) ----------------
__global__ void __launch_bounds__(64) attn_kernel(const float* __restrict__ q,
                                                  const float* __restrict__ k,
                                                  const float* __restrict__ v,
                                                  bf16* __restrict__ oh,
                                                  bf16* __restrict__ ol) {
    const int q0 = blockIdx.x * 64;
    const int h  = blockIdx.y;
    const int b  = blockIdx.z;
    const int t  = threadIdx.x;
    const int qg = q0 + t;
    const int kvh = h / (NHH / NKVV);

    __shared__ float Ks[64][64];
    __shared__ float Vs[64][64];

    float qreg[64], acc[64];
    const float* qp = q + ((long)(b * TT + qg) * NHH + h) * HDD;
    #pragma unroll
    for (int d = 0; d < 64; d++) { qreg[d] = qp[d]; acc[d] = 0.f; }
    float lsum = 0.f;

    for (int s0 = 0; s0 <= q0; s0 += 64) {
        __syncthreads();
        #pragma unroll 8
        for (int r = 0; r < 64; r++) {
            long base = ((long)(b * TT + s0 + r) * NKVV + kvh) * HDD + t;
            Ks[r][t] = k[base];
            Vs[r][t] = v[base];
        }
        __syncthreads();
        int kmax = min(64, qg - s0 + 1);
        for (int kk = 0; kk < kmax; kk++) {
            float s = 0.f;
            #pragma unroll
            for (int d = 0; d < 64; d++) s += qreg[d] * Ks[kk][d];
            float p = __expf(s * 0.125f);
            lsum += p;
            #pragma unroll
            for (int d = 0; d < 64; d++) acc[d] += p * Vs[kk][d];
        }
    }
    float inv = 1.f / lsum;
    long base = ((long)(b * TT + qg) * NHH + h) * HDD;
    #pragma unroll
    for (int d = 0; d < 64; d += 2) {
        unsigned hi, lo;
        split2(acc[d] * inv, acc[d + 1] * inv, hi, lo);
        *(unsigned*)&oh[base + d] = hi;
        *(unsigned*)&ol[base + d] = lo;
    }
}

// ---------------- tensor-core GEMM: bf16 hi/lo planes, cp.async, 2 CTA/SM ------
// C(MxN) = [C +] Ahi@Bhi + Ahi@Blo + Alo@Bhi   (fp32 accum)
// STAGES-deep cp.async pipeline (3 for non-trans, 2 for TRANSB to keep 2 CTA/SM).
// MODE 0: plain; optional pair (B2,C2) via blockIdx.z.
// MODE 1: MoE gate/up: z in [0,6): kexp=z>>1; plane = (z&1 ? B2 : B) +
//         (bb*3+kexp)*sstride; C += z*ROWS*N.
// MODE 2: MoE down: 3 K-segments; A seg s at +s*ROWS*K; B seg s at +(bb*3+s)*sstride.
template<bool ACC, bool TRANSB, int MODE, int STAGES>
__global__ void __launch_bounds__(256, 2) gemm_bf16(
    const bf16* __restrict__ Ah, const bf16* __restrict__ Al,
    const bf16* __restrict__ Bh, const bf16* __restrict__ Bl,
    float* __restrict__ C,
    const bf16* __restrict__ B2h, const bf16* __restrict__ B2l, float* __restrict__ C2,
    int M, int N, int K, long sstride)
{
    const int bx = blockIdx.x, by = blockIdx.y;
    const int bb = (by * 128) / TT;              // batch (tiles never straddle)
    if (MODE == 0) {
        if (B2h != nullptr && blockIdx.z == 1) { Bh = B2h; Bl = B2l; C = C2; }
    } else if (MODE == 1) {
        const int z = blockIdx.z, kexp = z >> 1;
        long off = (long)(bb * 3 + kexp) * sstride;
        if (z & 1) { Bh = B2h + off; Bl = B2l + off; }
        else       { Bh = Bh  + off; Bl = Bl  + off; }
        C += (long)z * ROWS * N;
    }
    const bf16 *Bsh[3], *Bsl[3];
    if (MODE == 2) {
        #pragma unroll
        for (int s = 0; s < 3; s++) {
            long off = (long)(bb * 3 + s) * sstride;
            Bsh[s] = Bh + off; Bsl[s] = Bl + off;
        }
    }

    extern __shared__ bf16 sm[];
    constexpr int ASZ2 = 128 * 40;
    constexpr int BSZ2 = TRANSB ? 128 * 40 : 32 * 136;
    bf16* smAh = sm;                        // [STAGES][ASZ2]
    bf16* smAl = smAh + STAGES * ASZ2;
    bf16* smBh = smAl + STAGES * ASZ2;      // [STAGES][BSZ2]
    bf16* smBl = smBh + STAGES * BSZ2;

    const unsigned uAh = (unsigned)__cvta_generic_to_shared(smAh);
    const unsigned uAl = (unsigned)__cvta_generic_to_shared(smAl);
    const unsigned uBh = (unsigned)__cvta_generic_to_shared(smBh);
    const unsigned uBl = (unsigned)__cvta_generic_to_shared(smBl);

    const int tid = threadIdx.x;
    const int wid = tid >> 5, lane = tid & 31;
    const int g = lane >> 2, t = lane & 3;
    const int m0 = (wid & 1) * 64, n0 = (wid >> 1) * 32;

    const int arow = tid >> 1, acb = (tid & 1) * 16;
    const int kr = tid >> 3,  nb = (tid & 7) * 16;

    const int kIters = K >> 5;
    const int total  = (MODE == 2 ? 3 : 1) * kIters;

    auto issue = [&](int it) {
        const int st  = it % STAGES;
        const int seg = (MODE == 2) ? it / kIters : 0;
        const int k0  = ((MODE == 2) ? (it % kIters) : it) * 32;
        const bf16* pAh = Ah + ((MODE == 2) ? (long)seg * ROWS * K : 0);
        const bf16* pAl = Al + ((MODE == 2) ? (long)seg * ROWS * K : 0);
        long aoff = (long)(by * 128 + arow) * K + k0 + acb;
        unsigned d = uAh + (unsigned)(st * ASZ2 + arow * 40 + acb) * 2u;
        cp16(d, pAh + aoff);       cp16(d + 16, pAh + aoff + 8);
        d = uAl + (unsigned)(st * ASZ2 + arow * 40 + acb) * 2u;
        cp16(d, pAl + aoff);       cp16(d + 16, pAl + aoff + 8);
        if (TRANSB) {
            long boff = (long)(bx * 128 + arow) * K + k0 + acb;
            d = uBh + (unsigned)(st * BSZ2 + arow * 40 + acb) * 2u;
            cp16(d, Bh + boff);   cp16(d + 16, Bh + boff + 8);
            d = uBl + (unsigned)(st * BSZ2 + arow * 40 + acb) * 2u;
            cp16(d, Bl + boff);   cp16(d + 16, Bl + boff + 8);
        } else {
            const bf16* pBh = (MODE == 2) ? Bsh[seg] : Bh;
            const bf16* pBl = (MODE == 2) ? Bsl[seg] : Bl;
            long boff = (long)(k0 + kr) * N + bx * 128 + nb;
            d = uBh + (unsigned)(st * BSZ2 + kr * 136 + nb) * 2u;
            cp16(d, pBh + boff);   cp16(d + 16, pBh + boff + 8);
            d = uBl + (unsigned)(st * BSZ2 + kr * 136 + nb) * 2u;
            cp16(d, pBl + boff);   cp16(d + 16, pBl + boff + 8);
        }
        cp_commit();
    };

    float acc[4][4][4];
    #pragma unroll
    for (int i = 0; i < 4; i++)
        #pragma unroll
        for (int j = 0; j < 4; j++)
            #pragma unroll
            for (int e = 0; e < 4; e++) acc[i][j][e] = 0.f;

    // preload STAGES-1 stages
    issue(0);
    if (STAGES >= 3 && total > 1) issue(1);

    for (int it = 0; it < total; it++) {
        const int st = it % STAGES;
        // wait so that stage `it` is complete
        if (STAGES >= 3 && it + 1 < total)
            asm volatile("cp.async.wait_group 1;\n" ::: "memory");
        else
            asm volatile("cp.async.wait_group 0;\n" ::: "memory");
        __syncthreads();
        if (it + STAGES - 1 < total) issue(it + STAGES - 1);

        const unsigned aO = (unsigned)(st * ASZ2) * 2u;
        const unsigned bO = (unsigned)(st * BSZ2) * 2u;
        #pragma unroll
        for (int ks = 0; ks < 2; ks++) {
            const int kk = ks * 16;
            unsigned ah[4][4], al[4][4];
            #pragma unroll
            for (int i = 0; i < 4; i++) {
                int row = m0 + i * 16 + (lane & 15);
                int col = kk + (lane >> 4) * 8;
                unsigned off = (unsigned)(row * 40 + col) * 2u;
                ldsm_x4(ah[i][0], ah[i][1], ah[i][2], ah[i][3], uAh + aO + off);
                ldsm_x4(al[i][0], al[i][1], al[i][2], al[i][3], uAl + aO + off);
            }
            unsigned bh[4][2], bl[4][2];
            if (TRANSB) {
                #pragma unroll
                for (int jp = 0; jp < 2; jp++) {
                    int row = n0 + jp * 16 + (lane & 15);
                    int col = kk + (lane >> 4) * 8;
                    unsigned off = (unsigned)(row * 40 + col) * 2u;
                    unsigned r0, r1, r2, r3;
                    ldsm_x4(r0, r1, r2, r3, uBh + bO + off);
                    bh[2*jp][0] = r0; bh[2*jp+1][0] = r1;
                    bh[2*jp][1] = r2; bh[2*jp+1][1] = r3;
                    ldsm_x4(r0, r1, r2, r3, uBl + bO + off);
                    bl[2*jp][0] = r0; bl[2*jp+1][0] = r1;
                    bl[2*jp][1] = r2; bl[2*jp+1][1] = r3;
                }
            } else {
                #pragma unroll
                for (int jp = 0; jp < 2; jp++) {
                    int row = kk + (lane & 15);
                    int col = n0 + jp * 16 + (lane >> 4) * 8;
                    unsigned off = (unsigned)(row * 136 + col) * 2u;
                    unsigned r0, r1, r2, r3;
                    ldsm_x4_t(r0, r1, r2, r3, uBh + bO + off);
                    bh[2*jp][0] = r0; bh[2*jp][1] = r1;
                    bh[2*jp+1][0] = r2; bh[2*jp+1][1] = r3;
                    ldsm_x4_t(r0, r1, r2, r3, uBl + bO + off);
                    bl[2*jp][0] = r0; bl[2*jp][1] = r1;
                    bl[2*jp+1][0] = r2; bl[2*jp+1][1] = r3;
                }
            }
            #pragma unroll
            for (int j = 0; j < 4; j++) {
                #pragma unroll
                for (int i = 0; i < 4; i++) {
                    mma16816(acc[i][j], ah[i], bh[j]);
                    mma16816(acc[i][j], ah[i], bl[j]);
                    mma16816(acc[i][j], al[i], bh[j]);
                }
            }
        }
    }

    // ---- epilogue ----
    #pragma unroll
    for (int i = 0; i < 4; i++) {
        long r0 = (long)(by * 128 + m0 + i * 16 + g);
        long r1 = r0 + 8;
        #pragma unroll
        for (int j = 0; j < 4; j++) {
            long c = (long)(bx * 128 + n0 + j * 8 + 2 * t);
            if (ACC) {
                C[r0 * N + c]     += acc[i][j][0];
                C[r0 * N + c + 1] += acc[i][j][1];
                C[r1 * N + c]     += acc[i][j][2];
                C[r1 * N + c + 1] += acc[i][j][3];
            } else {
                *(float2*)&C[r0 * N + c] = make_float2(acc[i][j][0], acc[i][j][1]);
                *(float2*)&C[r1 * N + c] = make_float2(acc[i][j][2], acc[i][j][3]);
            }
        }
    }
}

// smem sizes
constexpr int SMN = 3 * (2 * 128 * 40 + 2 * 32 * 136) * 2;   // 113,664 B (3-stage)
constexpr int SMT = 2 * (2 * 128 * 40 + 2 * 128 * 40) * 2;   //  81,920 B (2-stage)

// ---------------- launch ----------------
extern "C" void kernel_launch(void* const* d_in, const int* in_sizes, int n_in,
                              void* d_out, int out_size) {
    const int*   idx       = (const int*)  d_in[0];
    const float* cons      = (const float*)d_in[1];
    const float* tok_emb   = (const float*)d_in[2];
    const float* head_g    = (const float*)d_in[3];
    const float* cv_w1     = (const float*)d_in[4];
    const float* cv_b1     = (const float*)d_in[5];
    const float* cv_w2     = (const float*)d_in[6];
    const float* cv_b2     = (const float*)d_in[7];
    const float* tension_w = (const float*)d_in[8];
    const float* ln_attn   = (const float*)d_in[9];
    const float* ln_pf     = (const float*)d_in[10];
    const float* ln_moe    = (const float*)d_in[11];
    const float* ln_f      = (const float*)d_in[12];
    const float* wq        = (const float*)d_in[13];
    const float* wk        = (const float*)d_in[14];
    const float* wv        = (const float*)d_in[15];
    const float* wo        = (const float*)d_in[16];
    const float* pf_gate   = (const float*)d_in[17];
    const float* pf_up     = (const float*)d_in[18];
    const float* pf_down   = (const float*)d_in[19];
    const float* e_gate    = (const float*)d_in[20];
    const float* e_up      = (const float*)d_in[21];
    const float* e_down    = (const float*)d_in[22];
    const float* router_w  = (const float*)d_in[23];
    const float* router_b  = (const float*)d_in[24];
    float* out = (float*)d_out;

    // scratch addresses
    float *xp, *qp, *kp, *vp, *ebp, *cvp, *twp;  int* tip;
    bf16 *hh, *hl, *aoh, *aol, *hdh, *hdl, *mhh, *mhl;
    bf16 *wqh, *wql, *wkh, *wkl, *wvh, *wvl, *woh, *wol;
    bf16 *pgh, *pgl, *puh, *pul, *pdh, *pdl;
    bf16 *emh, *eml, *hgh, *hgl;
    bf16 *egh, *egl, *euh, *eul, *edh, *edl;
    cudaGetSymbolAddress((void**)&xp,  g_x);
    cudaGetSymbolAddress((void**)&qp,  g_q);
    cudaGetSymbolAddress((void**)&kp,  g_k);
    cudaGetSymbolAddress((void**)&vp,  g_v);
    cudaGetSymbolAddress((void**)&ebp, g_eb);
    cudaGetSymbolAddress((void**)&cvp, g_cv);
    cudaGetSymbolAddress((void**)&twp, g_tw);
    cudaGetSymbolAddress((void**)&tip, g_ti);
    cudaGetSymbolAddress((void**)&hh,  g_h_h);  cudaGetSymbolAddress((void**)&hl,  g_h_l);
    cudaGetSymbolAddress((void**)&aoh, g_ao_h); cudaGetSymbolAddress((void**)&aol, g_ao_l);
    cudaGetSymbolAddress((void**)&hdh, g_hd_h); cudaGetSymbolAddress((void**)&hdl, g_hd_l);
    cudaGetSymbolAddress((void**)&mhh, g_mh_h); cudaGetSymbolAddress((void**)&mhl, g_mh_l);
    cudaGetSymbolAddress((void**)&wqh, g_wq_h); cudaGetSymbolAddress((void**)&wql, g_wq_l);
    cudaGetSymbolAddress((void**)&wkh, g_wk_h); cudaGetSymbolAddress((void**)&wkl, g_wk_l);
    cudaGetSymbolAddress((void**)&wvh, g_wv_h); cudaGetSymbolAddress((void**)&wvl, g_wv_l);
    cudaGetSymbolAddress((void**)&woh, g_wo_h); cudaGetSymbolAddress((void**)&wol, g_wo_l);
    cudaGetSymbolAddress((void**)&pgh, g_pg_h); cudaGetSymbolAddress((void**)&pgl, g_pg_l);
    cudaGetSymbolAddress((void**)&puh, g_pu_h); cudaGetSymbolAddress((void**)&pul, g_pu_l);
    cudaGetSymbolAddress((void**)&pdh, g_pd_h); cudaGetSymbolAddress((void**)&pdl, g_pd_l);
    cudaGetSymbolAddress((void**)&emh, g_em_h); cudaGetSymbolAddress((void**)&eml, g_em_l);
    cudaGetSymbolAddress((void**)&hgh, g_hg_h); cudaGetSymbolAddress((void**)&hgl, g_hg_l);
    cudaGetSymbolAddress((void**)&egh, g_eg_h); cudaGetSymbolAddress((void**)&egl, g_eg_l);
    cudaGetSymbolAddress((void**)&euh, g_eu_h); cudaGetSymbolAddress((void**)&eul, g_eu_l);
    cudaGetSymbolAddress((void**)&edh, g_ed_h); cudaGetSymbolAddress((void**)&edl, g_ed_l);

    // opt-in smem (idempotent host calls, not captured)
    cudaFuncSetAttribute(gemm_bf16<false, false, 0, 3>, cudaFuncAttributeMaxDynamicSharedMemorySize, SMN);
    cudaFuncSetAttribute(gemm_bf16<true,  false, 0, 3>, cudaFuncAttributeMaxDynamicSharedMemorySize, SMN);
    cudaFuncSetAttribute(gemm_bf16<false, false, 1, 3>, cudaFuncAttributeMaxDynamicSharedMemorySize, SMN);
    cudaFuncSetAttribute(gemm_bf16<true,  false, 2, 3>, cudaFuncAttributeMaxDynamicSharedMemorySize, SMN);
    cudaFuncSetAttribute(gemm_bf16<false, true,  0, 2>, cudaFuncAttributeMaxDynamicSharedMemorySize, SMT);

    float* tens = out + (long)2 * ROWS * VV;   // output tail: tensions (L, B, T)
    float* b1p = ebp;                          // PF gate fp32
    float* b2p = ebp + (long)ROWS * DII;       // PF up fp32

    // ---- preprocessing: embed, cv, routers, weight conversion ----
    embed_kernel<<<(ROWS * DD + 255) / 256, 256>>>(idx, tok_emb, xp);
    cv_kernel<<<1, 256>>>(cons, cv_w1, cv_b1, cv_w2, cv_b2, cvp);
    router_all_kernel<<<LL, 32>>>(cvp, router_w, router_b, twp, tip);

    auto convw = [&](const float* s, bf16* hi, bf16* lo, long n) {
        convw_kernel<<<(int)(n / 4 / 256), 256>>>(s, hi, lo, n);
    };
    convw(wq, wqh, wql, 6L * 768 * 768);
    convw(wk, wkh, wkl, 6L * 768 * 256);
    convw(wv, wvh, wvl, 6L * 768 * 256);
    convw(wo, woh, wol, 6L * 768 * 768);
    convw(pf_gate, pgh, pgl, 6L * 768 * 1536);
    convw(pf_up,   puh, pul, 6L * 768 * 1536);
    convw(pf_down, pdh, pdl, 6L * 1536 * 768);
    convw(tok_emb, emh, eml, (long)VV * DD);
    convw(head_g,  hgh, hgl, (long)VV * DD);
    convexp_kernel<<<dim3((int)(EXN / 4 / 256), 36, 3), 256>>>(
        e_gate, e_up, e_down, egh, egl, euh, eul, edh, edl, tip);

    const dim3 g768 (DD  / 128, ROWS / 128, 1);
    const dim3 gkv  (256 / 128, ROWS / 128, 2);
    const dim3 gff  (DII / 128, ROWS / 128, 2);
    const dim3 gegu (DII / 128, ROWS / 128, 6);
    const dim3 gdn  (DD  / 128, ROWS / 128, 1);

    for (int l = 0; l < LL; l++) {
        long o768  = (long)l * 768 * 768;
        long o256  = (long)l * 768 * 256;
        long o1536 = (long)l * 768 * 1536;
        long oexp  = (long)l * 6 * EXN;

        // ---- attention ----
        rms_kernel<<<ROWS, 256>>>(xp, ln_attn + (long)l * DD, hh, hl);
        gemm_bf16<false, false, 0, 3><<<g768, 256, SMN>>>(hh, hl, wqh + o768, wql + o768, qp,
                                                          nullptr, nullptr, nullptr,
                                                          ROWS, 768, DD, 0);
        gemm_bf16<false, false, 0, 3><<<gkv, 256, SMN>>>(hh, hl, wkh + o256, wkl + o256, kp,
                                                         wvh + o256, wvl + o256, vp,
                                                         ROWS, 256, DD, 0);
        attn_kernel<<<dim3(TT / 64, NHH, BB), 64>>>(qp, kp, vp, aoh, aol);
        gemm_bf16<true, false, 0, 3><<<g768, 256, SMN>>>(aoh, aol, woh + o768, wol + o768, xp,
                                                         nullptr, nullptr, nullptr,
                                                         ROWS, DD, 768, 0);

        // ---- PureField FFN + tension ----
        rms_kernel<<<ROWS, 256>>>(xp, ln_pf + (long)l * DD, hh, hl);
        gemm_bf16<false, false, 0, 3><<<gff, 256, SMN>>>(hh, hl, pgh + o1536, pgl + o1536, b1p,
                                                         puh + o1536, pul + o1536, b2p,
                                                         ROWS, DII, DD, 0);
        swiglu_kernel<<<ROWS, 256>>>(b1p, b2p, hdh, hdl, tens + (long)l * ROWS);
        gemm_bf16<true, false, 0, 3><<<g768, 256, SMN>>>(hdh, hdl, pdh + (long)l * 1536 * 768,
                                                         pdl + (long)l * 1536 * 768, xp,
                                                         nullptr, nullptr, nullptr,
                                                         ROWS, DD, DII, 0);

        // ---- consciousness-state residual (previous layer's tension) ----
        if (l > 0)
            csadd_kernel<<<ROWS, 256>>>(xp, tens + (long)(l - 1) * ROWS, tension_w);

        // ---- MoE ----
        rms_kernel<<<ROWS, 256>>>(xp, ln_moe + (long)l * DD, hh, hl);
        gemm_bf16<false, false, 1, 3><<<gegu, 256, SMN>>>(hh, hl, egh + oexp, egl + oexp, ebp,
                                                          euh + oexp, eul + oexp, nullptr,
                                                          ROWS, DII, DD, EXN);
        swiglu_moe_kernel<<<dim3(ROWS, 3), 256>>>(ebp, twp + (long)l * 6, mhh, mhl);
        gemm_bf16<true, false, 2, 3><<<gdn, 256, SMN>>>(mhh, mhl, edh + oexp, edl + oexp, xp,
                                                        nullptr, nullptr, nullptr,
                                                        ROWS, DD, DII, EXN);
    }

    // ---- final norm + tied heads (paired) ----
    rms_kernel<<<ROWS, 256>>>(xp, ln_f, hh, hl);
    const dim3 gv(VV / 128, ROWS / 128, 2);
    gemm_bf16<false, true, 0, 2><<<gv, 256, SMT>>>(hh, hl, emh, eml, out,
                                                   hgh, hgl, out + (long)ROWS * VV,
                                                   ROWS, VV, DD, 0);
}

// round 13
// speedup vs baseline: 1.3219x; 1.3133x over previous
#include <cuda_runtime.h>
#include <cuda_fp16.h>
#include <math.h>

typedef __half fp16;

// ---------------- dims ----------------
#define BB   2
#define TT   2048
#define DD   768
#define NHH  12
#define NKVV 4
#define HDD  64
#define LL   6
#define VV   32000
#define DII  1536
#define NCC  64
#define CDD  128
#define ROWS (BB*TT)          // 4096
#define GATE_STRENGTH 0.001f
#define EXN  ((long)DD*DII)   // expert matrix elements = 1,179,648

// ---------------- fp32 scratch ----------------
__device__ float g_x [ROWS*DD];
__device__ float g_q [ROWS*NHH*HDD];
__device__ float g_k [ROWS*NKVV*HDD];
__device__ float g_v [ROWS*NKVV*HDD];
__device__ float g_eb[6L*ROWS*DII];    // gate/up GEMM outputs (PF uses slots 0,1)
__device__ float g_cv[BB*10];
__device__ float g_tw[LL*BB*3];
__device__ int   g_ti[LL*BB*3];

// ---------------- fp16 activation planes (single precision plane) --------------
__device__ fp16 g_h  [ROWS*DD];
__device__ fp16 g_ao [ROWS*NHH*HDD];
__device__ fp16 g_hd [ROWS*DII];          // PF hidden
__device__ fp16 g_mh [3L*ROWS*DII];       // MoE hidden

// ---------------- fp16 hi/lo weight planes (layouts as in source) --------------
__device__ fp16 g_wq_h[6L*768*768],  g_wq_l[6L*768*768];
__device__ fp16 g_wk_h[6L*768*256],  g_wk_l[6L*768*256];
__device__ fp16 g_wv_h[6L*768*256],  g_wv_l[6L*768*256];
__device__ fp16 g_wo_h[6L*768*768],  g_wo_l[6L*768*768];
__device__ fp16 g_pg_h[6L*768*1536], g_pg_l[6L*768*1536];
__device__ fp16 g_pu_h[6L*768*1536], g_pu_l[6L*768*1536];
__device__ fp16 g_pd_h[6L*1536*768], g_pd_l[6L*1536*768];
__device__ fp16 g_em_h[(long)VV*DD], g_em_l[(long)VV*DD];   // [N][K] for TRANSB
__device__ fp16 g_hg_h[(long)VV*DD], g_hg_l[(long)VV*DD];
__device__ fp16 g_eg_h[36L*DD*DII],  g_eg_l[36L*DD*DII];
__device__ fp16 g_eu_h[36L*DD*DII],  g_eu_l[36L*DD*DII];
__device__ fp16 g_ed_h[36L*DD*DII],  g_ed_l[36L*DD*DII];

// ---------------- helpers ----------------
__device__ __forceinline__ float block_reduce_sum_256(float v) {
    __shared__ float red[8];
    int t = threadIdx.x;
    #pragma unroll
    for (int off = 16; off; off >>= 1) v += __shfl_xor_sync(0xffffffffu, v, off);
    if ((t & 31) == 0) red[t >> 5] = v;
    __syncthreads();
    float tot = 0.f;
    #pragma unroll
    for (int i = 0; i < 8; i++) tot += red[i];
    return tot;
}

// weight split: hi/lo fp16 pairs (packed two at a time)
__device__ __forceinline__ void wsplit2(float f0, float f1, unsigned& hi, unsigned& lo) {
    __half2 h = __floats2half2_rn(f0, f1);
    float r0 = f0 - __half2float(__low2half(h));
    float r1 = f1 - __half2float(__high2half(h));
    __half2 l = __floats2half2_rn(r0, r1);
    hi = *(unsigned*)&h;
    lo = *(unsigned*)&l;
}

__device__ __forceinline__ void mma16816(float* c, const unsigned* a, const unsigned* b) {
    asm volatile(
        "mma.sync.aligned.m16n8k16.row.col.f32.f16.f16.f32 "
        "{%0,%1,%2,%3}, {%4,%5,%6,%7}, {%8,%9}, {%0,%1,%2,%3};\n"
        : "+f"(c[0]), "+f"(c[1]), "+f"(c[2]), "+f"(c[3])
        : "r"(a[0]), "r"(a[1]), "r"(a[2]), "r"(a[3]), "r"(b[0]), "r"(b[1]));
}

__device__ __forceinline__ void ldsm_x4(unsigned& r0, unsigned& r1, unsigned& r2,
                                        unsigned& r3, unsigned addr) {
    asm volatile("ldmatrix.sync.aligned.m8n8.x4.shared.b16 {%0,%1,%2,%3}, [%4];\n"
                 : "=r"(r0), "=r"(r1), "=r"(r2), "=r"(r3) : "r"(addr));
}

__device__ __forceinline__ void ldsm_x4_t(unsigned& r0, unsigned& r1, unsigned& r2,
                                          unsigned& r3, unsigned addr) {
    asm volatile("ldmatrix.sync.aligned.m8n8.x4.trans.shared.b16 {%0,%1,%2,%3}, [%4];\n"
                 : "=r"(r0), "=r"(r1), "=r"(r2), "=r"(r3) : "r"(addr));
}

__device__ __forceinline__ void cp16(unsigned dst, const void* src) {
    asm volatile("cp.async.cg.shared.global [%0], [%1], 16;\n" :: "r"(dst), "l"(src));
}
__device__ __forceinline__ void cp_commit() { asm volatile("cp.async.commit_group;\n"); }
__device__ __forceinline__ void cp_wait0()  { asm volatile("cp.async.wait_group 0;\n" ::: "memory"); }

// ---------------- weight converters ----------------
__global__ void convw_kernel(const float* __restrict__ s, fp16* __restrict__ hi,
                             fp16* __restrict__ lo, long n) {
    long i = ((long)blockIdx.x * blockDim.x + threadIdx.x) * 4;
    if (i < n) {
        float4 v = *(const float4*)(s + i);
        unsigned h0, l0, h1, l1;
        wsplit2(v.x, v.y, h0, l0);
        wsplit2(v.z, v.w, h1, l1);
        *(uint2*)&hi[i] = make_uint2(h0, h1);
        *(uint2*)&lo[i] = make_uint2(l0, l1);
    }
}

// selected-expert conversion: grid (EXN/1024, 36, 3)
__global__ void convexp_kernel(const float* __restrict__ eg, const float* __restrict__ eu,
                               const float* __restrict__ ed,
                               fp16* gh, fp16* gl, fp16* uh, fp16* ul,
                               fp16* dh, fp16* dl, const int* __restrict__ ti) {
    const int slot = blockIdx.y, mat = blockIdx.z;
    const int l = slot / 6, e = ti[slot];
    long i = ((long)blockIdx.x * 256 + threadIdx.x) * 4;
    if (i >= EXN) return;
    const float* src; fp16 *hi, *lo;
    if (mat == 0)      { src = eg; hi = gh; lo = gl; }
    else if (mat == 1) { src = eu; hi = uh; lo = ul; }
    else               { src = ed; hi = dh; lo = dl; }
    src += ((long)l * 10 + e) * EXN + i;
    hi  += (long)slot * EXN + i;
    lo  += (long)slot * EXN + i;
    float4 v = *(const float4*)src;
    unsigned h0, l0, h1, l1;
    wsplit2(v.x, v.y, h0, l0);
    wsplit2(v.z, v.w, h1, l1);
    *(uint2*)hi = make_uint2(h0, h1);
    *(uint2*)lo = make_uint2(l0, l1);
}

// ---------------- embedding ----------------
__global__ void embed_kernel(const int* __restrict__ idx,
                             const float* __restrict__ emb,
                             float* __restrict__ x) {
    long i = (long)blockIdx.x * blockDim.x + threadIdx.x;
    if (i < (long)ROWS * DD) {
        long r = i / DD, c = i % DD;
        x[i] = emb[(long)idx[r] * DD + c];
    }
}

// ---------------- consciousness vector (tiny MLP) ----------------
__global__ void cv_kernel(const float* __restrict__ cs,
                          const float* __restrict__ w1, const float* __restrict__ b1,
                          const float* __restrict__ w2, const float* __restrict__ b2,
                          float* __restrict__ cv) {
    __shared__ float pooled[BB][CDD];
    __shared__ float h1[BB][64];
    int t = threadIdx.x;  // 256 threads
    {
        int b = t / CDD, c = t % CDD;
        float s = 0.f;
        for (int n = 0; n < NCC; n++)
            s += cs[((long)b * NCC + n) * CDD + c];
        pooled[b][c] = s * (1.f / NCC);
    }
    __syncthreads();
    if (t < BB * 64) {
        int b = t / 64, j = t % 64;
        float z = b1[j];
        for (int c = 0; c < CDD; c++) z += pooled[b][c] * w1[c * 64 + j];
        float z3 = z * z * z;
        h1[b][j] = 0.5f * z * (1.f + tanhf(0.7978845608028654f * (z + 0.044715f * z3)));
    }
    __syncthreads();
    if (t < BB * 10) {
        int b = t / 10, i = t % 10;
        float z = b2[i];
        for (int j = 0; j < 64; j++) z += h1[b][j] * w2[j * 10 + i];
        cv[b * 10 + i] = 1.f / (1.f + expf(-z));
    }
}

// ---------------- routers for all layers ----------------
__global__ void router_all_kernel(const float* __restrict__ cv,
                                  const float* __restrict__ W,
                                  const float* __restrict__ bias,
                                  float* __restrict__ tw, int* __restrict__ ti) {
    int l = blockIdx.x;
    int b = threadIdx.x;
    if (b >= BB) return;
    const float* Wl = W + (long)l * 100;
    const float* bl = bias + (long)l * 10;
    float lg[10];
    float mx = -1e30f;
    for (int i = 0; i < 10; i++) {
        float z = bl[i];
        for (int j = 0; j < 10; j++) z += cv[b * 10 + j] * Wl[j * 10 + i];
        lg[i] = z;
        mx = fmaxf(mx, z);
    }
    float se = 0.f;
    for (int i = 0; i < 10; i++) { lg[i] = expf(lg[i] - mx); se += lg[i]; }
    for (int i = 0; i < 10; i++) lg[i] /= se;
    float wsum = 0.f;
    int base = l * 6 + b * 3;
    for (int kk = 0; kk < 3; kk++) {
        int bi = 0; float bv = -1.f;
        for (int i = 0; i < 10; i++) if (lg[i] > bv) { bv = lg[i]; bi = i; }
        ti[base + kk] = bi; tw[base + kk] = bv; wsum += bv;
        lg[bi] = -2.f;
    }
    for (int kk = 0; kk < 3; kk++) tw[base + kk] /= wsum;
}

// ---------------- RMSNorm -> fp16 plane ----------------
__global__ void __launch_bounds__(256) rms_kernel(const float* __restrict__ x,
                                                  const float* __restrict__ w,
                                                  fp16* __restrict__ o) {
    int row = blockIdx.x, t = threadIdx.x;
    const float* xr = x + (long)row * DD;
    float v0 = xr[t], v1 = xr[t + 256], v2 = xr[t + 512];
    float tot = block_reduce_sum_256(v0 * v0 + v1 * v1 + v2 * v2);
    float s = rsqrtf(tot * (1.f / DD) + 1e-6f);
    fp16* orow = o + (long)row * DD;
    orow[t]       = __float2half_rn(v0 * s * w[t]);
    orow[t + 256] = __float2half_rn(v1 * s * w[t + 256]);
    orow[t + 512] = __float2half_rn(v2 * s * w[t + 512]);
}

// ---------------- SwiGLU (+ tension) -> fp16 plane ----------------
__global__ void __launch_bounds__(256) swiglu_kernel(const float* __restrict__ g,
                                                     const float* __restrict__ u,
                                                     fp16* __restrict__ o,
                                                     float* __restrict__ tension) {
    int row = blockIdx.x, t = threadIdx.x;
    const float* gr = g + (long)row * DII;
    const float* ur = u + (long)row * DII;
    fp16* orow = o + (long)row * DII;
    float sum = 0.f;
    #pragma unroll
    for (int j = 0; j < 6; j++) {
        int c = t + j * 256;
        float a = gr[c], bv = ur[c];
        float hv = (a / (1.f + __expf(-a))) * bv;
        orow[c] = __float2half_rn(hv);
        sum += hv;
    }
    float tot = block_reduce_sum_256(sum);
    if (t == 0) tension[row] = tanhf(tot * (1.f / DII));
}

// ---------------- MoE SwiGLU (folds router weight) -> fp16 plane ---------------
__global__ void __launch_bounds__(256) swiglu_moe_kernel(const float* __restrict__ buf,
                                                         const float* __restrict__ tw,
                                                         fp16* __restrict__ mh) {
    int row = blockIdx.x, e = blockIdx.y, t = threadIdx.x;
    int b = row / TT;
    float scale = tw[b * 3 + e];
    const float* gr = buf + (long)(2 * e) * ROWS * DII + (long)row * DII;
    const float* ur = buf + (long)(2 * e + 1) * ROWS * DII + (long)row * DII;
    fp16* orow = mh + (long)e * ROWS * DII + (long)row * DII;
    #pragma unroll
    for (int j = 0; j < 6; j++) {
        int c = t + j * 256;
        float a = gr[c], bv = ur[c];
        orow[c] = __float2half_rn((a / (1.f + __expf(-a))) * bv * scale);
    }
}

// ---------------- consciousness-state residual add ----------------
__global__ void __launch_bounds__(256) csadd_kernel(float* __restrict__ x,
                                                    const float* __restrict__ tension,
                                                    const float* __restrict__ tw) {
    int row = blockIdx.x, t = threadIdx.x;
    float ten = tension[row] * GATE_STRENGTH;
    float* xr = x + (long)row * DD;
    xr[t]       += ten * tw[t];
    xr[t + 256] += ten * tw[t + 256];
    xr[t + 512] += ten * tw[t + 512];
}

// ---------------- flash-style causal attention (fp32, GQA) ----------------
__global__ void __launch_bounds__(64) attn_kernel(const float* __restrict__ q,
                                                  const float* __restrict__ k,
                                                  const float* __restrict__ v,
                                                  fp16* __restrict__ o) {
    const int q0 = blockIdx.x * 64;
    const int h  = blockIdx.y;
    const int b  = blockIdx.z;
    const int t  = threadIdx.x;
    const int qg = q0 + t;
    const int kvh = h / (NHH / NKVV);

    __shared__ float Ks[64][64];
    __shared__ float Vs[64][64];

    float qreg[64], acc[64];
    const float* qp = q + ((long)(b * TT + qg) * NHH + h) * HDD;
    #pragma unroll
    for (int d = 0; d < 64; d++) { qreg[d] = qp[d]; acc[d] = 0.f; }
    float lsum = 0.f;

    for (int s0 = 0; s0 <= q0; s0 += 64) {
        __syncthreads();
        #pragma unroll 8
        for (int r = 0; r < 64; r++) {
            long base = ((long)(b * TT + s0 + r) * NKVV + kvh) * HDD + t;
            Ks[r][t] = k[base];
            Vs[r][t] = v[base];
        }
        __syncthreads();
        int kmax = min(64, qg - s0 + 1);
        for (int kk = 0; kk < kmax; kk++) {
            float s = 0.f;
            #pragma unroll
            for (int d = 0; d < 64; d++) s += qreg[d] * Ks[kk][d];
            float p = __expf(s * 0.125f);
            lsum += p;
            #pragma unroll
            for (int d = 0; d < 64; d++) acc[d] += p * Vs[kk][d];
        }
    }
    float inv = 1.f / lsum;
    long base = ((long)(b * TT + qg) * NHH + h) * HDD;
    #pragma unroll
    for (int d = 0; d < 64; d += 2) {
        __half2 hv = __floats2half2_rn(acc[d] * inv, acc[d + 1] * inv);
        *(__half2*)&o[base + d] = hv;
    }
}

// ---------------- tensor-core GEMM: fp16 A plane, fp16 hi/lo B planes ----------
// C(MxN) = [C +] A@Bhi + A@Blo  (fp32 accum; B exact in fp16 hi+lo)
// 128x128 tile, 8 warps (64x32 warp tiles), BK=32, 2-stage cp.async, 2 CTA/SM.
// MODE 0: plain; optional pair (B2,C2) via blockIdx.z.
// MODE 1: MoE gate/up: z in [0,6): kexp=z>>1; plane = (z&1 ? B2 : B) +
//         (bb*3+kexp)*sstride; C += z*ROWS*N.
// MODE 2: MoE down: 3 K-segments; A seg s at +s*ROWS*K; B seg s at +(bb*3+s)*sstride.
template<bool ACC, bool TRANSB, int MODE>
__global__ void __launch_bounds__(256, 2) gemm_fp16(
    const fp16* __restrict__ A,
    const fp16* __restrict__ Bh, const fp16* __restrict__ Bl,
    float* __restrict__ C,
    const fp16* __restrict__ B2h, const fp16* __restrict__ B2l, float* __restrict__ C2,
    int M, int N, int K, long sstride)
{
    const int bx = blockIdx.x, by = blockIdx.y;
    const int bb = (by * 128) / TT;              // batch (tiles never straddle)
    if (MODE == 0) {
        if (B2h != nullptr && blockIdx.z == 1) { Bh = B2h; Bl = B2l; C = C2; }
    } else if (MODE == 1) {
        const int z = blockIdx.z, kexp = z >> 1;
        long off = (long)(bb * 3 + kexp) * sstride;
        if (z & 1) { Bh = B2h + off; Bl = B2l + off; }
        else       { Bh = Bh  + off; Bl = Bl  + off; }
        C += (long)z * ROWS * N;
    }
    const fp16 *Bsh[3], *Bsl[3];
    if (MODE == 2) {
        #pragma unroll
        for (int s = 0; s < 3; s++) {
            long off = (long)(bb * 3 + s) * sstride;
            Bsh[s] = Bh + off; Bsl[s] = Bl + off;
        }
    }

    extern __shared__ fp16 sm[];
    constexpr int ASZ2 = 128 * 40;
    constexpr int BSZ2 = TRANSB ? 128 * 40 : 32 * 136;
    fp16* smA  = sm;                 // [2][ASZ2]
    fp16* smBh = smA + 2 * ASZ2;     // [2][BSZ2]
    fp16* smBl = smBh + 2 * BSZ2;

    const unsigned uA  = (unsigned)__cvta_generic_to_shared(smA);
    const unsigned uBh = (unsigned)__cvta_generic_to_shared(smBh);
    const unsigned uBl = (unsigned)__cvta_generic_to_shared(smBl);

    const int tid = threadIdx.x;
    const int wid = tid >> 5, lane = tid & 31;
    const int g = lane >> 2, t = lane & 3;
    const int m0 = (wid & 1) * 64, n0 = (wid >> 1) * 32;

    const int arow = tid >> 1, acb = (tid & 1) * 16;
    const int kr = tid >> 3,  nb = (tid & 7) * 16;

    const int kIters = K >> 5;
    const int total  = (MODE == 2 ? 3 : 1) * kIters;

    auto issue = [&](int it, int st) {
        const int seg = (MODE == 2) ? it / kIters : 0;
        const int k0  = ((MODE == 2) ? (it % kIters) : it) * 32;
        const fp16* pA = A + ((MODE == 2) ? (long)seg * ROWS * K : 0);
        long aoff = (long)(by * 128 + arow) * K + k0 + acb;
        unsigned d = uA + (unsigned)(st * ASZ2 + arow * 40 + acb) * 2u;
        cp16(d, pA + aoff);       cp16(d + 16, pA + aoff + 8);
        if (TRANSB) {
            long boff = (long)(bx * 128 + arow) * K + k0 + acb;
            d = uBh + (unsigned)(st * BSZ2 + arow * 40 + acb) * 2u;
            cp16(d, Bh + boff);   cp16(d + 16, Bh + boff + 8);
            d = uBl + (unsigned)(st * BSZ2 + arow * 40 + acb) * 2u;
            cp16(d, Bl + boff);   cp16(d + 16, Bl + boff + 8);
        } else {
            const fp16* pBh = (MODE == 2) ? Bsh[seg] : Bh;
            const fp16* pBl = (MODE == 2) ? Bsl[seg] : Bl;
            long boff = (long)(k0 + kr) * N + bx * 128 + nb;
            d = uBh + (unsigned)(st * BSZ2 + kr * 136 + nb) * 2u;
            cp16(d, pBh + boff);   cp16(d + 16, pBh + boff + 8);
            d = uBl + (unsigned)(st * BSZ2 + kr * 136 + nb) * 2u;
            cp16(d, pBl + boff);   cp16(d + 16, pBl + boff + 8);
        }
        cp_commit();
    };

    float acc[4][4][4];
    #pragma unroll
    for (int i = 0; i < 4; i++)
        #pragma unroll
        for (int j = 0; j < 4; j++)
            #pragma unroll
            for (int e = 0; e < 4; e++) acc[i][j][e] = 0.f;

    issue(0, 0);

    for (int it = 0; it < total; it++) {
        const int st = it & 1;
        cp_wait0();
        __syncthreads();
        if (it + 1 < total) issue(it + 1, st ^ 1);

        const unsigned aO = (unsigned)(st * ASZ2) * 2u;
        const unsigned bO = (unsigned)(st * BSZ2) * 2u;
        #pragma unroll
        for (int ks = 0; ks < 2; ks++) {
            const int kk = ks * 16;
            unsigned ah[4][4];
            #pragma unroll
            for (int i = 0; i < 4; i++) {
                int row = m0 + i * 16 + (lane & 15);
                int col = kk + (lane >> 4) * 8;
                unsigned off = (unsigned)(row * 40 + col) * 2u;
                ldsm_x4(ah[i][0], ah[i][1], ah[i][2], ah[i][3], uA + aO + off);
            }
            unsigned bh[4][2], bl[4][2];
            if (TRANSB) {
                #pragma unroll
                for (int jp = 0; jp < 2; jp++) {
                    int row = n0 + jp * 16 + (lane & 15);
                    int col = kk + (lane >> 4) * 8;
                    unsigned off = (unsigned)(row * 40 + col) * 2u;
                    unsigned r0, r1, r2, r3;
                    ldsm_x4(r0, r1, r2, r3, uBh + bO + off);
                    bh[2*jp][0] = r0; bh[2*jp+1][0] = r1;
                    bh[2*jp][1] = r2; bh[2*jp+1][1] = r3;
                    ldsm_x4(r0, r1, r2, r3, uBl + bO + off);
                    bl[2*jp][0] = r0; bl[2*jp+1][0] = r1;
                    bl[2*jp][1] = r2; bl[2*jp+1][1] = r3;
                }
            } else {
                #pragma unroll
                for (int jp = 0; jp < 2; jp++) {
                    int row = kk + (lane & 15);
                    int col = n0 + jp * 16 + (lane >> 4) * 8;
                    unsigned off = (unsigned)(row * 136 + col) * 2u;
                    unsigned r0, r1, r2, r3;
                    ldsm_x4_t(r0, r1, r2, r3, uBh + bO + off);
                    bh[2*jp][0] = r0; bh[2*jp][1] = r1;
                    bh[2*jp+1][0] = r2; bh[2*jp+1][1] = r3;
                    ldsm_x4_t(r0, r1, r2, r3, uBl + bO + off);
                    bl[2*jp][0] = r0; bl[2*jp][1] = r1;
                    bl[2*jp+1][0] = r2; bl[2*jp+1][1] = r3;
                }
            }
            #pragma unroll
            for (int j = 0; j < 4; j++) {
                #pragma unroll
                for (int i = 0; i < 4; i++) {
                    mma16816(acc[i][j], ah[i], bh[j]);
                    mma16816(acc[i][j], ah[i], bl[j]);
                }
            }
        }
    }

    // ---- epilogue ----
    #pragma unroll
    for (int i = 0; i < 4; i++) {
        long r0 = (long)(by * 128 + m0 + i * 16 + g);
        long r1 = r0 + 8;
        #pragma unroll
        for (int j = 0; j < 4; j++) {
            long c = (long)(bx * 128 + n0 + j * 8 + 2 * t);
            if (ACC) {
                C[r0 * N + c]     += acc[i][j][0];
                C[r0 * N + c + 1] += acc[i][j][1];
                C[r1 * N + c]     += acc[i][j][2];
                C[r1 * N + c + 1] += acc[i][j][3];
            } else {
                *(float2*)&C[r0 * N + c] = make_float2(acc[i][j][0], acc[i][j][1]);
                *(float2*)&C[r1 * N + c] = make_float2(acc[i][j][2], acc[i][j][3]);
            }
        }
    }
}

// smem sizes
constexpr int SMN = (2 * 128 * 40 + 4 * 32 * 136) * 2;   // 55,296 B
constexpr int SMT = (2 * 128 * 40 + 4 * 128 * 40) * 2;   // 61,440 B

// ---------------- launch ----------------
extern "C" void kernel_launch(void* const* d_in, const int* in_sizes, int n_in,
                              void* d_out, int out_size) {
    const int*   idx       = (const int*)  d_in[0];
    const float* cons      = (const float*)d_in[1];
    const float* tok_emb   = (const float*)d_in[2];
    const float* head_g    = (const float*)d_in[3];
    const float* cv_w1     = (const float*)d_in[4];
    const float* cv_b1     = (const float*)d_in[5];
    const float* cv_w2     = (const float*)d_in[6];
    const float* cv_b2     = (const float*)d_in[7];
    const float* tension_w = (const float*)d_in[8];
    const float* ln_attn   = (const float*)d_in[9];
    const float* ln_pf     = (const float*)d_in[10];
    const float* ln_moe    = (const float*)d_in[11];
    const float* ln_f      = (const float*)d_in[12];
    const float* wq        = (const float*)d_in[13];
    const float* wk        = (const float*)d_in[14];
    const float* wv        = (const float*)d_in[15];
    const float* wo        = (const float*)d_in[16];
    const float* pf_gate   = (const float*)d_in[17];
    const float* pf_up     = (const float*)d_in[18];
    const float* pf_down   = (const float*)d_in[19];
    const float* e_gate    = (const float*)d_in[20];
    const float* e_up      = (const float*)d_in[21];
    const float* e_down    = (const float*)d_in[22];
    const float* router_w  = (const float*)d_in[23];
    const float* router_b  = (const float*)d_in[24];
    float* out = (float*)d_out;

    // scratch addresses
    float *xp, *qp, *kp, *vp, *ebp, *cvp, *twp;  int* tip;
    fp16 *hp, *aop, *hdp, *mhp;
    fp16 *wqh, *wql, *wkh, *wkl, *wvh, *wvl, *woh, *wol;
    fp16 *pgh, *pgl, *puh, *pul, *pdh, *pdl;
    fp16 *emh, *eml, *hgh, *hgl;
    fp16 *egh, *egl, *euh, *eul, *edh, *edl;
    cudaGetSymbolAddress((void**)&xp,  g_x);
    cudaGetSymbolAddress((void**)&qp,  g_q);
    cudaGetSymbolAddress((void**)&kp,  g_k);
    cudaGetSymbolAddress((void**)&vp,  g_v);
    cudaGetSymbolAddress((void**)&ebp, g_eb);
    cudaGetSymbolAddress((void**)&cvp, g_cv);
    cudaGetSymbolAddress((void**)&twp, g_tw);
    cudaGetSymbolAddress((void**)&tip, g_ti);
    cudaGetSymbolAddress((void**)&hp,  g_h);
    cudaGetSymbolAddress((void**)&aop, g_ao);
    cudaGetSymbolAddress((void**)&hdp, g_hd);
    cudaGetSymbolAddress((void**)&mhp, g_mh);
    cudaGetSymbolAddress((void**)&wqh, g_wq_h); cudaGetSymbolAddress((void**)&wql, g_wq_l);
    cudaGetSymbolAddress((void**)&wkh, g_wk_h); cudaGetSymbolAddress((void**)&wkl, g_wk_l);
    cudaGetSymbolAddress((void**)&wvh, g_wv_h); cudaGetSymbolAddress((void**)&wvl, g_wv_l);
    cudaGetSymbolAddress((void**)&woh, g_wo_h); cudaGetSymbolAddress((void**)&wol, g_wo_l);
    cudaGetSymbolAddress((void**)&pgh, g_pg_h); cudaGetSymbolAddress((void**)&pgl, g_pg_l);
    cudaGetSymbolAddress((void**)&puh, g_pu_h); cudaGetSymbolAddress((void**)&pul, g_pu_l);
    cudaGetSymbolAddress((void**)&pdh, g_pd_h); cudaGetSymbolAddress((void**)&pdl, g_pd_l);
    cudaGetSymbolAddress((void**)&emh, g_em_h); cudaGetSymbolAddress((void**)&eml, g_em_l);
    cudaGetSymbolAddress((void**)&hgh, g_hg_h); cudaGetSymbolAddress((void**)&hgl, g_hg_l);
    cudaGetSymbolAddress((void**)&egh, g_eg_h); cudaGetSymbolAddress((void**)&egl, g_eg_l);
    cudaGetSymbolAddress((void**)&euh, g_eu_h); cudaGetSymbolAddress((void**)&eul, g_eu_l);
    cudaGetSymbolAddress((void**)&edh, g_ed_h); cudaGetSymbolAddress((void**)&edl, g_ed_l);

    // opt-in smem (idempotent host calls, not captured)
    cudaFuncSetAttribute(gemm_fp16<false, false, 0>, cudaFuncAttributeMaxDynamicSharedMemorySize, SMN);
    cudaFuncSetAttribute(gemm_fp16<true,  false, 0>, cudaFuncAttributeMaxDynamicSharedMemorySize, SMN);
    cudaFuncSetAttribute(gemm_fp16<false, false, 1>, cudaFuncAttributeMaxDynamicSharedMemorySize, SMN);
    cudaFuncSetAttribute(gemm_fp16<true,  false, 2>, cudaFuncAttributeMaxDynamicSharedMemorySize, SMN);
    cudaFuncSetAttribute(gemm_fp16<false, true,  0>, cudaFuncAttributeMaxDynamicSharedMemorySize, SMT);

    float* tens = out + (long)2 * ROWS * VV;   // output tail: tensions (L, B, T)
    float* b1p = ebp;                          // PF gate fp32
    float* b2p = ebp + (long)ROWS * DII;       // PF up fp32

    // ---- preprocessing: embed, cv, routers, weight conversion ----
    embed_kernel<<<(ROWS * DD + 255) / 256, 256>>>(idx, tok_emb, xp);
    cv_kernel<<<1, 256>>>(cons, cv_w1, cv_b1, cv_w2, cv_b2, cvp);
    router_all_kernel<<<LL, 32>>>(cvp, router_w, router_b, twp, tip);

    auto convw = [&](const float* s, fp16* hi, fp16* lo, long n) {
        convw_kernel<<<(int)(n / 4 / 256), 256>>>(s, hi, lo, n);
    };
    convw(wq, wqh, wql, 6L * 768 * 768);
    convw(wk, wkh, wkl, 6L * 768 * 256);
    convw(wv, wvh, wvl, 6L * 768 * 256);
    convw(wo, woh, wol, 6L * 768 * 768);
    convw(pf_gate, pgh, pgl, 6L * 768 * 1536);
    convw(pf_up,   puh, pul, 6L * 768 * 1536);
    convw(pf_down, pdh, pdl, 6L * 1536 * 768);
    convw(tok_emb, emh, eml, (long)VV * DD);
    convw(head_g,  hgh, hgl, (long)VV * DD);
    convexp_kernel<<<dim3((int)(EXN / 4 / 256), 36, 3), 256>>>(
        e_gate, e_up, e_down, egh, egl, euh, eul, edh, edl, tip);

    const dim3 g768 (DD  / 128, ROWS / 128, 1);
    const dim3 gkv  (256 / 128, ROWS / 128, 2);
    const dim3 gff  (DII / 128, ROWS / 128, 2);
    const dim3 gegu (DII / 128, ROWS / 128, 6);
    const dim3 gdn  (DD  / 128, ROWS / 128, 1);

    for (int l = 0; l < LL; l++) {
        long o768  = (long)l * 768 * 768;
        long o256  = (long)l * 768 * 256;
        long o1536 = (long)l * 768 * 1536;
        long oexp  = (long)l * 6 * EXN;

        // ---- attention ----
        rms_kernel<<<ROWS, 256>>>(xp, ln_attn + (long)l * DD, hp);
        gemm_fp16<false, false, 0><<<g768, 256, SMN>>>(hp, wqh + o768, wql + o768, qp,
                                                       nullptr, nullptr, nullptr,
                                                       ROWS, 768, DD, 0);
        gemm_fp16<false, false, 0><<<gkv, 256, SMN>>>(hp, wkh + o256, wkl + o256, kp,
                                                      wvh + o256, wvl + o256, vp,
                                                      ROWS, 256, DD, 0);
        attn_kernel<<<dim3(TT / 64, NHH, BB), 64>>>(qp, kp, vp, aop);
        gemm_fp16<true, false, 0><<<g768, 256, SMN>>>(aop, woh + o768, wol + o768, xp,
                                                      nullptr, nullptr, nullptr,
                                                      ROWS, DD, 768, 0);

        // ---- PureField FFN + tension ----
        rms_kernel<<<ROWS, 256>>>(xp, ln_pf + (long)l * DD, hp);
        gemm_fp16<false, false, 0><<<gff, 256, SMN>>>(hp, pgh + o1536, pgl + o1536, b1p,
                                                      puh + o1536, pul + o1536, b2p,
                                                      ROWS, DII, DD, 0);
        swiglu_kernel<<<ROWS, 256>>>(b1p, b2p, hdp, tens + (long)l * ROWS);
        gemm_fp16<true, false, 0><<<g768, 256, SMN>>>(hdp, pdh + (long)l * 1536 * 768,
                                                      pdl + (long)l * 1536 * 768, xp,
                                                      nullptr, nullptr, nullptr,
                                                      ROWS, DD, DII, 0);

        // ---- consciousness-state residual (previous layer's tension) ----
        if (l > 0)
            csadd_kernel<<<ROWS, 256>>>(xp, tens + (long)(l - 1) * ROWS, tension_w);

        // ---- MoE ----
        rms_kernel<<<ROWS, 256>>>(xp, ln_moe + (long)l * DD, hp);
        gemm_fp16<false, false, 1><<<gegu, 256, SMN>>>(hp, egh + oexp, egl + oexp, ebp,
                                                       euh + oexp, eul + oexp, nullptr,
                                                       ROWS, DII, DD, EXN);
        swiglu_moe_kernel<<<dim3(ROWS, 3), 256>>>(ebp, twp + (long)l * 6, mhp);
        gemm_fp16<true, false, 2><<<gdn, 256, SMN>>>(mhp, edh + oexp, edl + oexp, xp,
                                                     nullptr, nullptr, nullptr,
                                                     ROWS, DD, DII, EXN);
    }

    // ---- final norm + tied heads (paired) ----
    rms_kernel<<<ROWS, 256>>>(xp, ln_f, hp);
    const dim3 gv(VV / 128, ROWS / 128, 2);
    gemm_fp16<false, true, 0><<<gv, 256, SMT>>>(hp, emh, eml, out,
                                                hgh, hgl, out + (long)ROWS * VV,
                                                ROWS, VV, DD, 0);
}

// round 14
// speedup vs baseline: 1.3267x; 1.0036x over previous
#include <cuda_runtime.h>
#include <cuda_fp16.h>
#include <math.h>

typedef __half fp16;

// ---------------- dims ----------------
#define BB   2
#define TT   2048
#define DD   768
#define NHH  12
#define NKVV 4
#define HDD  64
#define LL   6
#define VV   32000
#define DII  1536
#define NCC  64
#define CDD  128
#define ROWS (BB*TT)          // 4096
#define GATE_STRENGTH 0.001f
#define EXN  ((long)DD*DII)   // expert matrix elements = 1,179,648

// ---------------- fp32 scratch ----------------
__device__ float g_x [ROWS*DD];
__device__ float g_q [ROWS*NHH*HDD];
__device__ float g_k [ROWS*NKVV*HDD];
__device__ float g_v [ROWS*NKVV*HDD];
__device__ float g_eb[6L*ROWS*DII];    // gate/up GEMM outputs (PF uses slots 0,1)
__device__ float g_cv[BB*10];
__device__ float g_tw[LL*BB*3];
__device__ int   g_ti[LL*BB*3];

// ---------------- fp16 activation planes (single precision plane) --------------
__device__ fp16 g_h  [ROWS*DD];
__device__ fp16 g_ao [ROWS*NHH*HDD];
__device__ fp16 g_hd [ROWS*DII];          // PF hidden
__device__ fp16 g_mh [3L*ROWS*DII];       // MoE hidden

// ---------------- fp16 hi/lo weight planes (layouts as in source) --------------
__device__ fp16 g_wq_h[6L*768*768],  g_wq_l[6L*768*768];
__device__ fp16 g_wk_h[6L*768*256],  g_wk_l[6L*768*256];
__device__ fp16 g_wv_h[6L*768*256],  g_wv_l[6L*768*256];
__device__ fp16 g_wo_h[6L*768*768],  g_wo_l[6L*768*768];
__device__ fp16 g_pg_h[6L*768*1536], g_pg_l[6L*768*1536];
__device__ fp16 g_pu_h[6L*768*1536], g_pu_l[6L*768*1536];
__device__ fp16 g_pd_h[6L*1536*768], g_pd_l[6L*1536*768];
__device__ fp16 g_em_h[(long)VV*DD], g_em_l[(long)VV*DD];   // [N][K] for TRANSB
__device__ fp16 g_hg_h[(long)VV*DD], g_hg_l[(long)VV*DD];
__device__ fp16 g_eg_h[36L*DD*DII],  g_eg_l[36L*DD*DII];
__device__ fp16 g_eu_h[36L*DD*DII],  g_eu_l[36L*DD*DII];
__device__ fp16 g_ed_h[36L*DD*DII],  g_ed_l[36L*DD*DII];

// ---------------- helpers ----------------
__device__ __forceinline__ float block_reduce_sum_256(float v) {
    __shared__ float red[8];
    int t = threadIdx.x;
    #pragma unroll
    for (int off = 16; off; off >>= 1) v += __shfl_xor_sync(0xffffffffu, v, off);
    if ((t & 31) == 0) red[t >> 5] = v;
    __syncthreads();
    float tot = 0.f;
    #pragma unroll
    for (int i = 0; i < 8; i++) tot += red[i];
    return tot;
}

// weight split: hi/lo fp16 pairs (packed two at a time)
__device__ __forceinline__ void wsplit2(float f0, float f1, unsigned& hi, unsigned& lo) {
    __half2 h = __floats2half2_rn(f0, f1);
    float r0 = f0 - __half2float(__low2half(h));
    float r1 = f1 - __half2float(__high2half(h));
    __half2 l = __floats2half2_rn(r0, r1);
    hi = *(unsigned*)&h;
    lo = *(unsigned*)&l;
}

__device__ __forceinline__ void mma16816(float* c, const unsigned* a, const unsigned* b) {
    asm volatile(
        "mma.sync.aligned.m16n8k16.row.col.f32.f16.f16.f32 "
        "{%0,%1,%2,%3}, {%4,%5,%6,%7}, {%8,%9}, {%0,%1,%2,%3};\n"
        : "+f"(c[0]), "+f"(c[1]), "+f"(c[2]), "+f"(c[3])
        : "r"(a[0]), "r"(a[1]), "r"(a[2]), "r"(a[3]), "r"(b[0]), "r"(b[1]));
}

__device__ __forceinline__ void ldsm_x4(unsigned& r0, unsigned& r1, unsigned& r2,
                                        unsigned& r3, unsigned addr) {
    asm volatile("ldmatrix.sync.aligned.m8n8.x4.shared.b16 {%0,%1,%2,%3}, [%4];\n"
                 : "=r"(r0), "=r"(r1), "=r"(r2), "=r"(r3) : "r"(addr));
}

__device__ __forceinline__ void ldsm_x4_t(unsigned& r0, unsigned& r1, unsigned& r2,
                                          unsigned& r3, unsigned addr) {
    asm volatile("ldmatrix.sync.aligned.m8n8.x4.trans.shared.b16 {%0,%1,%2,%3}, [%4];\n"
                 : "=r"(r0), "=r"(r1), "=r"(r2), "=r"(r3) : "r"(addr));
}

__device__ __forceinline__ void cp16(unsigned dst, const void* src) {
    asm volatile("cp.async.cg.shared.global [%0], [%1], 16;\n" :: "r"(dst), "l"(src));
}
__device__ __forceinline__ void cp_commit() { asm volatile("cp.async.commit_group;\n"); }
__device__ __forceinline__ void cp_wait0()  { asm volatile("cp.async.wait_group 0;\n" ::: "memory"); }

// ---------------- weight converters ----------------
__global__ void convw_kernel(const float* __restrict__ s, fp16* __restrict__ hi,
                             fp16* __restrict__ lo, long n) {
    long i = ((long)blockIdx.x * blockDim.x + threadIdx.x) * 4;
    if (i < n) {
        float4 v = *(const float4*)(s + i);
        unsigned h0, l0, h1, l1;
        wsplit2(v.x, v.y, h0, l0);
        wsplit2(v.z, v.w, h1, l1);
        *(uint2*)&hi[i] = make_uint2(h0, h1);
        *(uint2*)&lo[i] = make_uint2(l0, l1);
    }
}

// selected-expert conversion: grid (EXN/1024, 36, 3)
__global__ void convexp_kernel(const float* __restrict__ eg, const float* __restrict__ eu,
                               const float* __restrict__ ed,
                               fp16* gh, fp16* gl, fp16* uh, fp16* ul,
                               fp16* dh, fp16* dl, const int* __restrict__ ti) {
    const int slot = blockIdx.y, mat = blockIdx.z;
    const int l = slot / 6, e = ti[slot];
    long i = ((long)blockIdx.x * 256 + threadIdx.x) * 4;
    if (i >= EXN) return;
    const float* src; fp16 *hi, *lo;
    if (mat == 0)      { src = eg; hi = gh; lo = gl; }
    else if (mat == 1) { src = eu; hi = uh; lo = ul; }
    else               { src = ed; hi = dh; lo = dl; }
    src += ((long)l * 10 + e) * EXN + i;
    hi  += (long)slot * EXN + i;
    lo  += (long)slot * EXN + i;
    float4 v = *(const float4*)src;
    unsigned h0, l0, h1, l1;
    wsplit2(v.x, v.y, h0, l0);
    wsplit2(v.z, v.w, h1, l1);
    *(uint2*)hi = make_uint2(h0, h1);
    *(uint2*)lo = make_uint2(l0, l1);
}

// ---------------- embedding (vectorized; DD % 4 == 0 so no row straddle) -------
__global__ void embed_kernel(const int* __restrict__ idx,
                             const float* __restrict__ emb,
                             float* __restrict__ x) {
    long i = ((long)blockIdx.x * blockDim.x + threadIdx.x) * 4;
    if (i < (long)ROWS * DD) {
        long r = i / DD, c = i % DD;
        *(float4*)&x[i] = *(const float4*)&emb[(long)idx[r] * DD + c];
    }
}

// ---------------- consciousness vector (tiny MLP) ----------------
__global__ void cv_kernel(const float* __restrict__ cs,
                          const float* __restrict__ w1, const float* __restrict__ b1,
                          const float* __restrict__ w2, const float* __restrict__ b2,
                          float* __restrict__ cv) {
    __shared__ float pooled[BB][CDD];
    __shared__ float h1[BB][64];
    int t = threadIdx.x;  // 256 threads
    {
        int b = t / CDD, c = t % CDD;
        float s = 0.f;
        for (int n = 0; n < NCC; n++)
            s += cs[((long)b * NCC + n) * CDD + c];
        pooled[b][c] = s * (1.f / NCC);
    }
    __syncthreads();
    if (t < BB * 64) {
        int b = t / 64, j = t % 64;
        float z = b1[j];
        for (int c = 0; c < CDD; c++) z += pooled[b][c] * w1[c * 64 + j];
        float z3 = z * z * z;
        h1[b][j] = 0.5f * z * (1.f + tanhf(0.7978845608028654f * (z + 0.044715f * z3)));
    }
    __syncthreads();
    if (t < BB * 10) {
        int b = t / 10, i = t % 10;
        float z = b2[i];
        for (int j = 0; j < 64; j++) z += h1[b][j] * w2[j * 10 + i];
        cv[b * 10 + i] = 1.f / (1.f + expf(-z));
    }
}

// ---------------- routers for all layers ----------------
__global__ void router_all_kernel(const float* __restrict__ cv,
                                  const float* __restrict__ W,
                                  const float* __restrict__ bias,
                                  float* __restrict__ tw, int* __restrict__ ti) {
    int l = blockIdx.x;
    int b = threadIdx.x;
    if (b >= BB) return;
    const float* Wl = W + (long)l * 100;
    const float* bl = bias + (long)l * 10;
    float lg[10];
    float mx = -1e30f;
    for (int i = 0; i < 10; i++) {
        float z = bl[i];
        for (int j = 0; j < 10; j++) z += cv[b * 10 + j] * Wl[j * 10 + i];
        lg[i] = z;
        mx = fmaxf(mx, z);
    }
    float se = 0.f;
    for (int i = 0; i < 10; i++) { lg[i] = expf(lg[i] - mx); se += lg[i]; }
    for (int i = 0; i < 10; i++) lg[i] /= se;
    float wsum = 0.f;
    int base = l * 6 + b * 3;
    for (int kk = 0; kk < 3; kk++) {
        int bi = 0; float bv = -1.f;
        for (int i = 0; i < 10; i++) if (lg[i] > bv) { bv = lg[i]; bi = i; }
        ti[base + kk] = bi; tw[base + kk] = bv; wsum += bv;
        lg[bi] = -2.f;
    }
    for (int kk = 0; kk < 3; kk++) tw[base + kk] /= wsum;
}

// ---------------- RMSNorm -> fp16 plane ----------------
__global__ void __launch_bounds__(256) rms_kernel(const float* __restrict__ x,
                                                  const float* __restrict__ w,
                                                  fp16* __restrict__ o) {
    int row = blockIdx.x, t = threadIdx.x;
    const float* xr = x + (long)row * DD;
    float v0 = xr[t], v1 = xr[t + 256], v2 = xr[t + 512];
    float tot = block_reduce_sum_256(v0 * v0 + v1 * v1 + v2 * v2);
    float s = rsqrtf(tot * (1.f / DD) + 1e-6f);
    fp16* orow = o + (long)row * DD;
    orow[t]       = __float2half_rn(v0 * s * w[t]);
    orow[t + 256] = __float2half_rn(v1 * s * w[t + 256]);
    orow[t + 512] = __float2half_rn(v2 * s * w[t + 512]);
}

// ---------------- SwiGLU (+ tension) -> fp16 plane ----------------
__global__ void __launch_bounds__(256) swiglu_kernel(const float* __restrict__ g,
                                                     const float* __restrict__ u,
                                                     fp16* __restrict__ o,
                                                     float* __restrict__ tension) {
    int row = blockIdx.x, t = threadIdx.x;
    const float* gr = g + (long)row * DII;
    const float* ur = u + (long)row * DII;
    fp16* orow = o + (long)row * DII;
    float sum = 0.f;
    #pragma unroll
    for (int j = 0; j < 6; j++) {
        int c = t + j * 256;
        float a = gr[c], bv = ur[c];
        float hv = (a / (1.f + __expf(-a))) * bv;
        orow[c] = __float2half_rn(hv);
        sum += hv;
    }
    float tot = block_reduce_sum_256(sum);
    if (t == 0) tension[row] = tanhf(tot * (1.f / DII));
}

// ---------------- MoE SwiGLU (folds router weight) -> fp16 plane ---------------
__global__ void __launch_bounds__(256) swiglu_moe_kernel(const float* __restrict__ buf,
                                                         const float* __restrict__ tw,
                                                         fp16* __restrict__ mh) {
    int row = blockIdx.x, e = blockIdx.y, t = threadIdx.x;
    int b = row / TT;
    float scale = tw[b * 3 + e];
    const float* gr = buf + (long)(2 * e) * ROWS * DII + (long)row * DII;
    const float* ur = buf + (long)(2 * e + 1) * ROWS * DII + (long)row * DII;
    fp16* orow = mh + (long)e * ROWS * DII + (long)row * DII;
    #pragma unroll
    for (int j = 0; j < 6; j++) {
        int c = t + j * 256;
        float a = gr[c], bv = ur[c];
        orow[c] = __float2half_rn((a / (1.f + __expf(-a))) * bv * scale);
    }
}

// ---------------- consciousness-state residual add ----------------
__global__ void __launch_bounds__(256) csadd_kernel(float* __restrict__ x,
                                                    const float* __restrict__ tension,
                                                    const float* __restrict__ tw) {
    int row = blockIdx.x, t = threadIdx.x;
    float ten = tension[row] * GATE_STRENGTH;
    float* xr = x + (long)row * DD;
    xr[t]       += ten * tw[t];
    xr[t + 256] += ten * tw[t + 256];
    xr[t + 512] += ten * tw[t + 512];
}

// ---------------- flash-style causal attention (fp32, GQA, vectorized) ---------
// Bit-identical math to the scalar version: per-d summation order preserved.
__global__ void __launch_bounds__(64) attn_kernel(const float* __restrict__ q,
                                                  const float* __restrict__ k,
                                                  const float* __restrict__ v,
                                                  fp16* __restrict__ o) {
    const int q0 = blockIdx.x * 64;
    const int h  = blockIdx.y;
    const int b  = blockIdx.z;
    const int t  = threadIdx.x;
    const int qg = q0 + t;
    const int kvh = h / (NHH / NKVV);

    __shared__ float Ks[64][64];
    __shared__ float Vs[64][64];

    float qreg[64], acc[64];
    const float4* qp4 = (const float4*)(q + ((long)(b * TT + qg) * NHH + h) * HDD);
    #pragma unroll
    for (int d4 = 0; d4 < 16; d4++) {
        float4 qv = qp4[d4];
        qreg[4*d4] = qv.x; qreg[4*d4+1] = qv.y; qreg[4*d4+2] = qv.z; qreg[4*d4+3] = qv.w;
    }
    #pragma unroll
    for (int d = 0; d < 64; d++) acc[d] = 0.f;
    float lsum = 0.f;

    const int rt = t >> 4, ct = (t & 15) * 4;   // fill: row group, col (float4)

    for (int s0 = 0; s0 <= q0; s0 += 64) {
        __syncthreads();
        #pragma unroll
        for (int j = 0; j < 16; j++) {
            int r = 4 * j + rt;
            long base = ((long)(b * TT + s0 + r) * NKVV + kvh) * HDD + ct;
            *(float4*)&Ks[r][ct] = *(const float4*)&k[base];
            *(float4*)&Vs[r][ct] = *(const float4*)&v[base];
        }
        __syncthreads();
        int kmax = min(64, qg - s0 + 1);
        for (int kk = 0; kk < kmax; kk++) {
            const float4* krow = (const float4*)Ks[kk];
            float s = 0.f;
            #pragma unroll
            for (int d4 = 0; d4 < 16; d4++) {
                float4 kv = krow[d4];
                s += qreg[4*d4]     * kv.x;
                s += qreg[4*d4 + 1] * kv.y;
                s += qreg[4*d4 + 2] * kv.z;
                s += qreg[4*d4 + 3] * kv.w;
            }
            float p = __expf(s * 0.125f);
            lsum += p;
            const float4* vrow = (const float4*)Vs[kk];
            #pragma unroll
            for (int d4 = 0; d4 < 16; d4++) {
                float4 vv = vrow[d4];
                acc[4*d4]     += p * vv.x;
                acc[4*d4 + 1] += p * vv.y;
                acc[4*d4 + 2] += p * vv.z;
                acc[4*d4 + 3] += p * vv.w;
            }
        }
    }
    float inv = 1.f / lsum;
    long base = ((long)(b * TT + qg) * NHH + h) * HDD;
    #pragma unroll
    for (int d = 0; d < 64; d += 2) {
        __half2 hv = __floats2half2_rn(acc[d] * inv, acc[d + 1] * inv);
        *(__half2*)&o[base + d] = hv;
    }
}

// ---------------- tensor-core GEMM: fp16 A plane, fp16 hi/lo B planes ----------
// C(MxN) = [C +] A@Bhi + A@Blo  (fp32 accum; B exact in fp16 hi+lo)
// 128x128 tile, 8 warps (64x32 warp tiles), BK=32, 2-stage cp.async, 2 CTA/SM.
// MODE 0: plain; optional pair (B2,C2) via blockIdx.z.
// MODE 1: MoE gate/up: z in [0,6): kexp=z>>1; plane = (z&1 ? B2 : B) +
//         (bb*3+kexp)*sstride; C += z*ROWS*N.
// MODE 2: MoE down: 3 K-segments; A seg s at +s*ROWS*K; B seg s at +(bb*3+s)*sstride.
template<bool ACC, bool TRANSB, int MODE>
__global__ void __launch_bounds__(256, 2) gemm_fp16(
    const fp16* __restrict__ A,
    const fp16* __restrict__ Bh, const fp16* __restrict__ Bl,
    float* __restrict__ C,
    const fp16* __restrict__ B2h, const fp16* __restrict__ B2l, float* __restrict__ C2,
    int M, int N, int K, long sstride)
{
    const int bx = blockIdx.x, by = blockIdx.y;
    const int bb = (by * 128) / TT;              // batch (tiles never straddle)
    if (MODE == 0) {
        if (B2h != nullptr && blockIdx.z == 1) { Bh = B2h; Bl = B2l; C = C2; }
    } else if (MODE == 1) {
        const int z = blockIdx.z, kexp = z >> 1;
        long off = (long)(bb * 3 + kexp) * sstride;
        if (z & 1) { Bh = B2h + off; Bl = B2l + off; }
        else       { Bh = Bh  + off; Bl = Bl  + off; }
        C += (long)z * ROWS * N;
    }
    const fp16 *Bsh[3], *Bsl[3];
    if (MODE == 2) {
        #pragma unroll
        for (int s = 0; s < 3; s++) {
            long off = (long)(bb * 3 + s) * sstride;
            Bsh[s] = Bh + off; Bsl[s] = Bl + off;
        }
    }

    extern __shared__ fp16 sm[];
    constexpr int ASZ2 = 128 * 40;
    constexpr int BSZ2 = TRANSB ? 128 * 40 : 32 * 136;
    fp16* smA  = sm;                 // [2][ASZ2]
    fp16* smBh = smA + 2 * ASZ2;     // [2][BSZ2]
    fp16* smBl = smBh + 2 * BSZ2;

    const unsigned uA  = (unsigned)__cvta_generic_to_shared(smA);
    const unsigned uBh = (unsigned)__cvta_generic_to_shared(smBh);
    const unsigned uBl = (unsigned)__cvta_generic_to_shared(smBl);

    const int tid = threadIdx.x;
    const int wid = tid >> 5, lane = tid & 31;
    const int g = lane >> 2, t = lane & 3;
    const int m0 = (wid & 1) * 64, n0 = (wid >> 1) * 32;

    const int arow = tid >> 1, acb = (tid & 1) * 16;
    const int kr = tid >> 3,  nb = (tid & 7) * 16;

    const int kIters = K >> 5;
    const int total  = (MODE == 2 ? 3 : 1) * kIters;

    auto issue = [&](int it, int st) {
        const int seg = (MODE == 2) ? it / kIters : 0;
        const int k0  = ((MODE == 2) ? (it % kIters) : it) * 32;
        const fp16* pA = A + ((MODE == 2) ? (long)seg * ROWS * K : 0);
        long aoff = (long)(by * 128 + arow) * K + k0 + acb;
        unsigned d = uA + (unsigned)(st * ASZ2 + arow * 40 + acb) * 2u;
        cp16(d, pA + aoff);       cp16(d + 16, pA + aoff + 8);
        if (TRANSB) {
            long boff = (long)(bx * 128 + arow) * K + k0 + acb;
            d = uBh + (unsigned)(st * BSZ2 + arow * 40 + acb) * 2u;
            cp16(d, Bh + boff);   cp16(d + 16, Bh + boff + 8);
            d = uBl + (unsigned)(st * BSZ2 + arow * 40 + acb) * 2u;
            cp16(d, Bl + boff);   cp16(d + 16, Bl + boff + 8);
        } else {
            const fp16* pBh = (MODE == 2) ? Bsh[seg] : Bh;
            const fp16* pBl = (MODE == 2) ? Bsl[seg] : Bl;
            long boff = (long)(k0 + kr) * N + bx * 128 + nb;
            d = uBh + (unsigned)(st * BSZ2 + kr * 136 + nb) * 2u;
            cp16(d, pBh + boff);   cp16(d + 16, pBh + boff + 8);
            d = uBl + (unsigned)(st * BSZ2 + kr * 136 + nb) * 2u;
            cp16(d, pBl + boff);   cp16(d + 16, pBl + boff + 8);
        }
        cp_commit();
    };

    float acc[4][4][4];
    #pragma unroll
    for (int i = 0; i < 4; i++)
        #pragma unroll
        for (int j = 0; j < 4; j++)
            #pragma unroll
            for (int e = 0; e < 4; e++) acc[i][j][e] = 0.f;

    issue(0, 0);

    for (int it = 0; it < total; it++) {
        const int st = it & 1;
        cp_wait0();
        __syncthreads();
        if (it + 1 < total) issue(it + 1, st ^ 1);

        const unsigned aO = (unsigned)(st * ASZ2) * 2u;
        const unsigned bO = (unsigned)(st * BSZ2) * 2u;
        #pragma unroll
        for (int ks = 0; ks < 2; ks++) {
            const int kk = ks * 16;
            unsigned ah[4][4];
            #pragma unroll
            for (int i = 0; i < 4; i++) {
                int row = m0 + i * 16 + (lane & 15);
                int col = kk + (lane >> 4) * 8;
                unsigned off = (unsigned)(row * 40 + col) * 2u;
                ldsm_x4(ah[i][0], ah[i][1], ah[i][2], ah[i][3], uA + aO + off);
            }
            unsigned bh[4][2], bl[4][2];
            if (TRANSB) {
                #pragma unroll
                for (int jp = 0; jp < 2; jp++) {
                    int row = n0 + jp * 16 + (lane & 15);
                    int col = kk + (lane >> 4) * 8;
                    unsigned off = (unsigned)(row * 40 + col) * 2u;
                    unsigned r0, r1, r2, r3;
                    ldsm_x4(r0, r1, r2, r3, uBh + bO + off);
                    bh[2*jp][0] = r0; bh[2*jp+1][0] = r1;
                    bh[2*jp][1] = r2; bh[2*jp+1][1] = r3;
                    ldsm_x4(r0, r1, r2, r3, uBl + bO + off);
                    bl[2*jp][0] = r0; bl[2*jp+1][0] = r1;
                    bl[2*jp][1] = r2; bl[2*jp+1][1] = r3;
                }
            } else {
                #pragma unroll
                for (int jp = 0; jp < 2; jp++) {
                    int row = kk + (lane & 15);
                    int col = n0 + jp * 16 + (lane >> 4) * 8;
                    unsigned off = (unsigned)(row * 136 + col) * 2u;
                    unsigned r0, r1, r2, r3;
                    ldsm_x4_t(r0, r1, r2, r3, uBh + bO + off);
                    bh[2*jp][0] = r0; bh[2*jp][1] = r1;
                    bh[2*jp+1][0] = r2; bh[2*jp+1][1] = r3;
                    ldsm_x4_t(r0, r1, r2, r3, uBl + bO + off);
                    bl[2*jp][0] = r0; bl[2*jp][1] = r1;
                    bl[2*jp+1][0] = r2; bl[2*jp+1][1] = r3;
                }
            }
            #pragma unroll
            for (int j = 0; j < 4; j++) {
                #pragma unroll
                for (int i = 0; i < 4; i++) {
                    mma16816(acc[i][j], ah[i], bh[j]);
                    mma16816(acc[i][j], ah[i], bl[j]);
                }
            }
        }
    }

    // ---- epilogue ----
    #pragma unroll
    for (int i = 0; i < 4; i++) {
        long r0 = (long)(by * 128 + m0 + i * 16 + g);
        long r1 = r0 + 8;
        #pragma unroll
        for (int j = 0; j < 4; j++) {
            long c = (long)(bx * 128 + n0 + j * 8 + 2 * t);
            if (ACC) {
                C[r0 * N + c]     += acc[i][j][0];
                C[r0 * N + c + 1] += acc[i][j][1];
                C[r1 * N + c]     += acc[i][j][2];
                C[r1 * N + c + 1] += acc[i][j][3];
            } else {
                *(float2*)&C[r0 * N + c] = make_float2(acc[i][j][0], acc[i][j][1]);
                *(float2*)&C[r1 * N + c] = make_float2(acc[i][j][2], acc[i][j][3]);
            }
        }
    }
}

// smem sizes
constexpr int SMN = (2 * 128 * 40 + 4 * 32 * 136) * 2;   // 55,296 B
constexpr int SMT = (2 * 128 * 40 + 4 * 128 * 40) * 2;   // 61,440 B

// ---------------- launch ----------------
extern "C" void kernel_launch(void* const* d_in, const int* in_sizes, int n_in,
                              void* d_out, int out_size) {
    const int*   idx       = (const int*)  d_in[0];
    const float* cons      = (const float*)d_in[1];
    const float* tok_emb   = (const float*)d_in[2];
    const float* head_g    = (const float*)d_in[3];
    const float* cv_w1     = (const float*)d_in[4];
    const float* cv_b1     = (const float*)d_in[5];
    const float* cv_w2     = (const float*)d_in[6];
    const float* cv_b2     = (const float*)d_in[7];
    const float* tension_w = (const float*)d_in[8];
    const float* ln_attn   = (const float*)d_in[9];
    const float* ln_pf     = (const float*)d_in[10];
    const float* ln_moe    = (const float*)d_in[11];
    const float* ln_f      = (const float*)d_in[12];
    const float* wq        = (const float*)d_in[13];
    const float* wk        = (const float*)d_in[14];
    const float* wv        = (const float*)d_in[15];
    const float* wo        = (const float*)d_in[16];
    const float* pf_gate   = (const float*)d_in[17];
    const float* pf_up     = (const float*)d_in[18];
    const float* pf_down   = (const float*)d_in[19];
    const float* e_gate    = (const float*)d_in[20];
    const float* e_up      = (const float*)d_in[21];
    const float* e_down    = (const float*)d_in[22];
    const float* router_w  = (const float*)d_in[23];
    const float* router_b  = (const float*)d_in[24];
    float* out = (float*)d_out;

    // scratch addresses
    float *xp, *qp, *kp, *vp, *ebp, *cvp, *twp;  int* tip;
    fp16 *hp, *aop, *hdp, *mhp;
    fp16 *wqh, *wql, *wkh, *wkl, *wvh, *wvl, *woh, *wol;
    fp16 *pgh, *pgl, *puh, *pul, *pdh, *pdl;
    fp16 *emh, *eml, *hgh, *hgl;
    fp16 *egh, *egl, *euh, *eul, *edh, *edl;
    cudaGetSymbolAddress((void**)&xp,  g_x);
    cudaGetSymbolAddress((void**)&qp,  g_q);
    cudaGetSymbolAddress((void**)&kp,  g_k);
    cudaGetSymbolAddress((void**)&vp,  g_v);
    cudaGetSymbolAddress((void**)&ebp, g_eb);
    cudaGetSymbolAddress((void**)&cvp, g_cv);
    cudaGetSymbolAddress((void**)&twp, g_tw);
    cudaGetSymbolAddress((void**)&tip, g_ti);
    cudaGetSymbolAddress((void**)&hp,  g_h);
    cudaGetSymbolAddress((void**)&aop, g_ao);
    cudaGetSymbolAddress((void**)&hdp, g_hd);
    cudaGetSymbolAddress((void**)&mhp, g_mh);
    cudaGetSymbolAddress((void**)&wqh, g_wq_h); cudaGetSymbolAddress((void**)&wql, g_wq_l);
    cudaGetSymbolAddress((void**)&wkh, g_wk_h); cudaGetSymbolAddress((void**)&wkl, g_wk_l);
    cudaGetSymbolAddress((void**)&wvh, g_wv_h); cudaGetSymbolAddress((void**)&wvl, g_wv_l);
    cudaGetSymbolAddress((void**)&woh, g_wo_h); cudaGetSymbolAddress((void**)&wol, g_wo_l);
    cudaGetSymbolAddress((void**)&pgh, g_pg_h); cudaGetSymbolAddress((void**)&pgl, g_pg_l);
    cudaGetSymbolAddress((void**)&puh, g_pu_h); cudaGetSymbolAddress((void**)&pul, g_pu_l);
    cudaGetSymbolAddress((void**)&pdh, g_pd_h); cudaGetSymbolAddress((void**)&pdl, g_pd_l);
    cudaGetSymbolAddress((void**)&emh, g_em_h); cudaGetSymbolAddress((void**)&eml, g_em_l);
    cudaGetSymbolAddress((void**)&hgh, g_hg_h); cudaGetSymbolAddress((void**)&hgl, g_hg_l);
    cudaGetSymbolAddress((void**)&egh, g_eg_h); cudaGetSymbolAddress((void**)&egl, g_eg_l);
    cudaGetSymbolAddress((void**)&euh, g_eu_h); cudaGetSymbolAddress((void**)&eul, g_eu_l);
    cudaGetSymbolAddress((void**)&edh, g_ed_h); cudaGetSymbolAddress((void**)&edl, g_ed_l);

    // opt-in smem (idempotent host calls, not captured)
    cudaFuncSetAttribute(gemm_fp16<false, false, 0>, cudaFuncAttributeMaxDynamicSharedMemorySize, SMN);
    cudaFuncSetAttribute(gemm_fp16<true,  false, 0>, cudaFuncAttributeMaxDynamicSharedMemorySize, SMN);
    cudaFuncSetAttribute(gemm_fp16<false, false, 1>, cudaFuncAttributeMaxDynamicSharedMemorySize, SMN);
    cudaFuncSetAttribute(gemm_fp16<true,  false, 2>, cudaFuncAttributeMaxDynamicSharedMemorySize, SMN);
    cudaFuncSetAttribute(gemm_fp16<false, true,  0>, cudaFuncAttributeMaxDynamicSharedMemorySize, SMT);

    float* tens = out + (long)2 * ROWS * VV;   // output tail: tensions (L, B, T)
    float* b1p = ebp;                          // PF gate fp32
    float* b2p = ebp + (long)ROWS * DII;       // PF up fp32

    // ---- preprocessing: embed, cv, routers, weight conversion ----
    embed_kernel<<<(ROWS * DD / 4 + 255) / 256, 256>>>(idx, tok_emb, xp);
    cv_kernel<<<1, 256>>>(cons, cv_w1, cv_b1, cv_w2, cv_b2, cvp);
    router_all_kernel<<<LL, 32>>>(cvp, router_w, router_b, twp, tip);

    auto convw = [&](const float* s, fp16* hi, fp16* lo, long n) {
        convw_kernel<<<(int)(n / 4 / 256), 256>>>(s, hi, lo, n);
    };
    convw(wq, wqh, wql, 6L * 768 * 768);
    convw(wk, wkh, wkl, 6L * 768 * 256);
    convw(wv, wvh, wvl, 6L * 768 * 256);
    convw(wo, woh, wol, 6L * 768 * 768);
    convw(pf_gate, pgh, pgl, 6L * 768 * 1536);
    convw(pf_up,   puh, pul, 6L * 768 * 1536);
    convw(pf_down, pdh, pdl, 6L * 1536 * 768);
    convw(tok_emb, emh, eml, (long)VV * DD);
    convw(head_g,  hgh, hgl, (long)VV * DD);
    convexp_kernel<<<dim3((int)(EXN / 4 / 256), 36, 3), 256>>>(
        e_gate, e_up, e_down, egh, egl, euh, eul, edh, edl, tip);

    const dim3 g768 (DD  / 128, ROWS / 128, 1);
    const dim3 gkv  (256 / 128, ROWS / 128, 2);
    const dim3 gff  (DII / 128, ROWS / 128, 2);
    const dim3 gegu (DII / 128, ROWS / 128, 6);
    const dim3 gdn  (DD  / 128, ROWS / 128, 1);

    for (int l = 0; l < LL; l++) {
        long o768  = (long)l * 768 * 768;
        long o256  = (long)l * 768 * 256;
        long o1536 = (long)l * 768 * 1536;
        long oexp  = (long)l * 6 * EXN;

        // ---- attention ----
        rms_kernel<<<ROWS, 256>>>(xp, ln_attn + (long)l * DD, hp);
        gemm_fp16<false, false, 0><<<g768, 256, SMN>>>(hp, wqh + o768, wql + o768, qp,
                                                       nullptr, nullptr, nullptr,
                                                       ROWS, 768, DD, 0);
        gemm_fp16<false, false, 0><<<gkv, 256, SMN>>>(hp, wkh + o256, wkl + o256, kp,
                                                      wvh + o256, wvl + o256, vp,
                                                      ROWS, 256, DD, 0);
        attn_kernel<<<dim3(TT / 64, NHH, BB), 64>>>(qp, kp, vp, aop);
        gemm_fp16<true, false, 0><<<g768, 256, SMN>>>(aop, woh + o768, wol + o768, xp,
                                                      nullptr, nullptr, nullptr,
                                                      ROWS, DD, 768, 0);

        // ---- PureField FFN + tension ----
        rms_kernel<<<ROWS, 256>>>(xp, ln_pf + (long)l * DD, hp);
        gemm_fp16<false, false, 0><<<gff, 256, SMN>>>(hp, pgh + o1536, pgl + o1536, b1p,
                                                      puh + o1536, pul + o1536, b2p,
                                                      ROWS, DII, DD, 0);
        swiglu_kernel<<<ROWS, 256>>>(b1p, b2p, hdp, tens + (long)l * ROWS);
        gemm_fp16<true, false, 0><<<g768, 256, SMN>>>(hdp, pdh + (long)l * 1536 * 768,
                                                      pdl + (long)l * 1536 * 768, xp,
                                                      nullptr, nullptr, nullptr,
                                                      ROWS, DD, DII, 0);

        // ---- consciousness-state residual (previous layer's tension) ----
        if (l > 0)
            csadd_kernel<<<ROWS, 256>>>(xp, tens + (long)(l - 1) * ROWS, tension_w);

        // ---- MoE ----
        rms_kernel<<<ROWS, 256>>>(xp, ln_moe + (long)l * DD, hp);
        gemm_fp16<false, false, 1><<<gegu, 256, SMN>>>(hp, egh + oexp, egl + oexp, ebp,
                                                       euh + oexp, eul + oexp, nullptr,
                                                       ROWS, DII, DD, EXN);
        swiglu_moe_kernel<<<dim3(ROWS, 3), 256>>>(ebp, twp + (long)l * 6, mhp);
        gemm_fp16<true, false, 2><<<gdn, 256, SMN>>>(mhp, edh + oexp, edl + oexp, xp,
                                                     nullptr, nullptr, nullptr,
                                                     ROWS, DD, DII, EXN);
    }

    // ---- final norm + tied heads (paired) ----
    rms_kernel<<<ROWS, 256>>>(xp, ln_f, hp);
    const dim3 gv(VV / 128, ROWS / 128, 2);
    gemm_fp16<false, true, 0><<<gv, 256, SMT>>>(hp, emh, eml, out,
                                                hgh, hgl, out + (long)ROWS * VV,
                                                ROWS, VV, DD, 0);
}

// round 15
// speedup vs baseline: 1.3287x; 1.0016x over previous
#include <cuda_runtime.h>
#include <cuda_fp16.h>
#include <math.h>

typedef __half fp16;

// ---------------- dims ----------------
#define BB   2
#define TT   2048
#define DD   768
#define NHH  12
#define NKVV 4
#define HDD  64
#define LL   6
#define VV   32000
#define DII  1536
#define NCC  64
#define CDD  128
#define ROWS (BB*TT)          // 4096
#define GATE_STRENGTH 0.001f
#define EXN  ((long)DD*DII)   // expert matrix elements = 1,179,648

// ---------------- fp32 scratch ----------------
__device__ float g_x [ROWS*DD];
__device__ float g_q [ROWS*NHH*HDD];
__device__ float g_k [ROWS*NKVV*HDD];
__device__ float g_v [ROWS*NKVV*HDD];
__device__ float g_eb[6L*ROWS*DII];    // gate/up GEMM outputs (PF uses slots 0,1)
__device__ float g_cv[BB*10];
__device__ float g_tw[LL*BB*3];
__device__ int   g_ti[LL*BB*3];

// ---------------- fp16 activation planes (single precision plane) --------------
__device__ fp16 g_h  [ROWS*DD];
__device__ fp16 g_ao [ROWS*NHH*HDD];
__device__ fp16 g_hd [ROWS*DII];          // PF hidden
__device__ fp16 g_mh [3L*ROWS*DII];       // MoE hidden

// ---------------- fp16 hi/lo weight planes (layouts as in source) --------------
__device__ fp16 g_wq_h[6L*768*768],  g_wq_l[6L*768*768];
__device__ fp16 g_wk_h[6L*768*256],  g_wk_l[6L*768*256];
__device__ fp16 g_wv_h[6L*768*256],  g_wv_l[6L*768*256];
__device__ fp16 g_wo_h[6L*768*768],  g_wo_l[6L*768*768];
__device__ fp16 g_pg_h[6L*768*1536], g_pg_l[6L*768*1536];
__device__ fp16 g_pu_h[6L*768*1536], g_pu_l[6L*768*1536];
__device__ fp16 g_pd_h[6L*1536*768], g_pd_l[6L*1536*768];
__device__ fp16 g_em_h[(long)VV*DD], g_em_l[(long)VV*DD];   // [N][K] for TRANSB
__device__ fp16 g_hg_h[(long)VV*DD], g_hg_l[(long)VV*DD];
__device__ fp16 g_eg_h[36L*DD*DII],  g_eg_l[36L*DD*DII];
__device__ fp16 g_eu_h[36L*DD*DII],  g_eu_l[36L*DD*DII];
__device__ fp16 g_ed_h[36L*DD*DII],  g_ed_l[36L*DD*DII];

// ---------------- helpers ----------------
__device__ __forceinline__ float block_reduce_sum_256(float v) {
    __shared__ float red[8];
    int t = threadIdx.x;
    #pragma unroll
    for (int off = 16; off; off >>= 1) v += __shfl_xor_sync(0xffffffffu, v, off);
    if ((t & 31) == 0) red[t >> 5] = v;
    __syncthreads();
    float tot = 0.f;
    #pragma unroll
    for (int i = 0; i < 8; i++) tot += red[i];
    return tot;
}

// weight split: hi/lo fp16 pairs (packed two at a time)
__device__ __forceinline__ void wsplit2(float f0, float f1, unsigned& hi, unsigned& lo) {
    __half2 h = __floats2half2_rn(f0, f1);
    float r0 = f0 - __half2float(__low2half(h));
    float r1 = f1 - __half2float(__high2half(h));
    __half2 l = __floats2half2_rn(r0, r1);
    hi = *(unsigned*)&h;
    lo = *(unsigned*)&l;
}

__device__ __forceinline__ void mma16816(float* c, const unsigned* a, const unsigned* b) {
    asm volatile(
        "mma.sync.aligned.m16n8k16.row.col.f32.f16.f16.f32 "
        "{%0,%1,%2,%3}, {%4,%5,%6,%7}, {%8,%9}, {%0,%1,%2,%3};\n"
        : "+f"(c[0]), "+f"(c[1]), "+f"(c[2]), "+f"(c[3])
        : "r"(a[0]), "r"(a[1]), "r"(a[2]), "r"(a[3]), "r"(b[0]), "r"(b[1]));
}

__device__ __forceinline__ void ldsm_x4(unsigned& r0, unsigned& r1, unsigned& r2,
                                        unsigned& r3, unsigned addr) {
    asm volatile("ldmatrix.sync.aligned.m8n8.x4.shared.b16 {%0,%1,%2,%3}, [%4];\n"
                 : "=r"(r0), "=r"(r1), "=r"(r2), "=r"(r3) : "r"(addr));
}

__device__ __forceinline__ void ldsm_x4_t(unsigned& r0, unsigned& r1, unsigned& r2,
                                          unsigned& r3, unsigned addr) {
    asm volatile("ldmatrix.sync.aligned.m8n8.x4.trans.shared.b16 {%0,%1,%2,%3}, [%4];\n"
                 : "=r"(r0), "=r"(r1), "=r"(r2), "=r"(r3) : "r"(addr));
}

__device__ __forceinline__ void cp16(unsigned dst, const void* src) {
    asm volatile("cp.async.cg.shared.global [%0], [%1], 16;\n" :: "r"(dst), "l"(src));
}
__device__ __forceinline__ void cp_commit() { asm volatile("cp.async.commit_group;\n"); }
__device__ __forceinline__ void cp_wait0()  { asm volatile("cp.async.wait_group 0;\n" ::: "memory"); }

// ---------------- weight converters (8 elems/thread, vectorized stores) --------
__global__ void convw_kernel(const float* __restrict__ s, fp16* __restrict__ hi,
                             fp16* __restrict__ lo, long n) {
    long i = ((long)blockIdx.x * blockDim.x + threadIdx.x) * 8;
    if (i < n) {
        float4 v0 = *(const float4*)(s + i);
        float4 v1 = *(const float4*)(s + i + 4);
        unsigned h0, l0, h1, l1, h2, l2, h3, l3;
        wsplit2(v0.x, v0.y, h0, l0);
        wsplit2(v0.z, v0.w, h1, l1);
        wsplit2(v1.x, v1.y, h2, l2);
        wsplit2(v1.z, v1.w, h3, l3);
        *(uint4*)&hi[i] = make_uint4(h0, h1, h2, h3);
        *(uint4*)&lo[i] = make_uint4(l0, l1, l2, l3);
    }
}

// selected-expert conversion: grid (EXN/2048, 36, 3)
__global__ void convexp_kernel(const float* __restrict__ eg, const float* __restrict__ eu,
                               const float* __restrict__ ed,
                               fp16* gh, fp16* gl, fp16* uh, fp16* ul,
                               fp16* dh, fp16* dl, const int* __restrict__ ti) {
    const int slot = blockIdx.y, mat = blockIdx.z;
    const int l = slot / 6, e = ti[slot];
    long i = ((long)blockIdx.x * 256 + threadIdx.x) * 8;
    if (i >= EXN) return;
    const float* src; fp16 *hi, *lo;
    if (mat == 0)      { src = eg; hi = gh; lo = gl; }
    else if (mat == 1) { src = eu; hi = uh; lo = ul; }
    else               { src = ed; hi = dh; lo = dl; }
    src += ((long)l * 10 + e) * EXN + i;
    hi  += (long)slot * EXN + i;
    lo  += (long)slot * EXN + i;
    float4 v0 = *(const float4*)src;
    float4 v1 = *(const float4*)(src + 4);
    unsigned h0, l0, h1, l1, h2, l2, h3, l3;
    wsplit2(v0.x, v0.y, h0, l0);
    wsplit2(v0.z, v0.w, h1, l1);
    wsplit2(v1.x, v1.y, h2, l2);
    wsplit2(v1.z, v1.w, h3, l3);
    *(uint4*)hi = make_uint4(h0, h1, h2, h3);
    *(uint4*)lo = make_uint4(l0, l1, l2, l3);
}

// ---------------- embedding (vectorized; DD % 4 == 0 so no row straddle) -------
__global__ void embed_kernel(const int* __restrict__ idx,
                             const float* __restrict__ emb,
                             float* __restrict__ x) {
    long i = ((long)blockIdx.x * blockDim.x + threadIdx.x) * 4;
    if (i < (long)ROWS * DD) {
        long r = i / DD, c = i % DD;
        *(float4*)&x[i] = *(const float4*)&emb[(long)idx[r] * DD + c];
    }
}

// ---------------- consciousness vector (tiny MLP) ----------------
__global__ void cv_kernel(const float* __restrict__ cs,
                          const float* __restrict__ w1, const float* __restrict__ b1,
                          const float* __restrict__ w2, const float* __restrict__ b2,
                          float* __restrict__ cv) {
    __shared__ float pooled[BB][CDD];
    __shared__ float h1[BB][64];
    int t = threadIdx.x;  // 256 threads
    {
        int b = t / CDD, c = t % CDD;
        float s = 0.f;
        for (int n = 0; n < NCC; n++)
            s += cs[((long)b * NCC + n) * CDD + c];
        pooled[b][c] = s * (1.f / NCC);
    }
    __syncthreads();
    if (t < BB * 64) {
        int b = t / 64, j = t % 64;
        float z = b1[j];
        for (int c = 0; c < CDD; c++) z += pooled[b][c] * w1[c * 64 + j];
        float z3 = z * z * z;
        h1[b][j] = 0.5f * z * (1.f + tanhf(0.7978845608028654f * (z + 0.044715f * z3)));
    }
    __syncthreads();
    if (t < BB * 10) {
        int b = t / 10, i = t % 10;
        float z = b2[i];
        for (int j = 0; j < 64; j++) z += h1[b][j] * w2[j * 10 + i];
        cv[b * 10 + i] = 1.f / (1.f + expf(-z));
    }
}

// ---------------- routers for all layers ----------------
__global__ void router_all_kernel(const float* __restrict__ cv,
                                  const float* __restrict__ W,
                                  const float* __restrict__ bias,
                                  float* __restrict__ tw, int* __restrict__ ti) {
    int l = blockIdx.x;
    int b = threadIdx.x;
    if (b >= BB) return;
    const float* Wl = W + (long)l * 100;
    const float* bl = bias + (long)l * 10;
    float lg[10];
    float mx = -1e30f;
    for (int i = 0; i < 10; i++) {
        float z = bl[i];
        for (int j = 0; j < 10; j++) z += cv[b * 10 + j] * Wl[j * 10 + i];
        lg[i] = z;
        mx = fmaxf(mx, z);
    }
    float se = 0.f;
    for (int i = 0; i < 10; i++) { lg[i] = expf(lg[i] - mx); se += lg[i]; }
    for (int i = 0; i < 10; i++) lg[i] /= se;
    float wsum = 0.f;
    int base = l * 6 + b * 3;
    for (int kk = 0; kk < 3; kk++) {
        int bi = 0; float bv = -1.f;
        for (int i = 0; i < 10; i++) if (lg[i] > bv) { bv = lg[i]; bi = i; }
        ti[base + kk] = bi; tw[base + kk] = bv; wsum += bv;
        lg[bi] = -2.f;
    }
    for (int kk = 0; kk < 3; kk++) tw[base + kk] /= wsum;
}

// ---------------- RMSNorm -> fp16 plane ----------------
__global__ void __launch_bounds__(256) rms_kernel(const float* __restrict__ x,
                                                  const float* __restrict__ w,
                                                  fp16* __restrict__ o) {
    int row = blockIdx.x, t = threadIdx.x;
    const float* xr = x + (long)row * DD;
    float v0 = xr[t], v1 = xr[t + 256], v2 = xr[t + 512];
    float tot = block_reduce_sum_256(v0 * v0 + v1 * v1 + v2 * v2);
    float s = rsqrtf(tot * (1.f / DD) + 1e-6f);
    fp16* orow = o + (long)row * DD;
    orow[t]       = __float2half_rn(v0 * s * w[t]);
    orow[t + 256] = __float2half_rn(v1 * s * w[t + 256]);
    orow[t + 512] = __float2half_rn(v2 * s * w[t + 512]);
}

// ---------------- fused cs-residual add + RMSNorm (MoE norm, l>0) --------------
// Bit-identical to csadd_kernel followed by rms_kernel.
__global__ void __launch_bounds__(256) rms_cs_kernel(float* __restrict__ x,
                                                     const float* __restrict__ w,
                                                     const float* __restrict__ tension,
                                                     const float* __restrict__ twv,
                                                     fp16* __restrict__ o) {
    int row = blockIdx.x, t = threadIdx.x;
    float* xr = x + (long)row * DD;
    float ten = tension[row] * GATE_STRENGTH;
    float v0 = xr[t]       + ten * twv[t];
    float v1 = xr[t + 256] + ten * twv[t + 256];
    float v2 = xr[t + 512] + ten * twv[t + 512];
    xr[t] = v0; xr[t + 256] = v1; xr[t + 512] = v2;
    float tot = block_reduce_sum_256(v0 * v0 + v1 * v1 + v2 * v2);
    float s = rsqrtf(tot * (1.f / DD) + 1e-6f);
    fp16* orow = o + (long)row * DD;
    orow[t]       = __float2half_rn(v0 * s * w[t]);
    orow[t + 256] = __float2half_rn(v1 * s * w[t + 256]);
    orow[t + 512] = __float2half_rn(v2 * s * w[t + 512]);
}

// ---------------- SwiGLU (+ tension) -> fp16 plane ----------------
__global__ void __launch_bounds__(256) swiglu_kernel(const float* __restrict__ g,
                                                     const float* __restrict__ u,
                                                     fp16* __restrict__ o,
                                                     float* __restrict__ tension) {
    int row = blockIdx.x, t = threadIdx.x;
    const float* gr = g + (long)row * DII;
    const float* ur = u + (long)row * DII;
    fp16* orow = o + (long)row * DII;
    float sum = 0.f;
    #pragma unroll
    for (int j = 0; j < 6; j++) {
        int c = t + j * 256;
        float a = gr[c], bv = ur[c];
        float hv = (a / (1.f + __expf(-a))) * bv;
        orow[c] = __float2half_rn(hv);
        sum += hv;
    }
    float tot = block_reduce_sum_256(sum);
    if (t == 0) tension[row] = tanhf(tot * (1.f / DII));
}

// ---------------- MoE SwiGLU (folds router weight) -> fp16 plane ---------------
__global__ void __launch_bounds__(256) swiglu_moe_kernel(const float* __restrict__ buf,
                                                         const float* __restrict__ tw,
                                                         fp16* __restrict__ mh) {
    int row = blockIdx.x, e = blockIdx.y, t = threadIdx.x;
    int b = row / TT;
    float scale = tw[b * 3 + e];
    const float* gr = buf + (long)(2 * e) * ROWS * DII + (long)row * DII;
    const float* ur = buf + (long)(2 * e + 1) * ROWS * DII + (long)row * DII;
    fp16* orow = mh + (long)e * ROWS * DII + (long)row * DII;
    #pragma unroll
    for (int j = 0; j < 6; j++) {
        int c = t + j * 256;
        float a = gr[c], bv = ur[c];
        orow[c] = __float2half_rn((a / (1.f + __expf(-a))) * bv * scale);
    }
}

// ---------------- flash-style causal attention (fp32, GQA, vectorized) ---------
__global__ void __launch_bounds__(64) attn_kernel(const float* __restrict__ q,
                                                  const float* __restrict__ k,
                                                  const float* __restrict__ v,
                                                  fp16* __restrict__ o) {
    const int q0 = blockIdx.x * 64;
    const int h  = blockIdx.y;
    const int b  = blockIdx.z;
    const int t  = threadIdx.x;
    const int qg = q0 + t;
    const int kvh = h / (NHH / NKVV);

    __shared__ float Ks[64][64];
    __shared__ float Vs[64][64];

    float qreg[64], acc[64];
    const float4* qp4 = (const float4*)(q + ((long)(b * TT + qg) * NHH + h) * HDD);
    #pragma unroll
    for (int d4 = 0; d4 < 16; d4++) {
        float4 qv = qp4[d4];
        qreg[4*d4] = qv.x; qreg[4*d4+1] = qv.y; qreg[4*d4+2] = qv.z; qreg[4*d4+3] = qv.w;
    }
    #pragma unroll
    for (int d = 0; d < 64; d++) acc[d] = 0.f;
    float lsum = 0.f;

    const int rt = t >> 4, ct = (t & 15) * 4;

    for (int s0 = 0; s0 <= q0; s0 += 64) {
        __syncthreads();
        #pragma unroll
        for (int j = 0; j < 16; j++) {
            int r = 4 * j + rt;
            long base = ((long)(b * TT + s0 + r) * NKVV + kvh) * HDD + ct;
            *(float4*)&Ks[r][ct] = *(const float4*)&k[base];
            *(float4*)&Vs[r][ct] = *(const float4*)&v[base];
        }
        __syncthreads();
        int kmax = min(64, qg - s0 + 1);
        for (int kk = 0; kk < kmax; kk++) {
            const float4* krow = (const float4*)Ks[kk];
            float s = 0.f;
            #pragma unroll
            for (int d4 = 0; d4 < 16; d4++) {
                float4 kv = krow[d4];
                s += qreg[4*d4]     * kv.x;
                s += qreg[4*d4 + 1] * kv.y;
                s += qreg[4*d4 + 2] * kv.z;
                s += qreg[4*d4 + 3] * kv.w;
            }
            float p = __expf(s * 0.125f);
            lsum += p;
            const float4* vrow = (const float4*)Vs[kk];
            #pragma unroll
            for (int d4 = 0; d4 < 16; d4++) {
                float4 vv = vrow[d4];
                acc[4*d4]     += p * vv.x;
                acc[4*d4 + 1] += p * vv.y;
                acc[4*d4 + 2] += p * vv.z;
                acc[4*d4 + 3] += p * vv.w;
            }
        }
    }
    float inv = 1.f / lsum;
    long base = ((long)(b * TT + qg) * NHH + h) * HDD;
    #pragma unroll
    for (int d = 0; d < 64; d += 2) {
        __half2 hv = __floats2half2_rn(acc[d] * inv, acc[d + 1] * inv);
        *(__half2*)&o[base + d] = hv;
    }
}

// ---------------- tensor-core GEMM: fp16 A plane, fp16 hi/lo B planes ----------
// C(MxN) = [C +] A@Bhi + A@Blo  (fp32 accum; B exact in fp16 hi+lo)
// 128x128 tile, 8 warps (64x32 warp tiles), BK=32, 2-stage cp.async, 2 CTA/SM.
// MODE 0: plain; optional pair (B2,C2) via blockIdx.z.
// MODE 1: MoE gate/up: z in [0,6): kexp=z>>1; plane = (z&1 ? B2 : B) +
//         (bb*3+kexp)*sstride; C += z*ROWS*N.
// MODE 2: MoE down: 3 K-segments; A seg s at +s*ROWS*K; B seg s at +(bb*3+s)*sstride.
template<bool ACC, bool TRANSB, int MODE>
__global__ void __launch_bounds__(256, 2) gemm_fp16(
    const fp16* __restrict__ A,
    const fp16* __restrict__ Bh, const fp16* __restrict__ Bl,
    float* __restrict__ C,
    const fp16* __restrict__ B2h, const fp16* __restrict__ B2l, float* __restrict__ C2,
    int M, int N, int K, long sstride)
{
    const int bx = blockIdx.x, by = blockIdx.y;
    const int bb = (by * 128) / TT;              // batch (tiles never straddle)
    if (MODE == 0) {
        if (B2h != nullptr && blockIdx.z == 1) { Bh = B2h; Bl = B2l; C = C2; }
    } else if (MODE == 1) {
        const int z = blockIdx.z, kexp = z >> 1;
        long off = (long)(bb * 3 + kexp) * sstride;
        if (z & 1) { Bh = B2h + off; Bl = B2l + off; }
        else       { Bh = Bh  + off; Bl = Bl  + off; }
        C += (long)z * ROWS * N;
    }
    const fp16 *Bsh[3], *Bsl[3];
    if (MODE == 2) {
        #pragma unroll
        for (int s = 0; s < 3; s++) {
            long off = (long)(bb * 3 + s) * sstride;
            Bsh[s] = Bh + off; Bsl[s] = Bl + off;
        }
    }

    extern __shared__ fp16 sm[];
    constexpr int ASZ2 = 128 * 40;
    constexpr int BSZ2 = TRANSB ? 128 * 40 : 32 * 136;
    fp16* smA  = sm;                 // [2][ASZ2]
    fp16* smBh = smA + 2 * ASZ2;     // [2][BSZ2]
    fp16* smBl = smBh + 2 * BSZ2;

    const unsigned uA  = (unsigned)__cvta_generic_to_shared(smA);
    const unsigned uBh = (unsigned)__cvta_generic_to_shared(smBh);
    const unsigned uBl = (unsigned)__cvta_generic_to_shared(smBl);

    const int tid = threadIdx.x;
    const int wid = tid >> 5, lane = tid & 31;
    const int g = lane >> 2, t = lane & 3;
    const int m0 = (wid & 1) * 64, n0 = (wid >> 1) * 32;

    const int arow = tid >> 1, acb = (tid & 1) * 16;
    const int kr = tid >> 3,  nb = (tid & 7) * 16;

    const int kIters = K >> 5;
    const int total  = (MODE == 2 ? 3 : 1) * kIters;

    auto issue = [&](int it, int st) {
        const int seg = (MODE == 2) ? it / kIters : 0;
        const int k0  = ((MODE == 2) ? (it % kIters) : it) * 32;
        const fp16* pA = A + ((MODE == 2) ? (long)seg * ROWS * K : 0);
        long aoff = (long)(by * 128 + arow) * K + k0 + acb;
        unsigned d = uA + (unsigned)(st * ASZ2 + arow * 40 + acb) * 2u;
        cp16(d, pA + aoff);       cp16(d + 16, pA + aoff + 8);
        if (TRANSB) {
            long boff = (long)(bx * 128 + arow) * K + k0 + acb;
            d = uBh + (unsigned)(st * BSZ2 + arow * 40 + acb) * 2u;
            cp16(d, Bh + boff);   cp16(d + 16, Bh + boff + 8);
            d = uBl + (unsigned)(st * BSZ2 + arow * 40 + acb) * 2u;
            cp16(d, Bl + boff);   cp16(d + 16, Bl + boff + 8);
        } else {
            const fp16* pBh = (MODE == 2) ? Bsh[seg] : Bh;
            const fp16* pBl = (MODE == 2) ? Bsl[seg] : Bl;
            long boff = (long)(k0 + kr) * N + bx * 128 + nb;
            d = uBh + (unsigned)(st * BSZ2 + kr * 136 + nb) * 2u;
            cp16(d, pBh + boff);   cp16(d + 16, pBh + boff + 8);
            d = uBl + (unsigned)(st * BSZ2 + kr * 136 + nb) * 2u;
            cp16(d, pBl + boff);   cp16(d + 16, pBl + boff + 8);
        }
        cp_commit();
    };

    float acc[4][4][4];
    #pragma unroll
    for (int i = 0; i < 4; i++)
        #pragma unroll
        for (int j = 0; j < 4; j++)
            #pragma unroll
            for (int e = 0; e < 4; e++) acc[i][j][e] = 0.f;

    issue(0, 0);

    for (int it = 0; it < total; it++) {
        const int st = it & 1;
        cp_wait0();
        __syncthreads();
        if (it + 1 < total) issue(it + 1, st ^ 1);

        const unsigned aO = (unsigned)(st * ASZ2) * 2u;
        const unsigned bO = (unsigned)(st * BSZ2) * 2u;
        #pragma unroll
        for (int ks = 0; ks < 2; ks++) {
            const int kk = ks * 16;
            unsigned ah[4][4];
            #pragma unroll
            for (int i = 0; i < 4; i++) {
                int row = m0 + i * 16 + (lane & 15);
                int col = kk + (lane >> 4) * 8;
                unsigned off = (unsigned)(row * 40 + col) * 2u;
                ldsm_x4(ah[i][0], ah[i][1], ah[i][2], ah[i][3], uA + aO + off);
            }
            unsigned bh[4][2], bl[4][2];
            if (TRANSB) {
                #pragma unroll
                for (int jp = 0; jp < 2; jp++) {
                    int row = n0 + jp * 16 + (lane & 15);
                    int col = kk + (lane >> 4) * 8;
                    unsigned off = (unsigned)(row * 40 + col) * 2u;
                    unsigned r0, r1, r2, r3;
                    ldsm_x4(r0, r1, r2, r3, uBh + bO + off);
                    bh[2*jp][0] = r0; bh[2*jp+1][0] = r1;
                    bh[2*jp][1] = r2; bh[2*jp+1][1] = r3;
                    ldsm_x4(r0, r1, r2, r3, uBl + bO + off);
                    bl[2*jp][0] = r0; bl[2*jp+1][0] = r1;
                    bl[2*jp][1] = r2; bl[2*jp+1][1] = r3;
                }
            } else {
                #pragma unroll
                for (int jp = 0; jp < 2; jp++) {
                    int row = kk + (lane & 15);
                    int col = n0 + jp * 16 + (lane >> 4) * 8;
                    unsigned off = (unsigned)(row * 136 + col) * 2u;
                    unsigned r0, r1, r2, r3;
                    ldsm_x4_t(r0, r1, r2, r3, uBh + bO + off);
                    bh[2*jp][0] = r0; bh[2*jp][1] = r1;
                    bh[2*jp+1][0] = r2; bh[2*jp+1][1] = r3;
                    ldsm_x4_t(r0, r1, r2, r3, uBl + bO + off);
                    bl[2*jp][0] = r0; bl[2*jp][1] = r1;
                    bl[2*jp+1][0] = r2; bl[2*jp+1][1] = r3;
                }
            }
            #pragma unroll
            for (int j = 0; j < 4; j++) {
                #pragma unroll
                for (int i = 0; i < 4; i++) {
                    mma16816(acc[i][j], ah[i], bh[j]);
                    mma16816(acc[i][j], ah[i], bl[j]);
                }
            }
        }
    }

    // ---- epilogue ----
    #pragma unroll
    for (int i = 0; i < 4; i++) {
        long r0 = (long)(by * 128 + m0 + i * 16 + g);
        long r1 = r0 + 8;
        #pragma unroll
        for (int j = 0; j < 4; j++) {
            long c = (long)(bx * 128 + n0 + j * 8 + 2 * t);
            if (ACC) {
                C[r0 * N + c]     += acc[i][j][0];
                C[r0 * N + c + 1] += acc[i][j][1];
                C[r1 * N + c]     += acc[i][j][2];
                C[r1 * N + c + 1] += acc[i][j][3];
            } else {
                *(float2*)&C[r0 * N + c] = make_float2(acc[i][j][0], acc[i][j][1]);
                *(float2*)&C[r1 * N + c] = make_float2(acc[i][j][2], acc[i][j][3]);
            }
        }
    }
}

// smem sizes
constexpr int SMN = (2 * 128 * 40 + 4 * 32 * 136) * 2;   // 55,296 B
constexpr int SMT = (2 * 128 * 40 + 4 * 128 * 40) * 2;   // 61,440 B

// ---------------- launch ----------------
extern "C" void kernel_launch(void* const* d_in, const int* in_sizes, int n_in,
                              void* d_out, int out_size) {
    const int*   idx       = (const int*)  d_in[0];
    const float* cons      = (const float*)d_in[1];
    const float* tok_emb   = (const float*)d_in[2];
    const float* head_g    = (const float*)d_in[3];
    const float* cv_w1     = (const float*)d_in[4];
    const float* cv_b1     = (const float*)d_in[5];
    const float* cv_w2     = (const float*)d_in[6];
    const float* cv_b2     = (const float*)d_in[7];
    const float* tension_w = (const float*)d_in[8];
    const float* ln_attn   = (const float*)d_in[9];
    const float* ln_pf     = (const float*)d_in[10];
    const float* ln_moe    = (const float*)d_in[11];
    const float* ln_f      = (const float*)d_in[12];
    const float* wq        = (const float*)d_in[13];
    const float* wk        = (const float*)d_in[14];
    const float* wv        = (const float*)d_in[15];
    const float* wo        = (const float*)d_in[16];
    const float* pf_gate   = (const float*)d_in[17];
    const float* pf_up     = (const float*)d_in[18];
    const float* pf_down   = (const float*)d_in[19];
    const float* e_gate    = (const float*)d_in[20];
    const float* e_up      = (const float*)d_in[21];
    const float* e_down    = (const float*)d_in[22];
    const float* router_w  = (const float*)d_in[23];
    const float* router_b  = (const float*)d_in[24];
    float* out = (float*)d_out;

    // scratch addresses
    float *xp, *qp, *kp, *vp, *ebp, *cvp, *twp;  int* tip;
    fp16 *hp, *aop, *hdp, *mhp;
    fp16 *wqh, *wql, *wkh, *wkl, *wvh, *wvl, *woh, *wol;
    fp16 *pgh, *pgl, *puh, *pul, *pdh, *pdl;
    fp16 *emh, *eml, *hgh, *hgl;
    fp16 *egh, *egl, *euh, *eul, *edh, *edl;
    cudaGetSymbolAddress((void**)&xp,  g_x);
    cudaGetSymbolAddress((void**)&qp,  g_q);
    cudaGetSymbolAddress((void**)&kp,  g_k);
    cudaGetSymbolAddress((void**)&vp,  g_v);
    cudaGetSymbolAddress((void**)&ebp, g_eb);
    cudaGetSymbolAddress((void**)&cvp, g_cv);
    cudaGetSymbolAddress((void**)&twp, g_tw);
    cudaGetSymbolAddress((void**)&tip, g_ti);
    cudaGetSymbolAddress((void**)&hp,  g_h);
    cudaGetSymbolAddress((void**)&aop, g_ao);
    cudaGetSymbolAddress((void**)&hdp, g_hd);
    cudaGetSymbolAddress((void**)&mhp, g_mh);
    cudaGetSymbolAddress((void**)&wqh, g_wq_h); cudaGetSymbolAddress((void**)&wql, g_wq_l);
    cudaGetSymbolAddress((void**)&wkh, g_wk_h); cudaGetSymbolAddress((void**)&wkl, g_wk_l);
    cudaGetSymbolAddress((void**)&wvh, g_wv_h); cudaGetSymbolAddress((void**)&wvl, g_wv_l);
    cudaGetSymbolAddress((void**)&woh, g_wo_h); cudaGetSymbolAddress((void**)&wol, g_wo_l);
    cudaGetSymbolAddress((void**)&pgh, g_pg_h); cudaGetSymbolAddress((void**)&pgl, g_pg_l);
    cudaGetSymbolAddress((void**)&puh, g_pu_h); cudaGetSymbolAddress((void**)&pul, g_pu_l);
    cudaGetSymbolAddress((void**)&pdh, g_pd_h); cudaGetSymbolAddress((void**)&pdl, g_pd_l);
    cudaGetSymbolAddress((void**)&emh, g_em_h); cudaGetSymbolAddress((void**)&eml, g_em_l);
    cudaGetSymbolAddress((void**)&hgh, g_hg_h); cudaGetSymbolAddress((void**)&hgl, g_hg_l);
    cudaGetSymbolAddress((void**)&egh, g_eg_h); cudaGetSymbolAddress((void**)&egl, g_eg_l);
    cudaGetSymbolAddress((void**)&euh, g_eu_h); cudaGetSymbolAddress((void**)&eul, g_eu_l);
    cudaGetSymbolAddress((void**)&edh, g_ed_h); cudaGetSymbolAddress((void**)&edl, g_ed_l);

    // opt-in smem (idempotent host calls, not captured)
    cudaFuncSetAttribute(gemm_fp16<false, false, 0>, cudaFuncAttributeMaxDynamicSharedMemorySize, SMN);
    cudaFuncSetAttribute(gemm_fp16<true,  false, 0>, cudaFuncAttributeMaxDynamicSharedMemorySize, SMN);
    cudaFuncSetAttribute(gemm_fp16<false, false, 1>, cudaFuncAttributeMaxDynamicSharedMemorySize, SMN);
    cudaFuncSetAttribute(gemm_fp16<true,  false, 2>, cudaFuncAttributeMaxDynamicSharedMemorySize, SMN);
    cudaFuncSetAttribute(gemm_fp16<false, true,  0>, cudaFuncAttributeMaxDynamicSharedMemorySize, SMT);

    float* tens = out + (long)2 * ROWS * VV;   // output tail: tensions (L, B, T)
    float* b1p = ebp;                          // PF gate fp32
    float* b2p = ebp + (long)ROWS * DII;       // PF up fp32

    // ---- preprocessing: embed, cv, routers, weight conversion ----
    embed_kernel<<<(ROWS * DD / 4 + 255) / 256, 256>>>(idx, tok_emb, xp);
    cv_kernel<<<1, 256>>>(cons, cv_w1, cv_b1, cv_w2, cv_b2, cvp);
    router_all_kernel<<<LL, 32>>>(cvp, router_w, router_b, twp, tip);

    auto convw = [&](const float* s, fp16* hi, fp16* lo, long n) {
        convw_kernel<<<(int)((n / 8 + 255) / 256), 256>>>(s, hi, lo, n);
    };
    convw(wq, wqh, wql, 6L * 768 * 768);
    convw(wk, wkh, wkl, 6L * 768 * 256);
    convw(wv, wvh, wvl, 6L * 768 * 256);
    convw(wo, woh, wol, 6L * 768 * 768);
    convw(pf_gate, pgh, pgl, 6L * 768 * 1536);
    convw(pf_up,   puh, pul, 6L * 768 * 1536);
    convw(pf_down, pdh, pdl, 6L * 1536 * 768);
    convw(tok_emb, emh, eml, (long)VV * DD);
    convw(head_g,  hgh, hgl, (long)VV * DD);
    convexp_kernel<<<dim3((int)(EXN / 8 / 256), 36, 3), 256>>>(
        e_gate, e_up, e_down, egh, egl, euh, eul, edh, edl, tip);

    const dim3 g768 (DD  / 128, ROWS / 128, 1);
    const dim3 gkv  (256 / 128, ROWS / 128, 2);
    const dim3 gff  (DII / 128, ROWS / 128, 2);
    const dim3 gegu (DII / 128, ROWS / 128, 6);
    const dim3 gdn  (DD  / 128, ROWS / 128, 1);

    for (int l = 0; l < LL; l++) {
        long o768  = (long)l * 768 * 768;
        long o256  = (long)l * 768 * 256;
        long o1536 = (long)l * 768 * 1536;
        long oexp  = (long)l * 6 * EXN;

        // ---- attention ----
        rms_kernel<<<ROWS, 256>>>(xp, ln_attn + (long)l * DD, hp);
        gemm_fp16<false, false, 0><<<g768, 256, SMN>>>(hp, wqh + o768, wql + o768, qp,
                                                       nullptr, nullptr, nullptr,
                                                       ROWS, 768, DD, 0);
        gemm_fp16<false, false, 0><<<gkv, 256, SMN>>>(hp, wkh + o256, wkl + o256, kp,
                                                      wvh + o256, wvl + o256, vp,
                                                      ROWS, 256, DD, 0);
        attn_kernel<<<dim3(TT / 64, NHH, BB), 64>>>(qp, kp, vp, aop);
        gemm_fp16<true, false, 0><<<g768, 256, SMN>>>(aop, woh + o768, wol + o768, xp,
                                                      nullptr, nullptr, nullptr,
                                                      ROWS, DD, 768, 0);

        // ---- PureField FFN + tension ----
        rms_kernel<<<ROWS, 256>>>(xp, ln_pf + (long)l * DD, hp);
        gemm_fp16<false, false, 0><<<gff, 256, SMN>>>(hp, pgh + o1536, pgl + o1536, b1p,
                                                      puh + o1536, pul + o1536, b2p,
                                                      ROWS, DII, DD, 0);
        swiglu_kernel<<<ROWS, 256>>>(b1p, b2p, hdp, tens + (long)l * ROWS);
        gemm_fp16<true, false, 0><<<g768, 256, SMN>>>(hdp, pdh + (long)l * 1536 * 768,
                                                      pdl + (long)l * 1536 * 768, xp,
                                                      nullptr, nullptr, nullptr,
                                                      ROWS, DD, DII, 0);

        // ---- MoE norm (fused with cs residual for l>0; bit-identical) ----
        if (l > 0)
            rms_cs_kernel<<<ROWS, 256>>>(xp, ln_moe + (long)l * DD,
                                         tens + (long)(l - 1) * ROWS, tension_w, hp);
        else
            rms_kernel<<<ROWS, 256>>>(xp, ln_moe + (long)l * DD, hp);

        // ---- MoE ----
        gemm_fp16<false, false, 1><<<gegu, 256, SMN>>>(hp, egh + oexp, egl + oexp, ebp,
                                                       euh + oexp, eul + oexp, nullptr,
                                                       ROWS, DII, DD, EXN);
        swiglu_moe_kernel<<<dim3(ROWS, 3), 256>>>(ebp, twp + (long)l * 6, mhp);
        gemm_fp16<true, false, 2><<<gdn, 256, SMN>>>(mhp, edh + oexp, edl + oexp, xp,
                                                     nullptr, nullptr, nullptr,
                                                     ROWS, DD, DII, EXN);
    }

    // ---- final norm + tied heads (paired) ----
    rms_kernel<<<ROWS, 256>>>(xp, ln_f, hp);
    const dim3 gv(VV / 128, ROWS / 128, 2);
    gemm_fp16<false, true, 0><<<gv, 256, SMT>>>(hp, emh, eml, out,
                                                hgh, hgl, out + (long)ROWS * VV,
                                                ROWS, VV, DD, 0);
}

// round 16
// speedup vs baseline: 1.3871x; 1.0439x over previous
#include <cuda_runtime.h>
#include <cuda_fp16.h>
#include <math.h>

typedef __half fp16;

// ---------------- dims ----------------
#define BB   2
#define TT   2048
#define DD   768
#define NHH  12
#define NKVV 4
#define HDD  64
#define LL   6
#define VV   32000
#define DII  1536
#define NCC  64
#define CDD  128
#define ROWS (BB*TT)          // 4096
#define GATE_STRENGTH 0.001f
#define EXN  ((long)DD*DII)   // expert matrix elements = 1,179,648

// ---------------- fp32 scratch ----------------
__device__ float g_x [ROWS*DD];
__device__ float g_q [ROWS*NHH*HDD];
__device__ float g_k [ROWS*NKVV*HDD];
__device__ float g_v [ROWS*NKVV*HDD];
__device__ float g_eb[6L*ROWS*DII];    // gate/up outputs; also MoE-down partials
__device__ float g_cv[BB*10];
__device__ float g_tw[LL*BB*3];
__device__ int   g_ti[LL*BB*3];

// ---------------- fp16 activation planes (single precision plane) --------------
__device__ fp16 g_h  [ROWS*DD];
__device__ fp16 g_ao [ROWS*NHH*HDD];
__device__ fp16 g_hd [ROWS*DII];          // PF hidden
__device__ fp16 g_mh [3L*ROWS*DII];       // MoE hidden

// ---------------- fp16 hi/lo weight planes (layouts as in source) --------------
__device__ fp16 g_wq_h[6L*768*768],  g_wq_l[6L*768*768];
__device__ fp16 g_wk_h[6L*768*256],  g_wk_l[6L*768*256];
__device__ fp16 g_wv_h[6L*768*256],  g_wv_l[6L*768*256];
__device__ fp16 g_wo_h[6L*768*768],  g_wo_l[6L*768*768];
__device__ fp16 g_pg_h[6L*768*1536], g_pg_l[6L*768*1536];
__device__ fp16 g_pu_h[6L*768*1536], g_pu_l[6L*768*1536];
__device__ fp16 g_pd_h[6L*1536*768], g_pd_l[6L*1536*768];
__device__ fp16 g_em_h[(long)VV*DD], g_em_l[(long)VV*DD];   // [N][K] for TRANSB
__device__ fp16 g_hg_h[(long)VV*DD], g_hg_l[(long)VV*DD];
__device__ fp16 g_eg_h[36L*DD*DII],  g_eg_l[36L*DD*DII];
__device__ fp16 g_eu_h[36L*DD*DII],  g_eu_l[36L*DD*DII];
__device__ fp16 g_ed_h[36L*DD*DII],  g_ed_l[36L*DD*DII];

// ---------------- helpers ----------------
__device__ __forceinline__ float block_reduce_sum_256(float v) {
    __shared__ float red[8];
    int t = threadIdx.x;
    #pragma unroll
    for (int off = 16; off; off >>= 1) v += __shfl_xor_sync(0xffffffffu, v, off);
    if ((t & 31) == 0) red[t >> 5] = v;
    __syncthreads();
    float tot = 0.f;
    #pragma unroll
    for (int i = 0; i < 8; i++) tot += red[i];
    return tot;
}

// weight split: hi/lo fp16 pairs (packed two at a time)
__device__ __forceinline__ void wsplit2(float f0, float f1, unsigned& hi, unsigned& lo) {
    __half2 h = __floats2half2_rn(f0, f1);
    float r0 = f0 - __half2float(__low2half(h));
    float r1 = f1 - __half2float(__high2half(h));
    __half2 l = __floats2half2_rn(r0, r1);
    hi = *(unsigned*)&h;
    lo = *(unsigned*)&l;
}

__device__ __forceinline__ void mma16816(float* c, const unsigned* a, const unsigned* b) {
    asm volatile(
        "mma.sync.aligned.m16n8k16.row.col.f32.f16.f16.f32 "
        "{%0,%1,%2,%3}, {%4,%5,%6,%7}, {%8,%9}, {%0,%1,%2,%3};\n"
        : "+f"(c[0]), "+f"(c[1]), "+f"(c[2]), "+f"(c[3])
        : "r"(a[0]), "r"(a[1]), "r"(a[2]), "r"(a[3]), "r"(b[0]), "r"(b[1]));
}

__device__ __forceinline__ void ldsm_x4(unsigned& r0, unsigned& r1, unsigned& r2,
                                        unsigned& r3, unsigned addr) {
    asm volatile("ldmatrix.sync.aligned.m8n8.x4.shared.b16 {%0,%1,%2,%3}, [%4];\n"
                 : "=r"(r0), "=r"(r1), "=r"(r2), "=r"(r3) : "r"(addr));
}

__device__ __forceinline__ void ldsm_x4_t(unsigned& r0, unsigned& r1, unsigned& r2,
                                          unsigned& r3, unsigned addr) {
    asm volatile("ldmatrix.sync.aligned.m8n8.x4.trans.shared.b16 {%0,%1,%2,%3}, [%4];\n"
                 : "=r"(r0), "=r"(r1), "=r"(r2), "=r"(r3) : "r"(addr));
}

__device__ __forceinline__ void cp16(unsigned dst, const void* src) {
    asm volatile("cp.async.cg.shared.global [%0], [%1], 16;\n" :: "r"(dst), "l"(src));
}
__device__ __forceinline__ void cp_commit() { asm volatile("cp.async.commit_group;\n"); }
__device__ __forceinline__ void cp_wait0()  { asm volatile("cp.async.wait_group 0;\n" ::: "memory"); }

// ---------------- weight converters (8 elems/thread, vectorized stores) --------
__global__ void convw_kernel(const float* __restrict__ s, fp16* __restrict__ hi,
                             fp16* __restrict__ lo, long n) {
    long i = ((long)blockIdx.x * blockDim.x + threadIdx.x) * 8;
    if (i < n) {
        float4 v0 = *(const float4*)(s + i);
        float4 v1 = *(const float4*)(s + i + 4);
        unsigned h0, l0, h1, l1, h2, l2, h3, l3;
        wsplit2(v0.x, v0.y, h0, l0);
        wsplit2(v0.z, v0.w, h1, l1);
        wsplit2(v1.x, v1.y, h2, l2);
        wsplit2(v1.z, v1.w, h3, l3);
        *(uint4*)&hi[i] = make_uint4(h0, h1, h2, h3);
        *(uint4*)&lo[i] = make_uint4(l0, l1, l2, l3);
    }
}

// selected-expert conversion: grid (EXN/2048, 36, 3)
__global__ void convexp_kernel(const float* __restrict__ eg, const float* __restrict__ eu,
                               const float* __restrict__ ed,
                               fp16* gh, fp16* gl, fp16* uh, fp16* ul,
                               fp16* dh, fp16* dl, const int* __restrict__ ti) {
    const int slot = blockIdx.y, mat = blockIdx.z;
    const int l = slot / 6, e = ti[slot];
    long i = ((long)blockIdx.x * 256 + threadIdx.x) * 8;
    if (i >= EXN) return;
    const float* src; fp16 *hi, *lo;
    if (mat == 0)      { src = eg; hi = gh; lo = gl; }
    else if (mat == 1) { src = eu; hi = uh; lo = ul; }
    else               { src = ed; hi = dh; lo = dl; }
    src += ((long)l * 10 + e) * EXN + i;
    hi  += (long)slot * EXN + i;
    lo  += (long)slot * EXN + i;
    float4 v0 = *(const float4*)src;
    float4 v1 = *(const float4*)(src + 4);
    unsigned h0, l0, h1, l1, h2, l2, h3, l3;
    wsplit2(v0.x, v0.y, h0, l0);
    wsplit2(v0.z, v0.w, h1, l1);
    wsplit2(v1.x, v1.y, h2, l2);
    wsplit2(v1.z, v1.w, h3, l3);
    *(uint4*)hi = make_uint4(h0, h1, h2, h3);
    *(uint4*)lo = make_uint4(l0, l1, l2, l3);
}

// ---------------- embedding (vectorized; DD % 4 == 0 so no row straddle) -------
__global__ void embed_kernel(const int* __restrict__ idx,
                             const float* __restrict__ emb,
                             float* __restrict__ x) {
    long i = ((long)blockIdx.x * blockDim.x + threadIdx.x) * 4;
    if (i < (long)ROWS * DD) {
        long r = i / DD, c = i % DD;
        *(float4*)&x[i] = *(const float4*)&emb[(long)idx[r] * DD + c];
    }
}

// ---------------- consciousness vector (tiny MLP) ----------------
__global__ void cv_kernel(const float* __restrict__ cs,
                          const float* __restrict__ w1, const float* __restrict__ b1,
                          const float* __restrict__ w2, const float* __restrict__ b2,
                          float* __restrict__ cv) {
    __shared__ float pooled[BB][CDD];
    __shared__ float h1[BB][64];
    int t = threadIdx.x;  // 256 threads
    {
        int b = t / CDD, c = t % CDD;
        float s = 0.f;
        for (int n = 0; n < NCC; n++)
            s += cs[((long)b * NCC + n) * CDD + c];
        pooled[b][c] = s * (1.f / NCC);
    }
    __syncthreads();
    if (t < BB * 64) {
        int b = t / 64, j = t % 64;
        float z = b1[j];
        for (int c = 0; c < CDD; c++) z += pooled[b][c] * w1[c * 64 + j];
        float z3 = z * z * z;
        h1[b][j] = 0.5f * z * (1.f + tanhf(0.7978845608028654f * (z + 0.044715f * z3)));
    }
    __syncthreads();
    if (t < BB * 10) {
        int b = t / 10, i = t % 10;
        float z = b2[i];
        for (int j = 0; j < 64; j++) z += h1[b][j] * w2[j * 10 + i];
        cv[b * 10 + i] = 1.f / (1.f + expf(-z));
    }
}

// ---------------- routers for all layers ----------------
__global__ void router_all_kernel(const float* __restrict__ cv,
                                  const float* __restrict__ W,
                                  const float* __restrict__ bias,
                                  float* __restrict__ tw, int* __restrict__ ti) {
    int l = blockIdx.x;
    int b = threadIdx.x;
    if (b >= BB) return;
    const float* Wl = W + (long)l * 100;
    const float* bl = bias + (long)l * 10;
    float lg[10];
    float mx = -1e30f;
    for (int i = 0; i < 10; i++) {
        float z = bl[i];
        for (int j = 0; j < 10; j++) z += cv[b * 10 + j] * Wl[j * 10 + i];
        lg[i] = z;
        mx = fmaxf(mx, z);
    }
    float se = 0.f;
    for (int i = 0; i < 10; i++) { lg[i] = expf(lg[i] - mx); se += lg[i]; }
    for (int i = 0; i < 10; i++) lg[i] /= se;
    float wsum = 0.f;
    int base = l * 6 + b * 3;
    for (int kk = 0; kk < 3; kk++) {
        int bi = 0; float bv = -1.f;
        for (int i = 0; i < 10; i++) if (lg[i] > bv) { bv = lg[i]; bi = i; }
        ti[base + kk] = bi; tw[base + kk] = bv; wsum += bv;
        lg[bi] = -2.f;
    }
    for (int kk = 0; kk < 3; kk++) tw[base + kk] /= wsum;
}

// ---------------- RMSNorm -> fp16 plane ----------------
__global__ void __launch_bounds__(256) rms_kernel(const float* __restrict__ x,
                                                  const float* __restrict__ w,
                                                  fp16* __restrict__ o) {
    int row = blockIdx.x, t = threadIdx.x;
    const float* xr = x + (long)row * DD;
    float v0 = xr[t], v1 = xr[t + 256], v2 = xr[t + 512];
    float tot = block_reduce_sum_256(v0 * v0 + v1 * v1 + v2 * v2);
    float s = rsqrtf(tot * (1.f / DD) + 1e-6f);
    fp16* orow = o + (long)row * DD;
    orow[t]       = __float2half_rn(v0 * s * w[t]);
    orow[t + 256] = __float2half_rn(v1 * s * w[t + 256]);
    orow[t + 512] = __float2half_rn(v2 * s * w[t + 512]);
}

// ---------------- fused: x += p0+p1+p2 (MoE-down partials), then RMSNorm -------
__global__ void __launch_bounds__(256) rms_sum3_kernel(float* __restrict__ x,
                                                       const float* __restrict__ p,
                                                       const float* __restrict__ w,
                                                       fp16* __restrict__ o) {
    int row = blockIdx.x, t = threadIdx.x;
    float* xr = x + (long)row * DD;
    const float* p0 = p + (long)row * DD;
    const float* p1 = p + (long)ROWS * DD + (long)row * DD;
    const float* p2 = p + 2L * ROWS * DD + (long)row * DD;
    float v0 = xr[t]       + p0[t]       + p1[t]       + p2[t];
    float v1 = xr[t + 256] + p0[t + 256] + p1[t + 256] + p2[t + 256];
    float v2 = xr[t + 512] + p0[t + 512] + p1[t + 512] + p2[t + 512];
    xr[t] = v0; xr[t + 256] = v1; xr[t + 512] = v2;
    float tot = block_reduce_sum_256(v0 * v0 + v1 * v1 + v2 * v2);
    float s = rsqrtf(tot * (1.f / DD) + 1e-6f);
    fp16* orow = o + (long)row * DD;
    orow[t]       = __float2half_rn(v0 * s * w[t]);
    orow[t + 256] = __float2half_rn(v1 * s * w[t + 256]);
    orow[t + 512] = __float2half_rn(v2 * s * w[t + 512]);
}

// ---------------- fused cs-residual add + RMSNorm (MoE norm, l>0) --------------
__global__ void __launch_bounds__(256) rms_cs_kernel(float* __restrict__ x,
                                                     const float* __restrict__ w,
                                                     const float* __restrict__ tension,
                                                     const float* __restrict__ twv,
                                                     fp16* __restrict__ o) {
    int row = blockIdx.x, t = threadIdx.x;
    float* xr = x + (long)row * DD;
    float ten = tension[row] * GATE_STRENGTH;
    float v0 = xr[t]       + ten * twv[t];
    float v1 = xr[t + 256] + ten * twv[t + 256];
    float v2 = xr[t + 512] + ten * twv[t + 512];
    xr[t] = v0; xr[t + 256] = v1; xr[t + 512] = v2;
    float tot = block_reduce_sum_256(v0 * v0 + v1 * v1 + v2 * v2);
    float s = rsqrtf(tot * (1.f / DD) + 1e-6f);
    fp16* orow = o + (long)row * DD;
    orow[t]       = __float2half_rn(v0 * s * w[t]);
    orow[t + 256] = __float2half_rn(v1 * s * w[t + 256]);
    orow[t + 512] = __float2half_rn(v2 * s * w[t + 512]);
}

// ---------------- SwiGLU (+ tension) -> fp16 plane ----------------
__global__ void __launch_bounds__(256) swiglu_kernel(const float* __restrict__ g,
                                                     const float* __restrict__ u,
                                                     fp16* __restrict__ o,
                                                     float* __restrict__ tension) {
    int row = blockIdx.x, t = threadIdx.x;
    const float* gr = g + (long)row * DII;
    const float* ur = u + (long)row * DII;
    fp16* orow = o + (long)row * DII;
    float sum = 0.f;
    #pragma unroll
    for (int j = 0; j < 6; j++) {
        int c = t + j * 256;
        float a = gr[c], bv = ur[c];
        float hv = (a / (1.f + __expf(-a))) * bv;
        orow[c] = __float2half_rn(hv);
        sum += hv;
    }
    float tot = block_reduce_sum_256(sum);
    if (t == 0) tension[row] = tanhf(tot * (1.f / DII));
}

// ---------------- MoE SwiGLU (folds router weight) -> fp16 plane ---------------
__global__ void __launch_bounds__(256) swiglu_moe_kernel(const float* __restrict__ buf,
                                                         const float* __restrict__ tw,
                                                         fp16* __restrict__ mh) {
    int row = blockIdx.x, e = blockIdx.y, t = threadIdx.x;
    int b = row / TT;
    float scale = tw[b * 3 + e];
    const float* gr = buf + (long)(2 * e) * ROWS * DII + (long)row * DII;
    const float* ur = buf + (long)(2 * e + 1) * ROWS * DII + (long)row * DII;
    fp16* orow = mh + (long)e * ROWS * DII + (long)row * DII;
    #pragma unroll
    for (int j = 0; j < 6; j++) {
        int c = t + j * 256;
        float a = gr[c], bv = ur[c];
        orow[c] = __float2half_rn((a / (1.f + __expf(-a))) * bv * scale);
    }
}

// ---------------- flash-style causal attention (fp32, GQA, vectorized) ---------
__global__ void __launch_bounds__(64) attn_kernel(const float* __restrict__ q,
                                                  const float* __restrict__ k,
                                                  const float* __restrict__ v,
                                                  fp16* __restrict__ o) {
    const int q0 = blockIdx.x * 64;
    const int h  = blockIdx.y;
    const int b  = blockIdx.z;
    const int t  = threadIdx.x;
    const int qg = q0 + t;
    const int kvh = h / (NHH / NKVV);

    __shared__ float Ks[64][64];
    __shared__ float Vs[64][64];

    float qreg[64], acc[64];
    const float4* qp4 = (const float4*)(q + ((long)(b * TT + qg) * NHH + h) * HDD);
    #pragma unroll
    for (int d4 = 0; d4 < 16; d4++) {
        float4 qv = qp4[d4];
        qreg[4*d4] = qv.x; qreg[4*d4+1] = qv.y; qreg[4*d4+2] = qv.z; qreg[4*d4+3] = qv.w;
    }
    #pragma unroll
    for (int d = 0; d < 64; d++) acc[d] = 0.f;
    float lsum = 0.f;

    const int rt = t >> 4, ct = (t & 15) * 4;

    for (int s0 = 0; s0 <= q0; s0 += 64) {
        __syncthreads();
        #pragma unroll
        for (int j = 0; j < 16; j++) {
            int r = 4 * j + rt;
            long base = ((long)(b * TT + s0 + r) * NKVV + kvh) * HDD + ct;
            *(float4*)&Ks[r][ct] = *(const float4*)&k[base];
            *(float4*)&Vs[r][ct] = *(const float4*)&v[base];
        }
        __syncthreads();
        int kmax = min(64, qg - s0 + 1);
        for (int kk = 0; kk < kmax; kk++) {
            const float4* krow = (const float4*)Ks[kk];
            float s = 0.f;
            #pragma unroll
            for (int d4 = 0; d4 < 16; d4++) {
                float4 kv = krow[d4];
                s += qreg[4*d4]     * kv.x;
                s += qreg[4*d4 + 1] * kv.y;
                s += qreg[4*d4 + 2] * kv.z;
                s += qreg[4*d4 + 3] * kv.w;
            }
            float p = __expf(s * 0.125f);
            lsum += p;
            const float4* vrow = (const float4*)Vs[kk];
            #pragma unroll
            for (int d4 = 0; d4 < 16; d4++) {
                float4 vv = vrow[d4];
                acc[4*d4]     += p * vv.x;
                acc[4*d4 + 1] += p * vv.y;
                acc[4*d4 + 2] += p * vv.z;
                acc[4*d4 + 3] += p * vv.w;
            }
        }
    }
    float inv = 1.f / lsum;
    long base = ((long)(b * TT + qg) * NHH + h) * HDD;
    #pragma unroll
    for (int d = 0; d < 64; d += 2) {
        __half2 hv = __floats2half2_rn(acc[d] * inv, acc[d + 1] * inv);
        *(__half2*)&o[base + d] = hv;
    }
}

// ---------------- tensor-core GEMM: fp16 A plane, fp16 hi/lo B planes ----------
// C(MxN) = [C +] A@Bhi + A@Blo  (fp32 accum; B exact in fp16 hi+lo)
// 128x128 tile, 8 warps (64x32 warp tiles), BK=32, 2-stage cp.async, 2 CTA/SM.
// MODE 0: plain; optional pair (B2,C2) via blockIdx.z.
// MODE 1: MoE gate/up: z in [0,6): kexp=z>>1; plane = (z&1 ? B2 : B) +
//         (bb*3+kexp)*sstride; C += z*ROWS*N.
// MODE 2: MoE down, seg-split: z=seg in [0,3): A += seg*ROWS*K;
//         B += (bb*3+seg)*sstride; C += seg*ROWS*N (partial stores, summed later).
template<bool ACC, bool TRANSB, int MODE>
__global__ void __launch_bounds__(256, 2) gemm_fp16(
    const fp16* __restrict__ A,
    const fp16* __restrict__ Bh, const fp16* __restrict__ Bl,
    float* __restrict__ C,
    const fp16* __restrict__ B2h, const fp16* __restrict__ B2l, float* __restrict__ C2,
    int M, int N, int K, long sstride)
{
    const int bx = blockIdx.x, by = blockIdx.y;
    const int bb = (by * 128) / TT;              // batch (tiles never straddle)
    if (MODE == 0) {
        if (B2h != nullptr && blockIdx.z == 1) { Bh = B2h; Bl = B2l; C = C2; }
    } else if (MODE == 1) {
        const int z = blockIdx.z, kexp = z >> 1;
        long off = (long)(bb * 3 + kexp) * sstride;
        if (z & 1) { Bh = B2h + off; Bl = B2l + off; }
        else       { Bh = Bh  + off; Bl = Bl  + off; }
        C += (long)z * ROWS * N;
    } else if (MODE == 2) {
        const int seg = blockIdx.z;
        A += (long)seg * ROWS * K;
        long off = (long)(bb * 3 + seg) * sstride;
        Bh += off; Bl += off;
        C += (long)seg * ROWS * N;
    }

    extern __shared__ fp16 sm[];
    constexpr int ASZ2 = 128 * 40;
    constexpr int BSZ2 = TRANSB ? 128 * 40 : 32 * 136;
    fp16* smA  = sm;                 // [2][ASZ2]
    fp16* smBh = smA + 2 * ASZ2;     // [2][BSZ2]
    fp16* smBl = smBh + 2 * BSZ2;

    const unsigned uA  = (unsigned)__cvta_generic_to_shared(smA);
    const unsigned uBh = (unsigned)__cvta_generic_to_shared(smBh);
    const unsigned uBl = (unsigned)__cvta_generic_to_shared(smBl);

    const int tid = threadIdx.x;
    const int wid = tid >> 5, lane = tid & 31;
    const int g = lane >> 2, t = lane & 3;
    const int m0 = (wid & 1) * 64, n0 = (wid >> 1) * 32;

    const int arow = tid >> 1, acb = (tid & 1) * 16;
    const int kr = tid >> 3,  nb = (tid & 7) * 16;

    const int total = K >> 5;

    auto issue = [&](int it, int st) {
        const int k0 = it * 32;
        long aoff = (long)(by * 128 + arow) * K + k0 + acb;
        unsigned d = uA + (unsigned)(st * ASZ2 + arow * 40 + acb) * 2u;
        cp16(d, A + aoff);       cp16(d + 16, A + aoff + 8);
        if (TRANSB) {
            long boff = (long)(bx * 128 + arow) * K + k0 + acb;
            d = uBh + (unsigned)(st * BSZ2 + arow * 40 + acb) * 2u;
            cp16(d, Bh + boff);   cp16(d + 16, Bh + boff + 8);
            d = uBl + (unsigned)(st * BSZ2 + arow * 40 + acb) * 2u;
            cp16(d, Bl + boff);   cp16(d + 16, Bl + boff + 8);
        } else {
            long boff = (long)(k0 + kr) * N + bx * 128 + nb;
            d = uBh + (unsigned)(st * BSZ2 + kr * 136 + nb) * 2u;
            cp16(d, Bh + boff);   cp16(d + 16, Bh + boff + 8);
            d = uBl + (unsigned)(st * BSZ2 + kr * 136 + nb) * 2u;
            cp16(d, Bl + boff);   cp16(d + 16, Bl + boff + 8);
        }
        cp_commit();
    };

    float acc[4][4][4];
    #pragma unroll
    for (int i = 0; i < 4; i++)
        #pragma unroll
        for (int j = 0; j < 4; j++)
            #pragma unroll
            for (int e = 0; e < 4; e++) acc[i][j][e] = 0.f;

    issue(0, 0);

    for (int it = 0; it < total; it++) {
        const int st = it & 1;
        cp_wait0();
        __syncthreads();
        if (it + 1 < total) issue(it + 1, st ^ 1);

        const unsigned aO = (unsigned)(st * ASZ2) * 2u;
        const unsigned bO = (unsigned)(st * BSZ2) * 2u;
        #pragma unroll
        for (int ks = 0; ks < 2; ks++) {
            const int kk = ks * 16;
            unsigned ah[4][4];
            #pragma unroll
            for (int i = 0; i < 4; i++) {
                int row = m0 + i * 16 + (lane & 15);
                int col = kk + (lane >> 4) * 8;
                unsigned off = (unsigned)(row * 40 + col) * 2u;
                ldsm_x4(ah[i][0], ah[i][1], ah[i][2], ah[i][3], uA + aO + off);
            }
            unsigned bh[4][2], bl[4][2];
            if (TRANSB) {
                #pragma unroll
                for (int jp = 0; jp < 2; jp++) {
                    int row = n0 + jp * 16 + (lane & 15);
                    int col = kk + (lane >> 4) * 8;
                    unsigned off = (unsigned)(row * 40 + col) * 2u;
                    unsigned r0, r1, r2, r3;
                    ldsm_x4(r0, r1, r2, r3, uBh + bO + off);
                    bh[2*jp][0] = r0; bh[2*jp+1][0] = r1;
                    bh[2*jp][1] = r2; bh[2*jp+1][1] = r3;
                    ldsm_x4(r0, r1, r2, r3, uBl + bO + off);
                    bl[2*jp][0] = r0; bl[2*jp+1][0] = r1;
                    bl[2*jp][1] = r2; bl[2*jp+1][1] = r3;
                }
            } else {
                #pragma unroll
                for (int jp = 0; jp < 2; jp++) {
                    int row = kk + (lane & 15);
                    int col = n0 + jp * 16 + (lane >> 4) * 8;
                    unsigned off = (unsigned)(row * 136 + col) * 2u;
                    unsigned r0, r1, r2, r3;
                    ldsm_x4_t(r0, r1, r2, r3, uBh + bO + off);
                    bh[2*jp][0] = r0; bh[2*jp][1] = r1;
                    bh[2*jp+1][0] = r2; bh[2*jp+1][1] = r3;
                    ldsm_x4_t(r0, r1, r2, r3, uBl + bO + off);
                    bl[2*jp][0] = r0; bl[2*jp][1] = r1;
                    bl[2*jp+1][0] = r2; bl[2*jp+1][1] = r3;
                }
            }
            #pragma unroll
            for (int j = 0; j < 4; j++) {
                #pragma unroll
                for (int i = 0; i < 4; i++) {
                    mma16816(acc[i][j], ah[i], bh[j]);
                    mma16816(acc[i][j], ah[i], bl[j]);
                }
            }
        }
    }

    // ---- epilogue ----
    #pragma unroll
    for (int i = 0; i < 4; i++) {
        long r0 = (long)(by * 128 + m0 + i * 16 + g);
        long r1 = r0 + 8;
        #pragma unroll
        for (int j = 0; j < 4; j++) {
            long c = (long)(bx * 128 + n0 + j * 8 + 2 * t);
            if (ACC) {
                C[r0 * N + c]     += acc[i][j][0];
                C[r0 * N + c + 1] += acc[i][j][1];
                C[r1 * N + c]     += acc[i][j][2];
                C[r1 * N + c + 1] += acc[i][j][3];
            } else {
                *(float2*)&C[r0 * N + c] = make_float2(acc[i][j][0], acc[i][j][1]);
                *(float2*)&C[r1 * N + c] = make_float2(acc[i][j][2], acc[i][j][3]);
            }
        }
    }
}

// smem sizes
constexpr int SMN = (2 * 128 * 40 + 4 * 32 * 136) * 2;   // 55,296 B
constexpr int SMT = (2 * 128 * 40 + 4 * 128 * 40) * 2;   // 61,440 B

// ---------------- launch ----------------
extern "C" void kernel_launch(void* const* d_in, const int* in_sizes, int n_in,
                              void* d_out, int out_size) {
    const int*   idx       = (const int*)  d_in[0];
    const float* cons      = (const float*)d_in[1];
    const float* tok_emb   = (const float*)d_in[2];
    const float* head_g    = (const float*)d_in[3];
    const float* cv_w1     = (const float*)d_in[4];
    const float* cv_b1     = (const float*)d_in[5];
    const float* cv_w2     = (const float*)d_in[6];
    const float* cv_b2     = (const float*)d_in[7];
    const float* tension_w = (const float*)d_in[8];
    const float* ln_attn   = (const float*)d_in[9];
    const float* ln_pf     = (const float*)d_in[10];
    const float* ln_moe    = (const float*)d_in[11];
    const float* ln_f      = (const float*)d_in[12];
    const float* wq        = (const float*)d_in[13];
    const float* wk        = (const float*)d_in[14];
    const float* wv        = (const float*)d_in[15];
    const float* wo        = (const float*)d_in[16];
    const float* pf_gate   = (const float*)d_in[17];
    const float* pf_up     = (const float*)d_in[18];
    const float* pf_down   = (const float*)d_in[19];
    const float* e_gate    = (const float*)d_in[20];
    const float* e_up      = (const float*)d_in[21];
    const float* e_down    = (const float*)d_in[22];
    const float* router_w  = (const float*)d_in[23];
    const float* router_b  = (const float*)d_in[24];
    float* out = (float*)d_out;

    // scratch addresses
    float *xp, *qp, *kp, *vp, *ebp, *cvp, *twp;  int* tip;
    fp16 *hp, *aop, *hdp, *mhp;
    fp16 *wqh, *wql, *wkh, *wkl, *wvh, *wvl, *woh, *wol;
    fp16 *pgh, *pgl, *puh, *pul, *pdh, *pdl;
    fp16 *emh, *eml, *hgh, *hgl;
    fp16 *egh, *egl, *euh, *eul, *edh, *edl;
    cudaGetSymbolAddress((void**)&xp,  g_x);
    cudaGetSymbolAddress((void**)&qp,  g_q);
    cudaGetSymbolAddress((void**)&kp,  g_k);
    cudaGetSymbolAddress((void**)&vp,  g_v);
    cudaGetSymbolAddress((void**)&ebp, g_eb);
    cudaGetSymbolAddress((void**)&cvp, g_cv);
    cudaGetSymbolAddress((void**)&twp, g_tw);
    cudaGetSymbolAddress((void**)&tip, g_ti);
    cudaGetSymbolAddress((void**)&hp,  g_h);
    cudaGetSymbolAddress((void**)&aop, g_ao);
    cudaGetSymbolAddress((void**)&hdp, g_hd);
    cudaGetSymbolAddress((void**)&mhp, g_mh);
    cudaGetSymbolAddress((void**)&wqh, g_wq_h); cudaGetSymbolAddress((void**)&wql, g_wq_l);
    cudaGetSymbolAddress((void**)&wkh, g_wk_h); cudaGetSymbolAddress((void**)&wkl, g_wk_l);
    cudaGetSymbolAddress((void**)&wvh, g_wv_h); cudaGetSymbolAddress((void**)&wvl, g_wv_l);
    cudaGetSymbolAddress((void**)&woh, g_wo_h); cudaGetSymbolAddress((void**)&wol, g_wo_l);
    cudaGetSymbolAddress((void**)&pgh, g_pg_h); cudaGetSymbolAddress((void**)&pgl, g_pg_l);
    cudaGetSymbolAddress((void**)&puh, g_pu_h); cudaGetSymbolAddress((void**)&pul, g_pu_l);
    cudaGetSymbolAddress((void**)&pdh, g_pd_h); cudaGetSymbolAddress((void**)&pdl, g_pd_l);
    cudaGetSymbolAddress((void**)&emh, g_em_h); cudaGetSymbolAddress((void**)&eml, g_em_l);
    cudaGetSymbolAddress((void**)&hgh, g_hg_h); cudaGetSymbolAddress((void**)&hgl, g_hg_l);
    cudaGetSymbolAddress((void**)&egh, g_eg_h); cudaGetSymbolAddress((void**)&egl, g_eg_l);
    cudaGetSymbolAddress((void**)&euh, g_eu_h); cudaGetSymbolAddress((void**)&eul, g_eu_l);
    cudaGetSymbolAddress((void**)&edh, g_ed_h); cudaGetSymbolAddress((void**)&edl, g_ed_l);

    // opt-in smem (idempotent host calls, not captured)
    cudaFuncSetAttribute(gemm_fp16<false, false, 0>, cudaFuncAttributeMaxDynamicSharedMemorySize, SMN);
    cudaFuncSetAttribute(gemm_fp16<true,  false, 0>, cudaFuncAttributeMaxDynamicSharedMemorySize, SMN);
    cudaFuncSetAttribute(gemm_fp16<false, false, 1>, cudaFuncAttributeMaxDynamicSharedMemorySize, SMN);
    cudaFuncSetAttribute(gemm_fp16<false, false, 2>, cudaFuncAttributeMaxDynamicSharedMemorySize, SMN);
    cudaFuncSetAttribute(gemm_fp16<false, true,  0>, cudaFuncAttributeMaxDynamicSharedMemorySize, SMT);

    float* tens = out + (long)2 * ROWS * VV;   // output tail: tensions (L, B, T)
    float* b1p = ebp;                          // PF gate fp32
    float* b2p = ebp + (long)ROWS * DII;       // PF up fp32
    float* pdown = ebp;                        // MoE-down partials (3 x ROWS x DD);
                                               // eb is dead after swiglu_moe, and the
                                               // partials are consumed by the next
                                               // rms_sum3 before eb is written again

    // ---- preprocessing: embed, cv, routers, weight conversion ----
    embed_kernel<<<(ROWS * DD / 4 + 255) / 256, 256>>>(idx, tok_emb, xp);
    cv_kernel<<<1, 256>>>(cons, cv_w1, cv_b1, cv_w2, cv_b2, cvp);
    router_all_kernel<<<LL, 32>>>(cvp, router_w, router_b, twp, tip);

    auto convw = [&](const float* s, fp16* hi, fp16* lo, long n) {
        convw_kernel<<<(int)((n / 8 + 255) / 256), 256>>>(s, hi, lo, n);
    };
    convw(wq, wqh, wql, 6L * 768 * 768);
    convw(wk, wkh, wkl, 6L * 768 * 256);
    convw(wv, wvh, wvl, 6L * 768 * 256);
    convw(wo, woh, wol, 6L * 768 * 768);
    convw(pf_gate, pgh, pgl, 6L * 768 * 1536);
    convw(pf_up,   puh, pul, 6L * 768 * 1536);
    convw(pf_down, pdh, pdl, 6L * 1536 * 768);
    convw(tok_emb, emh, eml, (long)VV * DD);
    convw(head_g,  hgh, hgl, (long)VV * DD);
    convexp_kernel<<<dim3((int)(EXN / 8 / 256), 36, 3), 256>>>(
        e_gate, e_up, e_down, egh, egl, euh, eul, edh, edl, tip);

    const dim3 g768 (DD  / 128, ROWS / 128, 1);
    const dim3 gkv  (256 / 128, ROWS / 128, 2);
    const dim3 gff  (DII / 128, ROWS / 128, 2);
    const dim3 gegu (DII / 128, ROWS / 128, 6);
    const dim3 gdn3 (DD  / 128, ROWS / 128, 3);   // MoE down, seg-split (576 blocks)

    for (int l = 0; l < LL; l++) {
        long o768  = (long)l * 768 * 768;
        long o256  = (long)l * 768 * 256;
        long o1536 = (long)l * 768 * 1536;
        long oexp  = (long)l * 6 * EXN;

        // ---- attention norm (folds previous layer's MoE-down partials) ----
        if (l > 0)
            rms_sum3_kernel<<<ROWS, 256>>>(xp, pdown, ln_attn + (long)l * DD, hp);
        else
            rms_kernel<<<ROWS, 256>>>(xp, ln_attn + (long)l * DD, hp);

        // ---- attention ----
        gemm_fp16<false, false, 0><<<g768, 256, SMN>>>(hp, wqh + o768, wql + o768, qp,
                                                       nullptr, nullptr, nullptr,
                                                       ROWS, 768, DD, 0);
        gemm_fp16<false, false, 0><<<gkv, 256, SMN>>>(hp, wkh + o256, wkl + o256, kp,
                                                      wvh + o256, wvl + o256, vp,
                                                      ROWS, 256, DD, 0);
        attn_kernel<<<dim3(TT / 64, NHH, BB), 64>>>(qp, kp, vp, aop);
        gemm_fp16<true, false, 0><<<g768, 256, SMN>>>(aop, woh + o768, wol + o768, xp,
                                                      nullptr, nullptr, nullptr,
                                                      ROWS, DD, 768, 0);

        // ---- PureField FFN + tension ----
        rms_kernel<<<ROWS, 256>>>(xp, ln_pf + (long)l * DD, hp);
        gemm_fp16<false, false, 0><<<gff, 256, SMN>>>(hp, pgh + o1536, pgl + o1536, b1p,
                                                      puh + o1536, pul + o1536, b2p,
                                                      ROWS, DII, DD, 0);
        swiglu_kernel<<<ROWS, 256>>>(b1p, b2p, hdp, tens + (long)l * ROWS);
        gemm_fp16<true, false, 0><<<g768, 256, SMN>>>(hdp, pdh + (long)l * 1536 * 768,
                                                      pdl + (long)l * 1536 * 768, xp,
                                                      nullptr, nullptr, nullptr,
                                                      ROWS, DD, DII, 0);

        // ---- MoE norm (fused with cs residual for l>0; bit-identical) ----
        if (l > 0)
            rms_cs_kernel<<<ROWS, 256>>>(xp, ln_moe + (long)l * DD,
                                         tens + (long)(l - 1) * ROWS, tension_w, hp);
        else
            rms_kernel<<<ROWS, 256>>>(xp, ln_moe + (long)l * DD, hp);

        // ---- MoE ----
        gemm_fp16<false, false, 1><<<gegu, 256, SMN>>>(hp, egh + oexp, egl + oexp, ebp,
                                                       euh + oexp, eul + oexp, nullptr,
                                                       ROWS, DII, DD, EXN);
        swiglu_moe_kernel<<<dim3(ROWS, 3), 256>>>(ebp, twp + (long)l * 6, mhp);
        // down: 3 segment partials (576 blocks -> 2 third-waves instead of 1 full)
        gemm_fp16<false, false, 2><<<gdn3, 256, SMN>>>(mhp, edh + oexp, edl + oexp,
                                                       pdown, nullptr, nullptr, nullptr,
                                                       ROWS, DD, DII, EXN);
    }

    // ---- final norm (folds last layer's partials) + tied heads (paired) ----
    rms_sum3_kernel<<<ROWS, 256>>>(xp, pdown, ln_f, hp);
    const dim3 gv(VV / 128, ROWS / 128, 2);
    gemm_fp16<false, true, 0><<<gv, 256, SMT>>>(hp, emh, eml, out,
                                                hgh, hgl, out + (long)ROWS * VV,
                                                ROWS, VV, DD, 0);
}

// round 17
// speedup vs baseline: 1.4064x; 1.0140x over previous
#include <cuda_runtime.h>
#include <cuda_fp16.h>
#include <math.h>

typedef __half fp16;

// ---------------- dims ----------------
#define BB   2
#define TT   2048
#define DD   768
#define NHH  12
#define NKVV 4
#define HDD  64
#define LL   6
#define VV   32000
#define DII  1536
#define NCC  64
#define CDD  128
#define ROWS (BB*TT)          // 4096
#define GATE_STRENGTH 0.001f
#define EXN  ((long)DD*DII)   // expert matrix elements = 1,179,648

// ---------------- fp32 scratch ----------------
__device__ float g_x [ROWS*DD];
__device__ float g_q [ROWS*NHH*HDD];
__device__ float g_k [ROWS*NKVV*HDD];
__device__ float g_v [ROWS*NKVV*HDD];
__device__ float g_eb[6L*ROWS*DII];    // gate/up outputs; also down-GEMM partials
__device__ float g_cv[BB*10];
__device__ float g_tw[LL*BB*3];
__device__ int   g_ti[LL*BB*3];

// ---------------- fp16 activation planes (single precision plane) --------------
__device__ fp16 g_h  [ROWS*DD];
__device__ fp16 g_ao [ROWS*NHH*HDD];
__device__ fp16 g_hd [ROWS*DII];          // PF hidden
__device__ fp16 g_mh [3L*ROWS*DII];       // MoE hidden

// ---------------- fp16 hi/lo weight planes (layouts as in source) --------------
__device__ fp16 g_wq_h[6L*768*768],  g_wq_l[6L*768*768];
__device__ fp16 g_wk_h[6L*768*256],  g_wk_l[6L*768*256];
__device__ fp16 g_wv_h[6L*768*256],  g_wv_l[6L*768*256];
__device__ fp16 g_wo_h[6L*768*768],  g_wo_l[6L*768*768];
__device__ fp16 g_pg_h[6L*768*1536], g_pg_l[6L*768*1536];
__device__ fp16 g_pu_h[6L*768*1536], g_pu_l[6L*768*1536];
__device__ fp16 g_pd_h[6L*1536*768], g_pd_l[6L*1536*768];
__device__ fp16 g_em_h[(long)VV*DD], g_em_l[(long)VV*DD];   // [N][K] for TRANSB
__device__ fp16 g_hg_h[(long)VV*DD], g_hg_l[(long)VV*DD];
__device__ fp16 g_eg_h[36L*DD*DII],  g_eg_l[36L*DD*DII];
__device__ fp16 g_eu_h[36L*DD*DII],  g_eu_l[36L*DD*DII];
__device__ fp16 g_ed_h[36L*DD*DII],  g_ed_l[36L*DD*DII];

// ---------------- helpers ----------------
__device__ __forceinline__ float block_reduce_sum_256(float v) {
    __shared__ float red[8];
    int t = threadIdx.x;
    #pragma unroll
    for (int off = 16; off; off >>= 1) v += __shfl_xor_sync(0xffffffffu, v, off);
    if ((t & 31) == 0) red[t >> 5] = v;
    __syncthreads();
    float tot = 0.f;
    #pragma unroll
    for (int i = 0; i < 8; i++) tot += red[i];
    return tot;
}

// weight split: hi/lo fp16 pairs (packed two at a time)
__device__ __forceinline__ void wsplit2(float f0, float f1, unsigned& hi, unsigned& lo) {
    __half2 h = __floats2half2_rn(f0, f1);
    float r0 = f0 - __half2float(__low2half(h));
    float r1 = f1 - __half2float(__high2half(h));
    __half2 l = __floats2half2_rn(r0, r1);
    hi = *(unsigned*)&h;
    lo = *(unsigned*)&l;
}

__device__ __forceinline__ void mma16816(float* c, const unsigned* a, const unsigned* b) {
    asm volatile(
        "mma.sync.aligned.m16n8k16.row.col.f32.f16.f16.f32 "
        "{%0,%1,%2,%3}, {%4,%5,%6,%7}, {%8,%9}, {%0,%1,%2,%3};\n"
        : "+f"(c[0]), "+f"(c[1]), "+f"(c[2]), "+f"(c[3])
        : "r"(a[0]), "r"(a[1]), "r"(a[2]), "r"(a[3]), "r"(b[0]), "r"(b[1]));
}

__device__ __forceinline__ void ldsm_x4(unsigned& r0, unsigned& r1, unsigned& r2,
                                        unsigned& r3, unsigned addr) {
    asm volatile("ldmatrix.sync.aligned.m8n8.x4.shared.b16 {%0,%1,%2,%3}, [%4];\n"
                 : "=r"(r0), "=r"(r1), "=r"(r2), "=r"(r3) : "r"(addr));
}

__device__ __forceinline__ void ldsm_x4_t(unsigned& r0, unsigned& r1, unsigned& r2,
                                          unsigned& r3, unsigned addr) {
    asm volatile("ldmatrix.sync.aligned.m8n8.x4.trans.shared.b16 {%0,%1,%2,%3}, [%4];\n"
                 : "=r"(r0), "=r"(r1), "=r"(r2), "=r"(r3) : "r"(addr));
}

__device__ __forceinline__ void cp16(unsigned dst, const void* src) {
    asm volatile("cp.async.cg.shared.global [%0], [%1], 16;\n" :: "r"(dst), "l"(src));
}
__device__ __forceinline__ void cp_commit() { asm volatile("cp.async.commit_group;\n"); }
__device__ __forceinline__ void cp_wait0()  { asm volatile("cp.async.wait_group 0;\n" ::: "memory"); }

// ---------------- weight converters (8 elems/thread, vectorized stores) --------
__global__ void convw_kernel(const float* __restrict__ s, fp16* __restrict__ hi,
                             fp16* __restrict__ lo, long n) {
    long i = ((long)blockIdx.x * blockDim.x + threadIdx.x) * 8;
    if (i < n) {
        float4 v0 = *(const float4*)(s + i);
        float4 v1 = *(const float4*)(s + i + 4);
        unsigned h0, l0, h1, l1, h2, l2, h3, l3;
        wsplit2(v0.x, v0.y, h0, l0);
        wsplit2(v0.z, v0.w, h1, l1);
        wsplit2(v1.x, v1.y, h2, l2);
        wsplit2(v1.z, v1.w, h3, l3);
        *(uint4*)&hi[i] = make_uint4(h0, h1, h2, h3);
        *(uint4*)&lo[i] = make_uint4(l0, l1, l2, l3);
    }
}

// selected-expert conversion: grid (EXN/2048, 36, 3)
__global__ void convexp_kernel(const float* __restrict__ eg, const float* __restrict__ eu,
                               const float* __restrict__ ed,
                               fp16* gh, fp16* gl, fp16* uh, fp16* ul,
                               fp16* dh, fp16* dl, const int* __restrict__ ti) {
    const int slot = blockIdx.y, mat = blockIdx.z;
    const int l = slot / 6, e = ti[slot];
    long i = ((long)blockIdx.x * 256 + threadIdx.x) * 8;
    if (i >= EXN) return;
    const float* src; fp16 *hi, *lo;
    if (mat == 0)      { src = eg; hi = gh; lo = gl; }
    else if (mat == 1) { src = eu; hi = uh; lo = ul; }
    else               { src = ed; hi = dh; lo = dl; }
    src += ((long)l * 10 + e) * EXN + i;
    hi  += (long)slot * EXN + i;
    lo  += (long)slot * EXN + i;
    float4 v0 = *(const float4*)src;
    float4 v1 = *(const float4*)(src + 4);
    unsigned h0, l0, h1, l1, h2, l2, h3, l3;
    wsplit2(v0.x, v0.y, h0, l0);
    wsplit2(v0.z, v0.w, h1, l1);
    wsplit2(v1.x, v1.y, h2, l2);
    wsplit2(v1.z, v1.w, h3, l3);
    *(uint4*)hi = make_uint4(h0, h1, h2, h3);
    *(uint4*)lo = make_uint4(l0, l1, l2, l3);
}

// ---------------- embedding (vectorized; DD % 4 == 0 so no row straddle) -------
__global__ void embed_kernel(const int* __restrict__ idx,
                             const float* __restrict__ emb,
                             float* __restrict__ x) {
    long i = ((long)blockIdx.x * blockDim.x + threadIdx.x) * 4;
    if (i < (long)ROWS * DD) {
        long r = i / DD, c = i % DD;
        *(float4*)&x[i] = *(const float4*)&emb[(long)idx[r] * DD + c];
    }
}

// ---------------- consciousness vector (tiny MLP) ----------------
__global__ void cv_kernel(const float* __restrict__ cs,
                          const float* __restrict__ w1, const float* __restrict__ b1,
                          const float* __restrict__ w2, const float* __restrict__ b2,
                          float* __restrict__ cv) {
    __shared__ float pooled[BB][CDD];
    __shared__ float h1[BB][64];
    int t = threadIdx.x;  // 256 threads
    {
        int b = t / CDD, c = t % CDD;
        float s = 0.f;
        for (int n = 0; n < NCC; n++)
            s += cs[((long)b * NCC + n) * CDD + c];
        pooled[b][c] = s * (1.f / NCC);
    }
    __syncthreads();
    if (t < BB * 64) {
        int b = t / 64, j = t % 64;
        float z = b1[j];
        for (int c = 0; c < CDD; c++) z += pooled[b][c] * w1[c * 64 + j];
        float z3 = z * z * z;
        h1[b][j] = 0.5f * z * (1.f + tanhf(0.7978845608028654f * (z + 0.044715f * z3)));
    }
    __syncthreads();
    if (t < BB * 10) {
        int b = t / 10, i = t % 10;
        float z = b2[i];
        for (int j = 0; j < 64; j++) z += h1[b][j] * w2[j * 10 + i];
        cv[b * 10 + i] = 1.f / (1.f + expf(-z));
    }
}

// ---------------- routers for all layers ----------------
__global__ void router_all_kernel(const float* __restrict__ cv,
                                  const float* __restrict__ W,
                                  const float* __restrict__ bias,
                                  float* __restrict__ tw, int* __restrict__ ti) {
    int l = blockIdx.x;
    int b = threadIdx.x;
    if (b >= BB) return;
    const float* Wl = W + (long)l * 100;
    const float* bl = bias + (long)l * 10;
    float lg[10];
    float mx = -1e30f;
    for (int i = 0; i < 10; i++) {
        float z = bl[i];
        for (int j = 0; j < 10; j++) z += cv[b * 10 + j] * Wl[j * 10 + i];
        lg[i] = z;
        mx = fmaxf(mx, z);
    }
    float se = 0.f;
    for (int i = 0; i < 10; i++) { lg[i] = expf(lg[i] - mx); se += lg[i]; }
    for (int i = 0; i < 10; i++) lg[i] /= se;
    float wsum = 0.f;
    int base = l * 6 + b * 3;
    for (int kk = 0; kk < 3; kk++) {
        int bi = 0; float bv = -1.f;
        for (int i = 0; i < 10; i++) if (lg[i] > bv) { bv = lg[i]; bi = i; }
        ti[base + kk] = bi; tw[base + kk] = bv; wsum += bv;
        lg[bi] = -2.f;
    }
    for (int kk = 0; kk < 3; kk++) tw[base + kk] /= wsum;
}

// ---------------- RMSNorm -> fp16 plane ----------------
__global__ void __launch_bounds__(256) rms_kernel(const float* __restrict__ x,
                                                  const float* __restrict__ w,
                                                  fp16* __restrict__ o) {
    int row = blockIdx.x, t = threadIdx.x;
    const float* xr = x + (long)row * DD;
    float v0 = xr[t], v1 = xr[t + 256], v2 = xr[t + 512];
    float tot = block_reduce_sum_256(v0 * v0 + v1 * v1 + v2 * v2);
    float s = rsqrtf(tot * (1.f / DD) + 1e-6f);
    fp16* orow = o + (long)row * DD;
    orow[t]       = __float2half_rn(v0 * s * w[t]);
    orow[t + 256] = __float2half_rn(v1 * s * w[t + 256]);
    orow[t + 512] = __float2half_rn(v2 * s * w[t + 512]);
}

// ---------------- fused: x += p0+p1+p2 (down-GEMM partials), then RMSNorm ------
__global__ void __launch_bounds__(256) rms_sum3_kernel(float* __restrict__ x,
                                                       const float* __restrict__ p,
                                                       const float* __restrict__ w,
                                                       fp16* __restrict__ o) {
    int row = blockIdx.x, t = threadIdx.x;
    float* xr = x + (long)row * DD;
    const float* p0 = p + (long)row * DD;
    const float* p1 = p + (long)ROWS * DD + (long)row * DD;
    const float* p2 = p + 2L * ROWS * DD + (long)row * DD;
    float v0 = xr[t]       + p0[t]       + p1[t]       + p2[t];
    float v1 = xr[t + 256] + p0[t + 256] + p1[t + 256] + p2[t + 256];
    float v2 = xr[t + 512] + p0[t + 512] + p1[t + 512] + p2[t + 512];
    xr[t] = v0; xr[t + 256] = v1; xr[t + 512] = v2;
    float tot = block_reduce_sum_256(v0 * v0 + v1 * v1 + v2 * v2);
    float s = rsqrtf(tot * (1.f / DD) + 1e-6f);
    fp16* orow = o + (long)row * DD;
    orow[t]       = __float2half_rn(v0 * s * w[t]);
    orow[t + 256] = __float2half_rn(v1 * s * w[t + 256]);
    orow[t + 512] = __float2half_rn(v2 * s * w[t + 512]);
}

// ---------------- fused: partials sum + cs residual + RMSNorm (MoE norm l>0) ---
__global__ void __launch_bounds__(256) rms_cs_sum3_kernel(float* __restrict__ x,
                                                          const float* __restrict__ p,
                                                          const float* __restrict__ w,
                                                          const float* __restrict__ tension,
                                                          const float* __restrict__ twv,
                                                          fp16* __restrict__ o) {
    int row = blockIdx.x, t = threadIdx.x;
    float* xr = x + (long)row * DD;
    const float* p0 = p + (long)row * DD;
    const float* p1 = p + (long)ROWS * DD + (long)row * DD;
    const float* p2 = p + 2L * ROWS * DD + (long)row * DD;
    float ten = tension[row] * GATE_STRENGTH;
    float v0 = xr[t]       + p0[t]       + p1[t]       + p2[t]       + ten * twv[t];
    float v1 = xr[t + 256] + p0[t + 256] + p1[t + 256] + p2[t + 256] + ten * twv[t + 256];
    float v2 = xr[t + 512] + p0[t + 512] + p1[t + 512] + p2[t + 512] + ten * twv[t + 512];
    xr[t] = v0; xr[t + 256] = v1; xr[t + 512] = v2;
    float tot = block_reduce_sum_256(v0 * v0 + v1 * v1 + v2 * v2);
    float s = rsqrtf(tot * (1.f / DD) + 1e-6f);
    fp16* orow = o + (long)row * DD;
    orow[t]       = __float2half_rn(v0 * s * w[t]);
    orow[t + 256] = __float2half_rn(v1 * s * w[t + 256]);
    orow[t + 512] = __float2half_rn(v2 * s * w[t + 512]);
}

// ---------------- SwiGLU (+ tension) -> fp16 plane ----------------
__global__ void __launch_bounds__(256) swiglu_kernel(const float* __restrict__ g,
                                                     const float* __restrict__ u,
                                                     fp16* __restrict__ o,
                                                     float* __restrict__ tension) {
    int row = blockIdx.x, t = threadIdx.x;
    const float* gr = g + (long)row * DII;
    const float* ur = u + (long)row * DII;
    fp16* orow = o + (long)row * DII;
    float sum = 0.f;
    #pragma unroll
    for (int j = 0; j < 6; j++) {
        int c = t + j * 256;
        float a = gr[c], bv = ur[c];
        float hv = (a / (1.f + __expf(-a))) * bv;
        orow[c] = __float2half_rn(hv);
        sum += hv;
    }
    float tot = block_reduce_sum_256(sum);
    if (t == 0) tension[row] = tanhf(tot * (1.f / DII));
}

// ---------------- MoE SwiGLU (folds router weight) -> fp16 plane ---------------
__global__ void __launch_bounds__(256) swiglu_moe_kernel(const float* __restrict__ buf,
                                                         const float* __restrict__ tw,
                                                         fp16* __restrict__ mh) {
    int row = blockIdx.x, e = blockIdx.y, t = threadIdx.x;
    int b = row / TT;
    float scale = tw[b * 3 + e];
    const float* gr = buf + (long)(2 * e) * ROWS * DII + (long)row * DII;
    const float* ur = buf + (long)(2 * e + 1) * ROWS * DII + (long)row * DII;
    fp16* orow = mh + (long)e * ROWS * DII + (long)row * DII;
    #pragma unroll
    for (int j = 0; j < 6; j++) {
        int c = t + j * 256;
        float a = gr[c], bv = ur[c];
        orow[c] = __float2half_rn((a / (1.f + __expf(-a))) * bv * scale);
    }
}

// ---------------- flash-style causal attention (fp32, GQA, vectorized) ---------
__global__ void __launch_bounds__(64) attn_kernel(const float* __restrict__ q,
                                                  const float* __restrict__ k,
                                                  const float* __restrict__ v,
                                                  fp16* __restrict__ o) {
    const int q0 = blockIdx.x * 64;
    const int h  = blockIdx.y;
    const int b  = blockIdx.z;
    const int t  = threadIdx.x;
    const int qg = q0 + t;
    const int kvh = h / (NHH / NKVV);

    __shared__ float Ks[64][64];
    __shared__ float Vs[64][64];

    float qreg[64], acc[64];
    const float4* qp4 = (const float4*)(q + ((long)(b * TT + qg) * NHH + h) * HDD);
    #pragma unroll
    for (int d4 = 0; d4 < 16; d4++) {
        float4 qv = qp4[d4];
        qreg[4*d4] = qv.x; qreg[4*d4+1] = qv.y; qreg[4*d4+2] = qv.z; qreg[4*d4+3] = qv.w;
    }
    #pragma unroll
    for (int d = 0; d < 64; d++) acc[d] = 0.f;
    float lsum = 0.f;

    const int rt = t >> 4, ct = (t & 15) * 4;

    for (int s0 = 0; s0 <= q0; s0 += 64) {
        __syncthreads();
        #pragma unroll
        for (int j = 0; j < 16; j++) {
            int r = 4 * j + rt;
            long base = ((long)(b * TT + s0 + r) * NKVV + kvh) * HDD + ct;
            *(float4*)&Ks[r][ct] = *(const float4*)&k[base];
            *(float4*)&Vs[r][ct] = *(const float4*)&v[base];
        }
        __syncthreads();
        int kmax = min(64, qg - s0 + 1);
        for (int kk = 0; kk < kmax; kk++) {
            const float4* krow = (const float4*)Ks[kk];
            float s = 0.f;
            #pragma unroll
            for (int d4 = 0; d4 < 16; d4++) {
                float4 kv = krow[d4];
                s += qreg[4*d4]     * kv.x;
                s += qreg[4*d4 + 1] * kv.y;
                s += qreg[4*d4 + 2] * kv.z;
                s += qreg[4*d4 + 3] * kv.w;
            }
            float p = __expf(s * 0.125f);
            lsum += p;
            const float4* vrow = (const float4*)Vs[kk];
            #pragma unroll
            for (int d4 = 0; d4 < 16; d4++) {
                float4 vv = vrow[d4];
                acc[4*d4]     += p * vv.x;
                acc[4*d4 + 1] += p * vv.y;
                acc[4*d4 + 2] += p * vv.z;
                acc[4*d4 + 3] += p * vv.w;
            }
        }
    }
    float inv = 1.f / lsum;
    long base = ((long)(b * TT + qg) * NHH + h) * HDD;
    #pragma unroll
    for (int d = 0; d < 64; d += 2) {
        __half2 hv = __floats2half2_rn(acc[d] * inv, acc[d + 1] * inv);
        *(__half2*)&o[base + d] = hv;
    }
}

// ---------------- tensor-core GEMM: fp16 A plane, fp16 hi/lo B planes ----------
// C(MxN) = [C +] A@Bhi + A@Blo  (fp32 accum; B exact in fp16 hi+lo)
// 128x128 tile, 8 warps (64x32 warp tiles), BK=32, 2-stage cp.async, 2 CTA/SM.
// A row stride = lda (== K except MODE 3).
// MODE 0: plain; optional pair (B2,C2) via blockIdx.z.
// MODE 1: MoE gate/up: z in [0,6): kexp=z>>1; plane = (z&1 ? B2 : B) +
//         (bb*3+kexp)*sstride; C += z*ROWS*N.
// MODE 2: MoE down, seg-split: z=seg in [0,3): A += seg*ROWS*K;
//         B += (bb*3+seg)*sstride; C += seg*ROWS*N (partials, summed later).
// MODE 3: plain K-split: z=seg in [0,3): A += seg*K (cols; lda = full stride);
//         B += seg*K*N; C += seg*ROWS*N (partials, summed later).
template<bool ACC, bool TRANSB, int MODE>
__global__ void __launch_bounds__(256, 2) gemm_fp16(
    const fp16* __restrict__ A,
    const fp16* __restrict__ Bh, const fp16* __restrict__ Bl,
    float* __restrict__ C,
    const fp16* __restrict__ B2h, const fp16* __restrict__ B2l, float* __restrict__ C2,
    int M, int N, int K, int lda, long sstride)
{
    const int bx = blockIdx.x, by = blockIdx.y;
    const int bb = (by * 128) / TT;              // batch (tiles never straddle)
    if (MODE == 0) {
        if (B2h != nullptr && blockIdx.z == 1) { Bh = B2h; Bl = B2l; C = C2; }
    } else if (MODE == 1) {
        const int z = blockIdx.z, kexp = z >> 1;
        long off = (long)(bb * 3 + kexp) * sstride;
        if (z & 1) { Bh = B2h + off; Bl = B2l + off; }
        else       { Bh = Bh  + off; Bl = Bl  + off; }
        C += (long)z * ROWS * N;
    } else if (MODE == 2) {
        const int seg = blockIdx.z;
        A += (long)seg * ROWS * K;
        long off = (long)(bb * 3 + seg) * sstride;
        Bh += off; Bl += off;
        C += (long)seg * ROWS * N;
    } else if (MODE == 3) {
        const int seg = blockIdx.z;
        A += (long)seg * K;                     // column offset within lda-stride rows
        Bh += (long)seg * K * N;
        Bl += (long)seg * K * N;
        C += (long)seg * ROWS * N;
    }

    extern __shared__ fp16 sm[];
    constexpr int ASZ2 = 128 * 40;
    constexpr int BSZ2 = TRANSB ? 128 * 40 : 32 * 136;
    fp16* smA  = sm;                 // [2][ASZ2]
    fp16* smBh = smA + 2 * ASZ2;     // [2][BSZ2]
    fp16* smBl = smBh + 2 * BSZ2;

    const unsigned uA  = (unsigned)__cvta_generic_to_shared(smA);
    const unsigned uBh = (unsigned)__cvta_generic_to_shared(smBh);
    const unsigned uBl = (unsigned)__cvta_generic_to_shared(smBl);

    const int tid = threadIdx.x;
    const int wid = tid >> 5, lane = tid & 31;
    const int g = lane >> 2, t = lane & 3;
    const int m0 = (wid & 1) * 64, n0 = (wid >> 1) * 32;

    const int arow = tid >> 1, acb = (tid & 1) * 16;
    const int kr = tid >> 3,  nb = (tid & 7) * 16;

    const int total = K >> 5;

    auto issue = [&](int it, int st) {
        const int k0 = it * 32;
        long aoff = (long)(by * 128 + arow) * lda + k0 + acb;
        unsigned d = uA + (unsigned)(st * ASZ2 + arow * 40 + acb) * 2u;
        cp16(d, A + aoff);       cp16(d + 16, A + aoff + 8);
        if (TRANSB) {
            long boff = (long)(bx * 128 + arow) * K + k0 + acb;
            d = uBh + (unsigned)(st * BSZ2 + arow * 40 + acb) * 2u;
            cp16(d, Bh + boff);   cp16(d + 16, Bh + boff + 8);
            d = uBl + (unsigned)(st * BSZ2 + arow * 40 + acb) * 2u;
            cp16(d, Bl + boff);   cp16(d + 16, Bl + boff + 8);
        } else {
            long boff = (long)(k0 + kr) * N + bx * 128 + nb;
            d = uBh + (unsigned)(st * BSZ2 + kr * 136 + nb) * 2u;
            cp16(d, Bh + boff);   cp16(d + 16, Bh + boff + 8);
            d = uBl + (unsigned)(st * BSZ2 + kr * 136 + nb) * 2u;
            cp16(d, Bl + boff);   cp16(d + 16, Bl + boff + 8);
        }
        cp_commit();
    };

    float acc[4][4][4];
    #pragma unroll
    for (int i = 0; i < 4; i++)
        #pragma unroll
        for (int j = 0; j < 4; j++)
            #pragma unroll
            for (int e = 0; e < 4; e++) acc[i][j][e] = 0.f;

    issue(0, 0);

    for (int it = 0; it < total; it++) {
        const int st = it & 1;
        cp_wait0();
        __syncthreads();
        if (it + 1 < total) issue(it + 1, st ^ 1);

        const unsigned aO = (unsigned)(st * ASZ2) * 2u;
        const unsigned bO = (unsigned)(st * BSZ2) * 2u;
        #pragma unroll
        for (int ks = 0; ks < 2; ks++) {
            const int kk = ks * 16;
            unsigned ah[4][4];
            #pragma unroll
            for (int i = 0; i < 4; i++) {
                int row = m0 + i * 16 + (lane & 15);
                int col = kk + (lane >> 4) * 8;
                unsigned off = (unsigned)(row * 40 + col) * 2u;
                ldsm_x4(ah[i][0], ah[i][1], ah[i][2], ah[i][3], uA + aO + off);
            }
            unsigned bh[4][2], bl[4][2];
            if (TRANSB) {
                #pragma unroll
                for (int jp = 0; jp < 2; jp++) {
                    int row = n0 + jp * 16 + (lane & 15);
                    int col = kk + (lane >> 4) * 8;
                    unsigned off = (unsigned)(row * 40 + col) * 2u;
                    unsigned r0, r1, r2, r3;
                    ldsm_x4(r0, r1, r2, r3, uBh + bO + off);
                    bh[2*jp][0] = r0; bh[2*jp+1][0] = r1;
                    bh[2*jp][1] = r2; bh[2*jp+1][1] = r3;
                    ldsm_x4(r0, r1, r2, r3, uBl + bO + off);
                    bl[2*jp][0] = r0; bl[2*jp+1][0] = r1;
                    bl[2*jp][1] = r2; bl[2*jp+1][1] = r3;
                }
            } else {
                #pragma unroll
                for (int jp = 0; jp < 2; jp++) {
                    int row = kk + (lane & 15);
                    int col = n0 + jp * 16 + (lane >> 4) * 8;
                    unsigned off = (unsigned)(row * 136 + col) * 2u;
                    unsigned r0, r1, r2, r3;
                    ldsm_x4_t(r0, r1, r2, r3, uBh + bO + off);
                    bh[2*jp][0] = r0; bh[2*jp][1] = r1;
                    bh[2*jp+1][0] = r2; bh[2*jp+1][1] = r3;
                    ldsm_x4_t(r0, r1, r2, r3, uBl + bO + off);
                    bl[2*jp][0] = r0; bl[2*jp][1] = r1;
                    bl[2*jp+1][0] = r2; bl[2*jp+1][1] = r3;
                }
            }
            #pragma unroll
            for (int j = 0; j < 4; j++) {
                #pragma unroll
                for (int i = 0; i < 4; i++) {
                    mma16816(acc[i][j], ah[i], bh[j]);
                    mma16816(acc[i][j], ah[i], bl[j]);
                }
            }
        }
    }

    // ---- epilogue ----
    #pragma unroll
    for (int i = 0; i < 4; i++) {
        long r0 = (long)(by * 128 + m0 + i * 16 + g);
        long r1 = r0 + 8;
        #pragma unroll
        for (int j = 0; j < 4; j++) {
            long c = (long)(bx * 128 + n0 + j * 8 + 2 * t);
            if (ACC) {
                C[r0 * N + c]     += acc[i][j][0];
                C[r0 * N + c + 1] += acc[i][j][1];
                C[r1 * N + c]     += acc[i][j][2];
                C[r1 * N + c + 1] += acc[i][j][3];
            } else {
                *(float2*)&C[r0 * N + c] = make_float2(acc[i][j][0], acc[i][j][1]);
                *(float2*)&C[r1 * N + c] = make_float2(acc[i][j][2], acc[i][j][3]);
            }
        }
    }
}

// smem sizes
constexpr int SMN = (2 * 128 * 40 + 4 * 32 * 136) * 2;   // 55,296 B
constexpr int SMT = (2 * 128 * 40 + 4 * 128 * 40) * 2;   // 61,440 B

// ---------------- launch ----------------
extern "C" void kernel_launch(void* const* d_in, const int* in_sizes, int n_in,
                              void* d_out, int out_size) {
    const int*   idx       = (const int*)  d_in[0];
    const float* cons      = (const float*)d_in[1];
    const float* tok_emb   = (const float*)d_in[2];
    const float* head_g    = (const float*)d_in[3];
    const float* cv_w1     = (const float*)d_in[4];
    const float* cv_b1     = (const float*)d_in[5];
    const float* cv_w2     = (const float*)d_in[6];
    const float* cv_b2     = (const float*)d_in[7];
    const float* tension_w = (const float*)d_in[8];
    const float* ln_attn   = (const float*)d_in[9];
    const float* ln_pf     = (const float*)d_in[10];
    const float* ln_moe    = (const float*)d_in[11];
    const float* ln_f      = (const float*)d_in[12];
    const float* wq        = (const float*)d_in[13];
    const float* wk        = (const float*)d_in[14];
    const float* wv        = (const float*)d_in[15];
    const float* wo        = (const float*)d_in[16];
    const float* pf_gate   = (const float*)d_in[17];
    const float* pf_up     = (const float*)d_in[18];
    const float* pf_down   = (const float*)d_in[19];
    const float* e_gate    = (const float*)d_in[20];
    const float* e_up      = (const float*)d_in[21];
    const float* e_down    = (const float*)d_in[22];
    const float* router_w  = (const float*)d_in[23];
    const float* router_b  = (const float*)d_in[24];
    float* out = (float*)d_out;

    // scratch addresses
    float *xp, *qp, *kp, *vp, *ebp, *cvp, *twp;  int* tip;
    fp16 *hp, *aop, *hdp, *mhp;
    fp16 *wqh, *wql, *wkh, *wkl, *wvh, *wvl, *woh, *wol;
    fp16 *pgh, *pgl, *puh, *pul, *pdh, *pdl;
    fp16 *emh, *eml, *hgh, *hgl;
    fp16 *egh, *egl, *euh, *eul, *edh, *edl;
    cudaGetSymbolAddress((void**)&xp,  g_x);
    cudaGetSymbolAddress((void**)&qp,  g_q);
    cudaGetSymbolAddress((void**)&kp,  g_k);
    cudaGetSymbolAddress((void**)&vp,  g_v);
    cudaGetSymbolAddress((void**)&ebp, g_eb);
    cudaGetSymbolAddress((void**)&cvp, g_cv);
    cudaGetSymbolAddress((void**)&twp, g_tw);
    cudaGetSymbolAddress((void**)&tip, g_ti);
    cudaGetSymbolAddress((void**)&hp,  g_h);
    cudaGetSymbolAddress((void**)&aop, g_ao);
    cudaGetSymbolAddress((void**)&hdp, g_hd);
    cudaGetSymbolAddress((void**)&mhp, g_mh);
    cudaGetSymbolAddress((void**)&wqh, g_wq_h); cudaGetSymbolAddress((void**)&wql, g_wq_l);
    cudaGetSymbolAddress((void**)&wkh, g_wk_h); cudaGetSymbolAddress((void**)&wkl, g_wk_l);
    cudaGetSymbolAddress((void**)&wvh, g_wv_h); cudaGetSymbolAddress((void**)&wvl, g_wv_l);
    cudaGetSymbolAddress((void**)&woh, g_wo_h); cudaGetSymbolAddress((void**)&wol, g_wo_l);
    cudaGetSymbolAddress((void**)&pgh, g_pg_h); cudaGetSymbolAddress((void**)&pgl, g_pg_l);
    cudaGetSymbolAddress((void**)&puh, g_pu_h); cudaGetSymbolAddress((void**)&pul, g_pu_l);
    cudaGetSymbolAddress((void**)&pdh, g_pd_h); cudaGetSymbolAddress((void**)&pdl, g_pd_l);
    cudaGetSymbolAddress((void**)&emh, g_em_h); cudaGetSymbolAddress((void**)&eml, g_em_l);
    cudaGetSymbolAddress((void**)&hgh, g_hg_h); cudaGetSymbolAddress((void**)&hgl, g_hg_l);
    cudaGetSymbolAddress((void**)&egh, g_eg_h); cudaGetSymbolAddress((void**)&egl, g_eg_l);
    cudaGetSymbolAddress((void**)&euh, g_eu_h); cudaGetSymbolAddress((void**)&eul, g_eu_l);
    cudaGetSymbolAddress((void**)&edh, g_ed_h); cudaGetSymbolAddress((void**)&edl, g_ed_l);

    // opt-in smem (idempotent host calls, not captured)
    cudaFuncSetAttribute(gemm_fp16<false, false, 0>, cudaFuncAttributeMaxDynamicSharedMemorySize, SMN);
    cudaFuncSetAttribute(gemm_fp16<true,  false, 0>, cudaFuncAttributeMaxDynamicSharedMemorySize, SMN);
    cudaFuncSetAttribute(gemm_fp16<false, false, 1>, cudaFuncAttributeMaxDynamicSharedMemorySize, SMN);
    cudaFuncSetAttribute(gemm_fp16<false, false, 2>, cudaFuncAttributeMaxDynamicSharedMemorySize, SMN);
    cudaFuncSetAttribute(gemm_fp16<false, false, 3>, cudaFuncAttributeMaxDynamicSharedMemorySize, SMN);
    cudaFuncSetAttribute(gemm_fp16<false, true,  0>, cudaFuncAttributeMaxDynamicSharedMemorySize, SMT);

    float* tens = out + (long)2 * ROWS * VV;   // output tail: tensions (L, B, T)
    float* b1p = ebp;                          // PF gate fp32
    float* b2p = ebp + (long)ROWS * DII;       // PF up fp32
    float* pdown = ebp;                        // down-GEMM partials (3 x ROWS x DD);
                                               // PF partials: live PF-down -> MoE norm;
                                               // MoE partials: live MoE-down -> next
                                               // attn norm. Never coexist; both fit in
                                               // eb slots 0-1 which are dead then.

    // ---- preprocessing: embed, cv, routers, weight conversion ----
    embed_kernel<<<(ROWS * DD / 4 + 255) / 256, 256>>>(idx, tok_emb, xp);
    cv_kernel<<<1, 256>>>(cons, cv_w1, cv_b1, cv_w2, cv_b2, cvp);
    router_all_kernel<<<LL, 32>>>(cvp, router_w, router_b, twp, tip);

    auto convw = [&](const float* s, fp16* hi, fp16* lo, long n) {
        convw_kernel<<<(int)((n / 8 + 255) / 256), 256>>>(s, hi, lo, n);
    };
    convw(wq, wqh, wql, 6L * 768 * 768);
    convw(wk, wkh, wkl, 6L * 768 * 256);
    convw(wv, wvh, wvl, 6L * 768 * 256);
    convw(wo, woh, wol, 6L * 768 * 768);
    convw(pf_gate, pgh, pgl, 6L * 768 * 1536);
    convw(pf_up,   puh, pul, 6L * 768 * 1536);
    convw(pf_down, pdh, pdl, 6L * 1536 * 768);
    convw(tok_emb, emh, eml, (long)VV * DD);
    convw(head_g,  hgh, hgl, (long)VV * DD);
    convexp_kernel<<<dim3((int)(EXN / 8 / 256), 36, 3), 256>>>(
        e_gate, e_up, e_down, egh, egl, euh, eul, edh, edl, tip);

    const dim3 g768 (DD  / 128, ROWS / 128, 1);
    const dim3 gkv  (256 / 128, ROWS / 128, 2);
    const dim3 gff  (DII / 128, ROWS / 128, 2);
    const dim3 gegu (DII / 128, ROWS / 128, 6);
    const dim3 gdn3 (DD  / 128, ROWS / 128, 3);   // down GEMMs, seg-split (576 blocks)

    for (int l = 0; l < LL; l++) {
        long o768  = (long)l * 768 * 768;
        long o256  = (long)l * 768 * 256;
        long o1536 = (long)l * 768 * 1536;
        long oexp  = (long)l * 6 * EXN;

        // ---- attention norm (folds previous layer's MoE-down partials) ----
        if (l > 0)
            rms_sum3_kernel<<<ROWS, 256>>>(xp, pdown, ln_attn + (long)l * DD, hp);
        else
            rms_kernel<<<ROWS, 256>>>(xp, ln_attn + (long)l * DD, hp);

        // ---- attention ----
        gemm_fp16<false, false, 0><<<g768, 256, SMN>>>(hp, wqh + o768, wql + o768, qp,
                                                       nullptr, nullptr, nullptr,
                                                       ROWS, 768, DD, DD, 0);
        gemm_fp16<false, false, 0><<<gkv, 256, SMN>>>(hp, wkh + o256, wkl + o256, kp,
                                                      wvh + o256, wvl + o256, vp,
                                                      ROWS, 256, DD, DD, 0);
        attn_kernel<<<dim3(TT / 64, NHH, BB), 64>>>(qp, kp, vp, aop);
        gemm_fp16<true, false, 0><<<g768, 256, SMN>>>(aop, woh + o768, wol + o768, xp,
                                                      nullptr, nullptr, nullptr,
                                                      ROWS, DD, 768, 768, 0);

        // ---- PureField FFN + tension ----
        rms_kernel<<<ROWS, 256>>>(xp, ln_pf + (long)l * DD, hp);
        gemm_fp16<false, false, 0><<<gff, 256, SMN>>>(hp, pgh + o1536, pgl + o1536, b1p,
                                                      puh + o1536, pul + o1536, b2p,
                                                      ROWS, DII, DD, DD, 0);
        swiglu_kernel<<<ROWS, 256>>>(b1p, b2p, hdp, tens + (long)l * ROWS);
        // PF-down: K-split into 3 segments of 512 (partials into pdown)
        gemm_fp16<false, false, 3><<<gdn3, 256, SMN>>>(hdp, pdh + (long)l * 1536 * 768,
                                                       pdl + (long)l * 1536 * 768, pdown,
                                                       nullptr, nullptr, nullptr,
                                                       ROWS, DD, 512, DII, 0);

        // ---- MoE norm (folds PF-down partials; + cs residual for l>0) ----
        if (l > 0)
            rms_cs_sum3_kernel<<<ROWS, 256>>>(xp, pdown, ln_moe + (long)l * DD,
                                              tens + (long)(l - 1) * ROWS, tension_w, hp);
        else
            rms_sum3_kernel<<<ROWS, 256>>>(xp, pdown, ln_moe + (long)l * DD, hp);

        // ---- MoE ----
        gemm_fp16<false, false, 1><<<gegu, 256, SMN>>>(hp, egh + oexp, egl + oexp, ebp,
                                                       euh + oexp, eul + oexp, nullptr,
                                                       ROWS, DII, DD, DD, EXN);
        swiglu_moe_kernel<<<dim3(ROWS, 3), 256>>>(ebp, twp + (long)l * 6, mhp);
        // MoE down: 3 expert-segment partials
        gemm_fp16<false, false, 2><<<gdn3, 256, SMN>>>(mhp, edh + oexp, edl + oexp,
                                                       pdown, nullptr, nullptr, nullptr,
                                                       ROWS, DD, DII, DII, EXN);
    }

    // ---- final norm (folds last layer's partials) + tied heads (paired) ----
    rms_sum3_kernel<<<ROWS, 256>>>(xp, pdown, ln_f, hp);
    const dim3 gv(VV / 128, ROWS / 128, 2);
    gemm_fp16<false, true, 0><<<gv, 256, SMT>>>(hp, emh, eml, out,
                                                hgh, hgl, out + (long)ROWS * VV,
                                                ROWS, VV, DD, DD, 0);
}